// round 5
// baseline (speedup 1.0000x reference)
#include <cuda_runtime.h>
#include <cstdint>
#include <cstddef>

#define BB   2
#define TT   2048
#define DD   1024
#define HH   16
#define HDD  64
#define FFD  4096
#define MT   (BB*TT)
#define QS   (3*DD)          // fused qkv row stride

// ---------------------------------------------------------------------------
// Scratch
// ---------------------------------------------------------------------------
__device__ float g_h  [MT*DD];
__device__ float g_qkv[MT*QS];        // fused q|k|v per row
__device__ float g_ao [MT*DD];
__device__ float g_tmp[MT*DD];
__device__ float g_y  [MT*DD];
__device__ float g_mid[MT*FFD];
__device__ float g_w  [12*1024*1024]; // tf32 weights: wqkv[1024][3072] | wo | w1 | w2

#define WQKV_OFF 0
#define WO_OFF (3*1024*1024)
#define W1_OFF (4*1024*1024)
#define W2_OFF (8*1024*1024)

// ---------------------------------------------------------------------------
// Helpers
// ---------------------------------------------------------------------------
__device__ __forceinline__ float tf32r(float x) {
    float r; asm("cvt.rna.tf32.f32 %0, %1;" : "=f"(r) : "f"(x)); return r;
}
__device__ __forceinline__ uint32_t smaddr(const void* p) {
    return (uint32_t)__cvta_generic_to_shared(p);
}
#define CP16(dst, src) asm volatile("cp.async.cg.shared.global [%0], [%1], 16;\n" :: "r"(dst), "l"(src))
#define CP_COMMIT()    asm volatile("cp.async.commit_group;\n")

__device__ __forceinline__ void mma8(float* d, const float* a, const float* b) {
    asm volatile(
        "mma.sync.aligned.m16n8k8.row.col.f32.tf32.tf32.f32 "
        "{%0,%1,%2,%3}, {%4,%5,%6,%7}, {%8,%9}, {%0,%1,%2,%3};\n"
        : "+f"(d[0]), "+f"(d[1]), "+f"(d[2]), "+f"(d[3])
        : "r"(__float_as_uint(a[0])), "r"(__float_as_uint(a[1])),
          "r"(__float_as_uint(a[2])), "r"(__float_as_uint(a[3])),
          "r"(__float_as_uint(b[0])), "r"(__float_as_uint(b[1])));
}

// ---------------------------------------------------------------------------
// Pack weights -> tf32, with wq|wk|wv interleaved into [1024][3072].
// float4 units: wq/wk/wv/wo = 256K each, w1/w2 = 1M each. total 3M float4.
// ---------------------------------------------------------------------------
__global__ void __launch_bounds__(256) pack_kernel(
    const float4* __restrict__ wq, const float4* __restrict__ wk,
    const float4* __restrict__ wv, const float4* __restrict__ wo,
    const float4* __restrict__ w1, const float4* __restrict__ w2,
    float4* __restrict__ out)
{
    int i = blockIdx.x * 256 + threadIdx.x;
    const int Q = 256 * 1024;          // float4 per 1024x1024 matrix
    float4 v; int dst;
    if (i < 3 * Q) {
        // qkv: src row r (0..1023), col c (0..255 float4) -> dst r*768 + sel*256 + c
        int sel = i / Q;               // 0=q,1=k,2=v
        int j = i - sel * Q;
        int r = j >> 8, c = j & 255;
        const float4* src = sel == 0 ? wq : (sel == 1 ? wk : wv);
        v = src[j];
        dst = r * 768 + sel * 256 + c;
    } else if (i < 4 * Q) {
        v = wo[i - 3 * Q]; dst = i;
    } else if (i < 8 * Q) {
        v = w1[i - 4 * Q]; dst = i;
    } else {
        v = w2[i - 8 * Q]; dst = i;
    }
    v.x = tf32r(v.x); v.y = tf32r(v.y); v.z = tf32r(v.z); v.w = tf32r(v.w);
    out[dst] = v;
}

// ---------------------------------------------------------------------------
// RMSNorm (optionally + residual); RND: round output to tf32
// ---------------------------------------------------------------------------
template <int RND>
__global__ void __launch_bounds__(256) rmsnorm_kernel(
    const float* __restrict__ a, const float* __restrict__ b,
    const float* __restrict__ w, float* __restrict__ out)
{
    int row = blockIdx.x;
    size_t base = (size_t)row * DD;
    float v[4];
    float ss = 0.f;
#pragma unroll
    for (int t = 0; t < 4; t++) {
        int c = threadIdx.x + t * 256;
        float x = a[base + c];
        if (b) x += b[base + c];
        v[t] = x;
        ss += x * x;
    }
    __shared__ float red[8];
#pragma unroll
    for (int o = 16; o; o >>= 1) ss += __shfl_xor_sync(0xffffffffu, ss, o);
    if ((threadIdx.x & 31) == 0) red[threadIdx.x >> 5] = ss;
    __syncthreads();
    if (threadIdx.x == 0) {
        float tot = 0.f;
#pragma unroll
        for (int i = 0; i < 8; i++) tot += red[i];
        red[0] = tot;
    }
    __syncthreads();
    float scale = rsqrtf(red[0] * (1.0f / DD) + 1e-6f);
#pragma unroll
    for (int t = 0; t < 4; t++) {
        int c = threadIdx.x + t * 256;
        float o = v[t] * scale * w[c];
        out[base + c] = RND ? tf32r(o) : o;
    }
}

// ---------------------------------------------------------------------------
// TF32 GEMM: CTA 128x128, 4 warps x (64x64), BK=16, double-buffered cp.async.
// 128 threads -> 2 CTAs/SM.  M%128==0, N%128==0, K%16==0.
// ---------------------------------------------------------------------------
template <int EPI, int RND>
__global__ void __launch_bounds__(128, 2) tgemm_kernel(
    const float* __restrict__ A, const float* __restrict__ B,
    float* __restrict__ C, int M, int N, int K)
{
    __shared__ float As[2][128 * 20];   // [m][k] stride 20
    __shared__ float Bs[2][16 * 136];   // [k][n] stride 136

    int tid = threadIdx.x;
    int warp = tid >> 5, lane = tid & 31;
    int g = lane >> 2, tig = lane & 3;
    int wm = (warp >> 1) * 64, wn = (warp & 1) * 64;
    int bx = blockIdx.x, by = blockIdx.y;

    int ar = tid;                 // A row 0..127, 4 CP16 (16 k)
    int br = tid >> 3;            // B k-row 0..15
    int bc = (tid & 7) * 16;      // B n-col block, 4 CP16

    const float* a_src = A + (size_t)(by * 128 + ar) * K;
    const float* b_src = B + (size_t)br * N + bx * 128 + bc;
    uint32_t a_dst = smaddr(&As[0][ar * 20]);
    uint32_t b_dst = smaddr(&Bs[0][br * 136 + bc]);

    float acc[4][8][4];
#pragma unroll
    for (int i = 0; i < 4; i++)
#pragma unroll
        for (int j = 0; j < 8; j++)
#pragma unroll
            for (int r = 0; r < 4; r++) acc[i][j][r] = 0.f;

    int KT = K >> 4;

#define ISSUE(stage, kt)                                                     \
    {                                                                        \
        uint32_t ad = a_dst + (stage) * 10240;                               \
        const float* ap = a_src + ((kt) << 4);                               \
        CP16(ad, ap);      CP16(ad + 16, ap + 4);                            \
        CP16(ad + 32, ap + 8); CP16(ad + 48, ap + 12);                       \
        uint32_t bd = b_dst + (stage) * 8704;                                \
        const float* bp = b_src + (size_t)((kt) << 4) * N;                   \
        CP16(bd, bp);      CP16(bd + 16, bp + 4);                            \
        CP16(bd + 32, bp + 8); CP16(bd + 48, bp + 12);                       \
        CP_COMMIT();                                                         \
    }

    ISSUE(0, 0);

    for (int kt = 0; kt < KT; kt++) {
        int buf = kt & 1;
        if (kt + 1 < KT) {
            ISSUE(buf ^ 1, kt + 1);
            asm volatile("cp.async.wait_group 1;\n");
        } else {
            asm volatile("cp.async.wait_group 0;\n");
        }
        __syncthreads();

        const float* as = As[buf];
        const float* bs = Bs[buf];
#pragma unroll
        for (int ch = 0; ch < 2; ch++) {
            int kb = ch * 8 + tig;
            float a[4][4], b[8][2];
#pragma unroll
            for (int mt = 0; mt < 4; mt++) {
                int m = wm + mt * 16 + g;
                a[mt][0] = as[m * 20 + kb];
                a[mt][1] = as[(m + 8) * 20 + kb];
                a[mt][2] = as[m * 20 + kb + 4];
                a[mt][3] = as[(m + 8) * 20 + kb + 4];
            }
#pragma unroll
            for (int nt = 0; nt < 8; nt++) {
                int n = wn + nt * 8 + g;
                b[nt][0] = bs[kb * 136 + n];
                b[nt][1] = bs[(kb + 4) * 136 + n];
            }
#pragma unroll
            for (int mt = 0; mt < 4; mt++)
#pragma unroll
                for (int nt = 0; nt < 8; nt++) mma8(acc[mt][nt], a[mt], b[nt]);
        }
        __syncthreads();
    }
#undef ISSUE

#pragma unroll
    for (int mt = 0; mt < 4; mt++) {
#pragma unroll
        for (int nt = 0; nt < 8; nt++) {
            int row = by * 128 + wm + mt * 16 + g;
            int col = bx * 128 + wn + nt * 8 + 2 * tig;
            float e[4];
#pragma unroll
            for (int r = 0; r < 4; r++) {
                float c = acc[mt][nt][r];
                if (EPI == 1) c = c / (1.0f + __expf(-c));
                if (RND)      c = tf32r(c);
                e[r] = c;
            }
            *(float2*)&C[(size_t)row * N + col]       = make_float2(e[0], e[1]);
            *(float2*)&C[(size_t)(row + 8) * N + col] = make_float2(e[2], e[3]);
        }
    }
}

// ---------------------------------------------------------------------------
// Flash attention over fused qkv (row stride QS=3072).
// Per block: 128 q-rows, one head. 8 warps x 16 rows. Online softmax.
// ---------------------------------------------------------------------------
__global__ void __launch_bounds__(256) flash_kernel(
    const float* __restrict__ qkv, float* __restrict__ ao)
{
    int it = blockIdx.x;
    int bh = blockIdx.y;
    int b = bh >> 4, h = bh & 15;
    int i0 = it * 128;

    __shared__ float smem[64 * 68 + 64 * 72];
    float* Ks = smem;
    float* Vs = smem + 64 * 68;
    float* Qstage = smem;

    int tid = threadIdx.x, warp = tid >> 5, lane = tid & 31;
    int g = lane >> 2, tig = lane & 3;

    const float* q = qkv + h * HDD;            // col offset 0
    const float* k = qkv + DD + h * HDD;       // col offset 1024
    const float* v = qkv + 2 * DD + h * HDD;   // col offset 2048

    {
        int r = tid >> 1;
        int cb = (tid & 1) * 32;
        const float* qp = q + (size_t)(b * TT + i0 + r) * QS + cb;
        float* dst = Qstage + r * 68 + cb;
#pragma unroll
        for (int c4 = 0; c4 < 8; c4++)
            *(float4*)(dst + c4 * 4) = *(const float4*)(qp + c4 * 4);
    }
    __syncthreads();
    float qa[8][4];
    {
        int m = warp * 16 + g;
#pragma unroll
        for (int kt = 0; kt < 8; kt++) {
            int kb = kt * 8 + tig;
            qa[kt][0] = Qstage[m * 68 + kb] * 0.125f;
            qa[kt][1] = Qstage[(m + 8) * 68 + kb] * 0.125f;
            qa[kt][2] = Qstage[m * 68 + kb + 4] * 0.125f;
            qa[kt][3] = Qstage[(m + 8) * 68 + kb + 4] * 0.125f;
        }
    }
    __syncthreads();

    float o[8][4];
#pragma unroll
    for (int nt = 0; nt < 8; nt++)
#pragma unroll
        for (int r = 0; r < 4; r++) o[nt][r] = 0.f;
    float rm0 = -1e30f, rm1 = -1e30f, rs0 = 0.f, rs1 = 0.f;

    int jt_max = 2 * it + 1;
    int warp_row0 = i0 + warp * 16;
    int src0 = g * 4 + (tig >> 1);
    int src1 = src0 + 2;
    bool hi = tig & 1;

    for (int jt = 0; jt <= jt_max; jt++) {
        int j0 = jt * 64;
        {
            int r = tid >> 2, cb = (tid & 3) * 16;
            const float* kp = k + (size_t)(b * TT + j0 + r) * QS + cb;
            const float* vp = v + (size_t)(b * TT + j0 + r) * QS + cb;
#pragma unroll
            for (int c4 = 0; c4 < 4; c4++) {
                *(float4*)(Ks + r * 68 + cb + c4 * 4) = *(const float4*)(kp + c4 * 4);
                *(float4*)(Vs + r * 72 + cb + c4 * 4) = *(const float4*)(vp + c4 * 4);
            }
        }
        __syncthreads();

        if (j0 <= warp_row0 + 15) {
            float s[8][4];
#pragma unroll
            for (int nt = 0; nt < 8; nt++)
#pragma unroll
                for (int r = 0; r < 4; r++) s[nt][r] = 0.f;
#pragma unroll
            for (int kt = 0; kt < 8; kt++) {
                int kb = kt * 8 + tig;
#pragma unroll
                for (int nt = 0; nt < 8; nt++) {
                    float bfr[2] = { Ks[(nt * 8 + g) * 68 + kb],
                                     Ks[(nt * 8 + g) * 68 + kb + 4] };
                    mma8(s[nt], qa[kt], bfr);
                }
            }
            int r0 = warp_row0 + g, r1 = r0 + 8;
            if (j0 + 63 > warp_row0) {
#pragma unroll
                for (int nt = 0; nt < 8; nt++) {
                    int j = j0 + nt * 8 + 2 * tig;
                    if (j     > r0) s[nt][0] = -1e30f;
                    if (j + 1 > r0) s[nt][1] = -1e30f;
                    if (j     > r1) s[nt][2] = -1e30f;
                    if (j + 1 > r1) s[nt][3] = -1e30f;
                }
            }
            float m0 = -1e30f, m1 = -1e30f;
#pragma unroll
            for (int nt = 0; nt < 8; nt++) {
                m0 = fmaxf(m0, fmaxf(s[nt][0], s[nt][1]));
                m1 = fmaxf(m1, fmaxf(s[nt][2], s[nt][3]));
            }
            m0 = fmaxf(m0, __shfl_xor_sync(0xffffffffu, m0, 1));
            m0 = fmaxf(m0, __shfl_xor_sync(0xffffffffu, m0, 2));
            m1 = fmaxf(m1, __shfl_xor_sync(0xffffffffu, m1, 1));
            m1 = fmaxf(m1, __shfl_xor_sync(0xffffffffu, m1, 2));
            float nm0 = fmaxf(rm0, m0), nm1 = fmaxf(rm1, m1);
            float al0 = __expf(rm0 - nm0), al1 = __expf(rm1 - nm1);
            rm0 = nm0; rm1 = nm1;
            float l0 = 0.f, l1 = 0.f;
#pragma unroll
            for (int nt = 0; nt < 8; nt++) {
                s[nt][0] = tf32r(__expf(s[nt][0] - nm0));
                s[nt][1] = tf32r(__expf(s[nt][1] - nm0));
                s[nt][2] = tf32r(__expf(s[nt][2] - nm1));
                s[nt][3] = tf32r(__expf(s[nt][3] - nm1));
                l0 += s[nt][0] + s[nt][1];
                l1 += s[nt][2] + s[nt][3];
            }
            l0 += __shfl_xor_sync(0xffffffffu, l0, 1);
            l0 += __shfl_xor_sync(0xffffffffu, l0, 2);
            l1 += __shfl_xor_sync(0xffffffffu, l1, 1);
            l1 += __shfl_xor_sync(0xffffffffu, l1, 2);
            rs0 = rs0 * al0 + l0;
            rs1 = rs1 * al1 + l1;
#pragma unroll
            for (int nt = 0; nt < 8; nt++) {
                o[nt][0] *= al0; o[nt][1] *= al0;
                o[nt][2] *= al1; o[nt][3] *= al1;
            }
#pragma unroll
            for (int kt = 0; kt < 8; kt++) {
                float v00 = __shfl_sync(0xffffffffu, s[kt][0], src0);
                float v01 = __shfl_sync(0xffffffffu, s[kt][1], src0);
                float v02 = __shfl_sync(0xffffffffu, s[kt][2], src0);
                float v03 = __shfl_sync(0xffffffffu, s[kt][3], src0);
                float v10 = __shfl_sync(0xffffffffu, s[kt][0], src1);
                float v11 = __shfl_sync(0xffffffffu, s[kt][1], src1);
                float v12 = __shfl_sync(0xffffffffu, s[kt][2], src1);
                float v13 = __shfl_sync(0xffffffffu, s[kt][3], src1);
                float a[4];
                a[0] = hi ? v01 : v00;
                a[1] = hi ? v03 : v02;
                a[2] = hi ? v11 : v10;
                a[3] = hi ? v13 : v12;
                int kb = kt * 8 + tig;
#pragma unroll
                for (int nt = 0; nt < 8; nt++) {
                    float bfr[2] = { Vs[kb * 72 + nt * 8 + g],
                                     Vs[(kb + 4) * 72 + nt * 8 + g] };
                    mma8(o[nt], a, bfr);
                }
            }
        }
        __syncthreads();
    }

    float inv0 = 1.0f / rs0, inv1 = 1.0f / rs1;
    int r0 = i0 + warp * 16 + g;
#pragma unroll
    for (int nt = 0; nt < 8; nt++) {
        int col = h * HDD + nt * 8 + 2 * tig;
        float* p0 = ao + (size_t)(b * TT + r0) * DD + col;
        float* p1 = ao + (size_t)(b * TT + r0 + 8) * DD + col;
        *(float2*)p0 = make_float2(tf32r(o[nt][0] * inv0), tf32r(o[nt][1] * inv0));
        *(float2*)p1 = make_float2(tf32r(o[nt][2] * inv1), tf32r(o[nt][3] * inv1));
    }
}

// ---------------------------------------------------------------------------
// Launch
// ---------------------------------------------------------------------------
extern "C" void kernel_launch(void* const* d_in, const int* in_sizes, int n_in,
                              void* d_out, int out_size)
{
    const float* x      = (const float*)d_in[0];
    const float* w_pre  = (const float*)d_in[1];
    const float* wq     = (const float*)d_in[2];
    const float* wk     = (const float*)d_in[3];
    const float* wv     = (const float*)d_in[4];
    const float* wo     = (const float*)d_in[5];
    const float* w_attn = (const float*)d_in[6];
    const float* w1     = (const float*)d_in[7];
    const float* w2     = (const float*)d_in[8];
    const float* w_ffn  = (const float*)d_in[9];
    float* out = (float*)d_out;

    float *h_, *qkv_, *ao_, *tmp_, *y_, *mid_, *w_;
    cudaGetSymbolAddress((void**)&h_,   g_h);
    cudaGetSymbolAddress((void**)&qkv_, g_qkv);
    cudaGetSymbolAddress((void**)&ao_,  g_ao);
    cudaGetSymbolAddress((void**)&tmp_, g_tmp);
    cudaGetSymbolAddress((void**)&y_,   g_y);
    cudaGetSymbolAddress((void**)&mid_, g_mid);
    cudaGetSymbolAddress((void**)&w_,   g_w);

    // 0) pack + round weights (qkv interleaved)
    pack_kernel<<<12288, 256>>>((const float4*)wq, (const float4*)wk,
                                (const float4*)wv, (const float4*)wo,
                                (const float4*)w1, (const float4*)w2,
                                (float4*)w_);

    // 1) h = rmsnorm(x)
    rmsnorm_kernel<1><<<MT, 256>>>(x, nullptr, w_pre, h_);

    // 2) fused qkv projection: [4096x1024] @ [1024x3072]
    {
        dim3 g(QS / 128, MT / 128);    // 24 x 32 = 768 CTAs
        tgemm_kernel<0, 1><<<g, 128>>>(h_, w_ + WQKV_OFF, qkv_, MT, QS, DD);
    }

    // 3) fused flash attention
    {
        dim3 g(TT / 128, BB * HH);
        flash_kernel<<<g, 256>>>(qkv_, ao_);
    }

    // 4) o-proj + residual norm
    {
        dim3 g(DD / 128, MT / 128);    // 8 x 32 = 256
        tgemm_kernel<0, 0><<<g, 128>>>(ao_, w_ + WO_OFF, tmp_, MT, DD, DD);
    }
    rmsnorm_kernel<1><<<MT, 256>>>(h_, tmp_, w_attn, y_);

    // 5) FFN
    {
        dim3 g(FFD / 128, MT / 128);   // 32 x 32 = 1024
        tgemm_kernel<1, 1><<<g, 128>>>(y_, w_ + W1_OFF, mid_, MT, FFD, DD);
    }
    {
        dim3 g(DD / 128, MT / 128);
        tgemm_kernel<0, 0><<<g, 128>>>(mid_, w_ + W2_OFF, tmp_, MT, DD, FFD);
    }
    rmsnorm_kernel<0><<<MT, 256>>>(y_, tmp_, w_ffn, out);
}

// round 7
// speedup vs baseline: 1.3294x; 1.3294x over previous
#include <cuda_runtime.h>
#include <cstdint>
#include <cstddef>

#define BB   2
#define TT   2048
#define DD   1024
#define HH   16
#define HDD  64
#define FFD  4096
#define MT   (BB*TT)
#define QS   (3*DD)          // fused qkv row stride

// ---------------------------------------------------------------------------
// Scratch
// ---------------------------------------------------------------------------
__device__ float g_h  [MT*DD];
__device__ float g_qkv[MT*QS];
__device__ float g_ao [MT*DD];
__device__ float g_tmp[MT*DD];
__device__ float g_y  [MT*DD];
__device__ float g_mid[MT*FFD];
__device__ float g_w  [12*1024*1024]; // tf32: wqkv[1024][3072] | wo | w1 | w2

#define WQKV_OFF 0
#define WO_OFF (3*1024*1024)
#define W1_OFF (4*1024*1024)
#define W2_OFF (8*1024*1024)

// ---------------------------------------------------------------------------
// Helpers
// ---------------------------------------------------------------------------
__device__ __forceinline__ float tf32r(float x) {
    float r; asm("cvt.rna.tf32.f32 %0, %1;" : "=f"(r) : "f"(x)); return r;
}
__device__ __forceinline__ uint32_t smaddr(const void* p) {
    return (uint32_t)__cvta_generic_to_shared(p);
}
#define CP16(dst, src) asm volatile("cp.async.cg.shared.global [%0], [%1], 16;\n" :: "r"(dst), "l"(src))
#define CP_COMMIT()    asm volatile("cp.async.commit_group;\n")

__device__ __forceinline__ void mma8(float* d, const float* a, const float* b) {
    asm volatile(
        "mma.sync.aligned.m16n8k8.row.col.f32.tf32.tf32.f32 "
        "{%0,%1,%2,%3}, {%4,%5,%6,%7}, {%8,%9}, {%0,%1,%2,%3};\n"
        : "+f"(d[0]), "+f"(d[1]), "+f"(d[2]), "+f"(d[3])
        : "r"(__float_as_uint(a[0])), "r"(__float_as_uint(a[1])),
          "r"(__float_as_uint(a[2])), "r"(__float_as_uint(a[3])),
          "r"(__float_as_uint(b[0])), "r"(__float_as_uint(b[1])));
}

// ---------------------------------------------------------------------------
// Pack weights -> tf32, wq|wk|wv interleaved into [1024][3072]
// ---------------------------------------------------------------------------
__global__ void __launch_bounds__(256) pack_kernel(
    const float4* __restrict__ wq, const float4* __restrict__ wk,
    const float4* __restrict__ wv, const float4* __restrict__ wo,
    const float4* __restrict__ w1, const float4* __restrict__ w2,
    float4* __restrict__ out)
{
    int i = blockIdx.x * 256 + threadIdx.x;
    const int Q = 256 * 1024;
    float4 v; int dst;
    if (i < 3 * Q) {
        int sel = i / Q;
        int j = i - sel * Q;
        int r = j >> 8, c = j & 255;
        const float4* src = sel == 0 ? wq : (sel == 1 ? wk : wv);
        v = src[j];
        dst = r * 768 + sel * 256 + c;
    } else if (i < 4 * Q) {
        v = wo[i - 3 * Q]; dst = i;
    } else if (i < 8 * Q) {
        v = w1[i - 4 * Q]; dst = i;
    } else {
        v = w2[i - 8 * Q]; dst = i;
    }
    v.x = tf32r(v.x); v.y = tf32r(v.y); v.z = tf32r(v.z); v.w = tf32r(v.w);
    out[dst] = v;
}

// ---------------------------------------------------------------------------
// RMSNorm (optionally + residual); RND: round output to tf32
// ---------------------------------------------------------------------------
template <int RND>
__global__ void __launch_bounds__(256) rmsnorm_kernel(
    const float* __restrict__ a, const float* __restrict__ b,
    const float* __restrict__ w, float* __restrict__ out)
{
    int row = blockIdx.x;
    size_t base = (size_t)row * DD;
    float v[4];
    float ss = 0.f;
#pragma unroll
    for (int t = 0; t < 4; t++) {
        int c = threadIdx.x + t * 256;
        float x = a[base + c];
        if (b) x += b[base + c];
        v[t] = x;
        ss += x * x;
    }
    __shared__ float red[8];
#pragma unroll
    for (int o = 16; o; o >>= 1) ss += __shfl_xor_sync(0xffffffffu, ss, o);
    if ((threadIdx.x & 31) == 0) red[threadIdx.x >> 5] = ss;
    __syncthreads();
    if (threadIdx.x == 0) {
        float tot = 0.f;
#pragma unroll
        for (int i = 0; i < 8; i++) tot += red[i];
        red[0] = tot;
    }
    __syncthreads();
    float scale = rsqrtf(red[0] * (1.0f / DD) + 1e-6f);
#pragma unroll
    for (int t = 0; t < 4; t++) {
        int c = threadIdx.x + t * 256;
        float o = v[t] * scale * w[c];
        out[base + c] = RND ? tf32r(o) : o;
    }
}

// ---------------------------------------------------------------------------
// TF32 GEMM — R3-proven config: BM=BN=128, BK=16, 256 threads
// (8 warps x 64x32), 2-stage cp.async, launch_bounds(256,2).
// A loader: ar = tid>>2 (0..63, +64 second load), ac = (tid&3)*4 (0..15).
// ---------------------------------------------------------------------------
template <int EPI, int RND>
__global__ void __launch_bounds__(256, 2) tgemm_kernel(
    const float* __restrict__ A, const float* __restrict__ B,
    float* __restrict__ C, int M, int N, int K)
{
    __shared__ float As[2][128 * 20];
    __shared__ float Bs[2][16 * 136];

    int tid = threadIdx.x;
    int warp = tid >> 5, lane = tid & 31;
    int g = lane >> 2, tig = lane & 3;
    int wm = (warp >> 2) * 64, wn = (warp & 3) * 32;
    int bx = blockIdx.x, by = blockIdx.y;

    int ar = tid >> 2;            // 0..63 (+64 on second load)
    int ac = (tid & 3) * 4;       // 0,4,8,12
    int br = tid >> 5;            // 0..7 (+8 on second load)
    int bc = lane * 4;            // 0..124

    const float* a_src = A + (size_t)(by * 128 + ar) * K + ac;
    const float* b_src = B + (size_t)br * N + bx * 128 + bc;
    uint32_t a_dst = smaddr(&As[0][ar * 20 + ac]);
    uint32_t b_dst = smaddr(&Bs[0][br * 136 + bc]);

    float acc[4][4][4];
#pragma unroll
    for (int i = 0; i < 4; i++)
#pragma unroll
        for (int j = 0; j < 4; j++)
#pragma unroll
            for (int r = 0; r < 4; r++) acc[i][j][r] = 0.f;

    int KT = K >> 4;
    {
        CP16(a_dst, a_src);
        CP16(a_dst + 5120, a_src + (size_t)64 * K);   // rows ar+64
        CP16(b_dst, b_src);
        CP16(b_dst + 4352, b_src + (size_t)8 * N);    // k-rows br+8
        CP_COMMIT();
    }

    for (int kt = 0; kt < KT; kt++) {
        int buf = kt & 1;
        if (kt + 1 < KT) {
            int k0 = (kt + 1) << 4;
            uint32_t ad = a_dst + (buf ^ 1) * 10240;
            const float* as_ = a_src + k0;
            CP16(ad, as_);
            CP16(ad + 5120, as_ + (size_t)64 * K);
            uint32_t bd = b_dst + (buf ^ 1) * 8704;
            const float* bs_ = b_src + (size_t)k0 * N;
            CP16(bd, bs_);
            CP16(bd + 4352, bs_ + (size_t)8 * N);
            CP_COMMIT();
            asm volatile("cp.async.wait_group 1;\n");
        } else {
            asm volatile("cp.async.wait_group 0;\n");
        }
        __syncthreads();

        const float* as = As[buf];
        const float* bs = Bs[buf];
#pragma unroll
        for (int ch = 0; ch < 2; ch++) {
            int kb = ch * 8 + tig;
            float a[4][4], b[4][2];
#pragma unroll
            for (int mt = 0; mt < 4; mt++) {
                int m = wm + mt * 16 + g;
                a[mt][0] = as[m * 20 + kb];
                a[mt][1] = as[(m + 8) * 20 + kb];
                a[mt][2] = as[m * 20 + kb + 4];
                a[mt][3] = as[(m + 8) * 20 + kb + 4];
            }
#pragma unroll
            for (int nt = 0; nt < 4; nt++) {
                int n = wn + nt * 8 + g;
                b[nt][0] = bs[kb * 136 + n];
                b[nt][1] = bs[(kb + 4) * 136 + n];
            }
#pragma unroll
            for (int mt = 0; mt < 4; mt++)
#pragma unroll
                for (int nt = 0; nt < 4; nt++) mma8(acc[mt][nt], a[mt], b[nt]);
        }
        __syncthreads();
    }

#pragma unroll
    for (int mt = 0; mt < 4; mt++) {
#pragma unroll
        for (int nt = 0; nt < 4; nt++) {
            int row = by * 128 + wm + mt * 16 + g;
            int col = bx * 128 + wn + nt * 8 + 2 * tig;
            float e[4];
#pragma unroll
            for (int r = 0; r < 4; r++) {
                float c = acc[mt][nt][r];
                if (EPI == 1) c = c / (1.0f + __expf(-c));
                if (RND)      c = tf32r(c);
                e[r] = c;
            }
            *(float2*)&C[(size_t)row * N + col]       = make_float2(e[0], e[1]);
            *(float2*)&C[(size_t)(row + 8) * N + col] = make_float2(e[2], e[3]);
        }
    }
}

// ---------------------------------------------------------------------------
// Flash attention over fused qkv; heavy tiles scheduled first.
// ---------------------------------------------------------------------------
__global__ void __launch_bounds__(256) flash_kernel(
    const float* __restrict__ qkv, float* __restrict__ ao)
{
    int it = (int)gridDim.x - 1 - (int)blockIdx.x;   // heavy-first (LPT)
    int bh = blockIdx.y;
    int b = bh >> 4, h = bh & 15;
    int i0 = it * 128;

    __shared__ float smem[64 * 68 + 64 * 72];
    float* Ks = smem;
    float* Vs = smem + 64 * 68;
    float* Qstage = smem;

    int tid = threadIdx.x, warp = tid >> 5, lane = tid & 31;
    int g = lane >> 2, tig = lane & 3;

    const float* q = qkv + h * HDD;
    const float* k = qkv + DD + h * HDD;
    const float* v = qkv + 2 * DD + h * HDD;

    {
        int r = tid >> 1;
        int cb = (tid & 1) * 32;
        const float* qp = q + (size_t)(b * TT + i0 + r) * QS + cb;
        float* dst = Qstage + r * 68 + cb;
#pragma unroll
        for (int c4 = 0; c4 < 8; c4++)
            *(float4*)(dst + c4 * 4) = *(const float4*)(qp + c4 * 4);
    }
    __syncthreads();
    float qa[8][4];
    {
        int m = warp * 16 + g;
#pragma unroll
        for (int kt = 0; kt < 8; kt++) {
            int kb = kt * 8 + tig;
            qa[kt][0] = Qstage[m * 68 + kb] * 0.125f;
            qa[kt][1] = Qstage[(m + 8) * 68 + kb] * 0.125f;
            qa[kt][2] = Qstage[m * 68 + kb + 4] * 0.125f;
            qa[kt][3] = Qstage[(m + 8) * 68 + kb + 4] * 0.125f;
        }
    }
    __syncthreads();

    float o[8][4];
#pragma unroll
    for (int nt = 0; nt < 8; nt++)
#pragma unroll
        for (int r = 0; r < 4; r++) o[nt][r] = 0.f;
    float rm0 = -1e30f, rm1 = -1e30f, rs0 = 0.f, rs1 = 0.f;

    int jt_max = 2 * it + 1;
    int warp_row0 = i0 + warp * 16;
    int src0 = g * 4 + (tig >> 1);
    int src1 = src0 + 2;
    bool hi = tig & 1;

    for (int jt = 0; jt <= jt_max; jt++) {
        int j0 = jt * 64;
        {
            int r = tid >> 2, cb = (tid & 3) * 16;
            const float* kp = k + (size_t)(b * TT + j0 + r) * QS + cb;
            const float* vp = v + (size_t)(b * TT + j0 + r) * QS + cb;
#pragma unroll
            for (int c4 = 0; c4 < 4; c4++) {
                *(float4*)(Ks + r * 68 + cb + c4 * 4) = *(const float4*)(kp + c4 * 4);
                *(float4*)(Vs + r * 72 + cb + c4 * 4) = *(const float4*)(vp + c4 * 4);
            }
        }
        __syncthreads();

        if (j0 <= warp_row0 + 15) {
            float s[8][4];
#pragma unroll
            for (int nt = 0; nt < 8; nt++)
#pragma unroll
                for (int r = 0; r < 4; r++) s[nt][r] = 0.f;
#pragma unroll
            for (int kt = 0; kt < 8; kt++) {
                int kb = kt * 8 + tig;
#pragma unroll
                for (int nt = 0; nt < 8; nt++) {
                    float bfr[2] = { Ks[(nt * 8 + g) * 68 + kb],
                                     Ks[(nt * 8 + g) * 68 + kb + 4] };
                    mma8(s[nt], qa[kt], bfr);
                }
            }
            int r0 = warp_row0 + g, r1 = r0 + 8;
            if (j0 + 63 > warp_row0) {
#pragma unroll
                for (int nt = 0; nt < 8; nt++) {
                    int j = j0 + nt * 8 + 2 * tig;
                    if (j     > r0) s[nt][0] = -1e30f;
                    if (j + 1 > r0) s[nt][1] = -1e30f;
                    if (j     > r1) s[nt][2] = -1e30f;
                    if (j + 1 > r1) s[nt][3] = -1e30f;
                }
            }
            float m0 = -1e30f, m1 = -1e30f;
#pragma unroll
            for (int nt = 0; nt < 8; nt++) {
                m0 = fmaxf(m0, fmaxf(s[nt][0], s[nt][1]));
                m1 = fmaxf(m1, fmaxf(s[nt][2], s[nt][3]));
            }
            m0 = fmaxf(m0, __shfl_xor_sync(0xffffffffu, m0, 1));
            m0 = fmaxf(m0, __shfl_xor_sync(0xffffffffu, m0, 2));
            m1 = fmaxf(m1, __shfl_xor_sync(0xffffffffu, m1, 1));
            m1 = fmaxf(m1, __shfl_xor_sync(0xffffffffu, m1, 2));
            float nm0 = fmaxf(rm0, m0), nm1 = fmaxf(rm1, m1);
            float al0 = __expf(rm0 - nm0), al1 = __expf(rm1 - nm1);
            rm0 = nm0; rm1 = nm1;
            float l0 = 0.f, l1 = 0.f;
#pragma unroll
            for (int nt = 0; nt < 8; nt++) {
                s[nt][0] = tf32r(__expf(s[nt][0] - nm0));
                s[nt][1] = tf32r(__expf(s[nt][1] - nm0));
                s[nt][2] = tf32r(__expf(s[nt][2] - nm1));
                s[nt][3] = tf32r(__expf(s[nt][3] - nm1));
                l0 += s[nt][0] + s[nt][1];
                l1 += s[nt][2] + s[nt][3];
            }
            l0 += __shfl_xor_sync(0xffffffffu, l0, 1);
            l0 += __shfl_xor_sync(0xffffffffu, l0, 2);
            l1 += __shfl_xor_sync(0xffffffffu, l1, 1);
            l1 += __shfl_xor_sync(0xffffffffu, l1, 2);
            rs0 = rs0 * al0 + l0;
            rs1 = rs1 * al1 + l1;
#pragma unroll
            for (int nt = 0; nt < 8; nt++) {
                o[nt][0] *= al0; o[nt][1] *= al0;
                o[nt][2] *= al1; o[nt][3] *= al1;
            }
#pragma unroll
            for (int kt = 0; kt < 8; kt++) {
                float v00 = __shfl_sync(0xffffffffu, s[kt][0], src0);
                float v01 = __shfl_sync(0xffffffffu, s[kt][1], src0);
                float v02 = __shfl_sync(0xffffffffu, s[kt][2], src0);
                float v03 = __shfl_sync(0xffffffffu, s[kt][3], src0);
                float v10 = __shfl_sync(0xffffffffu, s[kt][0], src1);
                float v11 = __shfl_sync(0xffffffffu, s[kt][1], src1);
                float v12 = __shfl_sync(0xffffffffu, s[kt][2], src1);
                float v13 = __shfl_sync(0xffffffffu, s[kt][3], src1);
                float a[4];
                a[0] = hi ? v01 : v00;
                a[1] = hi ? v03 : v02;
                a[2] = hi ? v11 : v10;
                a[3] = hi ? v13 : v12;
                int kb = kt * 8 + tig;
#pragma unroll
                for (int nt = 0; nt < 8; nt++) {
                    float bfr[2] = { Vs[kb * 72 + nt * 8 + g],
                                     Vs[(kb + 4) * 72 + nt * 8 + g] };
                    mma8(o[nt], a, bfr);
                }
            }
        }
        __syncthreads();
    }

    float inv0 = 1.0f / rs0, inv1 = 1.0f / rs1;
    int r0 = i0 + warp * 16 + g;
#pragma unroll
    for (int nt = 0; nt < 8; nt++) {
        int col = h * HDD + nt * 8 + 2 * tig;
        float* p0 = ao + (size_t)(b * TT + r0) * DD + col;
        float* p1 = ao + (size_t)(b * TT + r0 + 8) * DD + col;
        *(float2*)p0 = make_float2(tf32r(o[nt][0] * inv0), tf32r(o[nt][1] * inv0));
        *(float2*)p1 = make_float2(tf32r(o[nt][2] * inv1), tf32r(o[nt][3] * inv1));
    }
}

// ---------------------------------------------------------------------------
// Launch
// ---------------------------------------------------------------------------
extern "C" void kernel_launch(void* const* d_in, const int* in_sizes, int n_in,
                              void* d_out, int out_size)
{
    const float* x      = (const float*)d_in[0];
    const float* w_pre  = (const float*)d_in[1];
    const float* wq     = (const float*)d_in[2];
    const float* wk     = (const float*)d_in[3];
    const float* wv     = (const float*)d_in[4];
    const float* wo     = (const float*)d_in[5];
    const float* w_attn = (const float*)d_in[6];
    const float* w1     = (const float*)d_in[7];
    const float* w2     = (const float*)d_in[8];
    const float* w_ffn  = (const float*)d_in[9];
    float* out = (float*)d_out;

    float *h_, *qkv_, *ao_, *tmp_, *y_, *mid_, *w_;
    cudaGetSymbolAddress((void**)&h_,   g_h);
    cudaGetSymbolAddress((void**)&qkv_, g_qkv);
    cudaGetSymbolAddress((void**)&ao_,  g_ao);
    cudaGetSymbolAddress((void**)&tmp_, g_tmp);
    cudaGetSymbolAddress((void**)&y_,   g_y);
    cudaGetSymbolAddress((void**)&mid_, g_mid);
    cudaGetSymbolAddress((void**)&w_,   g_w);

    // 0) pack + round weights
    pack_kernel<<<12288, 256>>>((const float4*)wq, (const float4*)wk,
                                (const float4*)wv, (const float4*)wo,
                                (const float4*)w1, (const float4*)w2,
                                (float4*)w_);

    // 1) h = rmsnorm(x)
    rmsnorm_kernel<1><<<MT, 256>>>(x, nullptr, w_pre, h_);

    // 2) fused qkv projection: [4096x1024] @ [1024x3072]
    {
        dim3 g(QS / 128, MT / 128);    // 24 x 32 = 768 CTAs
        tgemm_kernel<0, 1><<<g, 256>>>(h_, w_ + WQKV_OFF, qkv_, MT, QS, DD);
    }

    // 3) fused flash attention (heavy-first)
    {
        dim3 g(TT / 128, BB * HH);
        flash_kernel<<<g, 256>>>(qkv_, ao_);
    }

    // 4) o-proj + residual norm
    {
        dim3 g(DD / 128, MT / 128);
        tgemm_kernel<0, 0><<<g, 256>>>(ao_, w_ + WO_OFF, tmp_, MT, DD, DD);
    }
    rmsnorm_kernel<1><<<MT, 256>>>(h_, tmp_, w_attn, y_);

    // 5) FFN
    {
        dim3 g(FFD / 128, MT / 128);
        tgemm_kernel<1, 1><<<g, 256>>>(y_, w_ + W1_OFF, mid_, MT, FFD, DD);
    }
    {
        dim3 g(DD / 128, MT / 128);
        tgemm_kernel<0, 0><<<g, 256>>>(mid_, w_ + W2_OFF, tmp_, MT, DD, FFD);
    }
    rmsnorm_kernel<0><<<MT, 256>>>(y_, tmp_, w_ffn, out);
}

// round 8
// speedup vs baseline: 1.3479x; 1.0139x over previous
#include <cuda_runtime.h>
#include <cstdint>
#include <cstddef>

#define BB   2
#define TT   2048
#define DD   1024
#define HH   16
#define HDD  64
#define FFD  4096
#define MT   (BB*TT)
#define QS   (3*DD)          // fused qkv row stride

// ---------------------------------------------------------------------------
// Scratch
// ---------------------------------------------------------------------------
__device__ float g_h  [MT*DD];
__device__ float g_qkv[MT*QS];
__device__ float g_ao [MT*DD];
__device__ float g_tmp[MT*DD];
__device__ float g_y  [MT*DD];
__device__ float g_mid[MT*FFD];
__device__ float g_w  [12*1024*1024]; // tf32: wqkv[1024][3072] | wo | w1 | w2

#define WQKV_OFF 0
#define WO_OFF (3*1024*1024)
#define W1_OFF (4*1024*1024)
#define W2_OFF (8*1024*1024)

// ---------------------------------------------------------------------------
// Helpers
// ---------------------------------------------------------------------------
__device__ __forceinline__ float tf32r(float x) {
    float r; asm("cvt.rna.tf32.f32 %0, %1;" : "=f"(r) : "f"(x)); return r;
}
__device__ __forceinline__ uint32_t smaddr(const void* p) {
    return (uint32_t)__cvta_generic_to_shared(p);
}
#define CP16(dst, src) asm volatile("cp.async.cg.shared.global [%0], [%1], 16;\n" :: "r"(dst), "l"(src))
#define CP_COMMIT()    asm volatile("cp.async.commit_group;\n")

__device__ __forceinline__ void mma8(float* d, const float* a, const float* b) {
    asm volatile(
        "mma.sync.aligned.m16n8k8.row.col.f32.tf32.tf32.f32 "
        "{%0,%1,%2,%3}, {%4,%5,%6,%7}, {%8,%9}, {%0,%1,%2,%3};\n"
        : "+f"(d[0]), "+f"(d[1]), "+f"(d[2]), "+f"(d[3])
        : "r"(__float_as_uint(a[0])), "r"(__float_as_uint(a[1])),
          "r"(__float_as_uint(a[2])), "r"(__float_as_uint(a[3])),
          "r"(__float_as_uint(b[0])), "r"(__float_as_uint(b[1])));
}

// ---------------------------------------------------------------------------
// Pack weights -> tf32, wq|wk|wv interleaved into [1024][3072]
// ---------------------------------------------------------------------------
__global__ void __launch_bounds__(256) pack_kernel(
    const float4* __restrict__ wq, const float4* __restrict__ wk,
    const float4* __restrict__ wv, const float4* __restrict__ wo,
    const float4* __restrict__ w1, const float4* __restrict__ w2,
    float4* __restrict__ out)
{
    int i = blockIdx.x * 256 + threadIdx.x;
    const int Q = 256 * 1024;
    float4 v; int dst;
    if (i < 3 * Q) {
        int sel = i / Q;
        int j = i - sel * Q;
        int r = j >> 8, c = j & 255;
        const float4* src = sel == 0 ? wq : (sel == 1 ? wk : wv);
        v = src[j];
        dst = r * 768 + sel * 256 + c;
    } else if (i < 4 * Q) {
        v = wo[i - 3 * Q]; dst = i;
    } else if (i < 8 * Q) {
        v = w1[i - 4 * Q]; dst = i;
    } else {
        v = w2[i - 8 * Q]; dst = i;
    }
    v.x = tf32r(v.x); v.y = tf32r(v.y); v.z = tf32r(v.z); v.w = tf32r(v.w);
    out[dst] = v;
}

// ---------------------------------------------------------------------------
// RMSNorm (optionally + residual); RND: round output to tf32
// ---------------------------------------------------------------------------
template <int RND>
__global__ void __launch_bounds__(256) rmsnorm_kernel(
    const float* __restrict__ a, const float* __restrict__ b,
    const float* __restrict__ w, float* __restrict__ out)
{
    int row = blockIdx.x;
    size_t base = (size_t)row * DD;
    float v[4];
    float ss = 0.f;
#pragma unroll
    for (int t = 0; t < 4; t++) {
        int c = threadIdx.x + t * 256;
        float x = a[base + c];
        if (b) x += b[base + c];
        v[t] = x;
        ss += x * x;
    }
    __shared__ float red[8];
#pragma unroll
    for (int o = 16; o; o >>= 1) ss += __shfl_xor_sync(0xffffffffu, ss, o);
    if ((threadIdx.x & 31) == 0) red[threadIdx.x >> 5] = ss;
    __syncthreads();
    if (threadIdx.x == 0) {
        float tot = 0.f;
#pragma unroll
        for (int i = 0; i < 8; i++) tot += red[i];
        red[0] = tot;
    }
    __syncthreads();
    float scale = rsqrtf(red[0] * (1.0f / DD) + 1e-6f);
#pragma unroll
    for (int t = 0; t < 4; t++) {
        int c = threadIdx.x + t * 256;
        float o = v[t] * scale * w[c];
        out[base + c] = RND ? tf32r(o) : o;
    }
}

// ---------------------------------------------------------------------------
// TF32 GEMM — R3-proven config: BM=BN=128, BK=16, 256 threads
// (8 warps x 64x32), 2-stage cp.async, launch_bounds(256,2).
// ---------------------------------------------------------------------------
template <int EPI, int RND>
__global__ void __launch_bounds__(256, 2) tgemm_kernel(
    const float* __restrict__ A, const float* __restrict__ B,
    float* __restrict__ C, int M, int N, int K)
{
    __shared__ float As[2][128 * 20];
    __shared__ float Bs[2][16 * 136];

    int tid = threadIdx.x;
    int warp = tid >> 5, lane = tid & 31;
    int g = lane >> 2, tig = lane & 3;
    int wm = (warp >> 2) * 64, wn = (warp & 3) * 32;
    int bx = blockIdx.x, by = blockIdx.y;

    int ar = tid >> 2;            // 0..63 (+64 on second load)
    int ac = (tid & 3) * 4;       // 0,4,8,12
    int br = tid >> 5;            // 0..7 (+8 on second load)
    int bc = lane * 4;            // 0..124

    const float* a_src = A + (size_t)(by * 128 + ar) * K + ac;
    const float* b_src = B + (size_t)br * N + bx * 128 + bc;
    uint32_t a_dst = smaddr(&As[0][ar * 20 + ac]);
    uint32_t b_dst = smaddr(&Bs[0][br * 136 + bc]);

    float acc[4][4][4];
#pragma unroll
    for (int i = 0; i < 4; i++)
#pragma unroll
        for (int j = 0; j < 4; j++)
#pragma unroll
            for (int r = 0; r < 4; r++) acc[i][j][r] = 0.f;

    int KT = K >> 4;
    {
        CP16(a_dst, a_src);
        CP16(a_dst + 5120, a_src + (size_t)64 * K);
        CP16(b_dst, b_src);
        CP16(b_dst + 4352, b_src + (size_t)8 * N);
        CP_COMMIT();
    }

    for (int kt = 0; kt < KT; kt++) {
        int buf = kt & 1;
        if (kt + 1 < KT) {
            int k0 = (kt + 1) << 4;
            uint32_t ad = a_dst + (buf ^ 1) * 10240;
            const float* as_ = a_src + k0;
            CP16(ad, as_);
            CP16(ad + 5120, as_ + (size_t)64 * K);
            uint32_t bd = b_dst + (buf ^ 1) * 8704;
            const float* bs_ = b_src + (size_t)k0 * N;
            CP16(bd, bs_);
            CP16(bd + 4352, bs_ + (size_t)8 * N);
            CP_COMMIT();
            asm volatile("cp.async.wait_group 1;\n");
        } else {
            asm volatile("cp.async.wait_group 0;\n");
        }
        __syncthreads();

        const float* as = As[buf];
        const float* bs = Bs[buf];
#pragma unroll
        for (int ch = 0; ch < 2; ch++) {
            int kb = ch * 8 + tig;
            float a[4][4], b[4][2];
#pragma unroll
            for (int mt = 0; mt < 4; mt++) {
                int m = wm + mt * 16 + g;
                a[mt][0] = as[m * 20 + kb];
                a[mt][1] = as[(m + 8) * 20 + kb];
                a[mt][2] = as[m * 20 + kb + 4];
                a[mt][3] = as[(m + 8) * 20 + kb + 4];
            }
#pragma unroll
            for (int nt = 0; nt < 4; nt++) {
                int n = wn + nt * 8 + g;
                b[nt][0] = bs[kb * 136 + n];
                b[nt][1] = bs[(kb + 4) * 136 + n];
            }
#pragma unroll
            for (int mt = 0; mt < 4; mt++)
#pragma unroll
                for (int nt = 0; nt < 4; nt++) mma8(acc[mt][nt], a[mt], b[nt]);
        }
        __syncthreads();
    }

#pragma unroll
    for (int mt = 0; mt < 4; mt++) {
#pragma unroll
        for (int nt = 0; nt < 4; nt++) {
            int row = by * 128 + wm + mt * 16 + g;
            int col = bx * 128 + wn + nt * 8 + 2 * tig;
            float e[4];
#pragma unroll
            for (int r = 0; r < 4; r++) {
                float c = acc[mt][nt][r];
                if (EPI == 1) c = c / (1.0f + __expf(-c));
                if (RND)      c = tf32r(c);
                e[r] = c;
            }
            *(float2*)&C[(size_t)row * N + col]       = make_float2(e[0], e[1]);
            *(float2*)&C[(size_t)(row + 8) * N + col] = make_float2(e[2], e[3]);
        }
    }
}

// ---------------------------------------------------------------------------
// Flash attention over fused qkv; heavy tiles first; FORCED 2 CTAs/SM.
// ---------------------------------------------------------------------------
__global__ void __launch_bounds__(256, 2) flash_kernel(
    const float* __restrict__ qkv, float* __restrict__ ao)
{
    int it = (int)gridDim.x - 1 - (int)blockIdx.x;   // heavy-first (LPT)
    int bh = blockIdx.y;
    int b = bh >> 4, h = bh & 15;
    int i0 = it * 128;

    __shared__ float smem[64 * 68 + 64 * 72];
    float* Ks = smem;
    float* Vs = smem + 64 * 68;
    float* Qstage = smem;

    int tid = threadIdx.x, warp = tid >> 5, lane = tid & 31;
    int g = lane >> 2, tig = lane & 3;

    const float* q = qkv + h * HDD;
    const float* k = qkv + DD + h * HDD;
    const float* v = qkv + 2 * DD + h * HDD;

    {
        int r = tid >> 1;
        int cb = (tid & 1) * 32;
        const float* qp = q + (size_t)(b * TT + i0 + r) * QS + cb;
        float* dst = Qstage + r * 68 + cb;
#pragma unroll
        for (int c4 = 0; c4 < 8; c4++)
            *(float4*)(dst + c4 * 4) = *(const float4*)(qp + c4 * 4);
    }
    __syncthreads();
    float qa[8][4];
    {
        int m = warp * 16 + g;
#pragma unroll
        for (int kt = 0; kt < 8; kt++) {
            int kb = kt * 8 + tig;
            qa[kt][0] = Qstage[m * 68 + kb] * 0.125f;
            qa[kt][1] = Qstage[(m + 8) * 68 + kb] * 0.125f;
            qa[kt][2] = Qstage[m * 68 + kb + 4] * 0.125f;
            qa[kt][3] = Qstage[(m + 8) * 68 + kb + 4] * 0.125f;
        }
    }
    __syncthreads();

    float o[8][4];
#pragma unroll
    for (int nt = 0; nt < 8; nt++)
#pragma unroll
        for (int r = 0; r < 4; r++) o[nt][r] = 0.f;
    float rm0 = -1e30f, rm1 = -1e30f, rs0 = 0.f, rs1 = 0.f;

    int jt_max = 2 * it + 1;
    int warp_row0 = i0 + warp * 16;
    int src0 = g * 4 + (tig >> 1);
    int src1 = src0 + 2;
    bool hi = tig & 1;

    for (int jt = 0; jt <= jt_max; jt++) {
        int j0 = jt * 64;
        {
            int r = tid >> 2, cb = (tid & 3) * 16;
            const float* kp = k + (size_t)(b * TT + j0 + r) * QS + cb;
            const float* vp = v + (size_t)(b * TT + j0 + r) * QS + cb;
#pragma unroll
            for (int c4 = 0; c4 < 4; c4++) {
                *(float4*)(Ks + r * 68 + cb + c4 * 4) = *(const float4*)(kp + c4 * 4);
                *(float4*)(Vs + r * 72 + cb + c4 * 4) = *(const float4*)(vp + c4 * 4);
            }
        }
        __syncthreads();

        if (j0 <= warp_row0 + 15) {
            float s[8][4];
#pragma unroll
            for (int nt = 0; nt < 8; nt++)
#pragma unroll
                for (int r = 0; r < 4; r++) s[nt][r] = 0.f;
#pragma unroll
            for (int kt = 0; kt < 8; kt++) {
                int kb = kt * 8 + tig;
#pragma unroll
                for (int nt = 0; nt < 8; nt++) {
                    float bfr[2] = { Ks[(nt * 8 + g) * 68 + kb],
                                     Ks[(nt * 8 + g) * 68 + kb + 4] };
                    mma8(s[nt], qa[kt], bfr);
                }
            }
            int r0 = warp_row0 + g, r1 = r0 + 8;
            if (j0 + 63 > warp_row0) {
#pragma unroll
                for (int nt = 0; nt < 8; nt++) {
                    int j = j0 + nt * 8 + 2 * tig;
                    if (j     > r0) s[nt][0] = -1e30f;
                    if (j + 1 > r0) s[nt][1] = -1e30f;
                    if (j     > r1) s[nt][2] = -1e30f;
                    if (j + 1 > r1) s[nt][3] = -1e30f;
                }
            }
            float m0 = -1e30f, m1 = -1e30f;
#pragma unroll
            for (int nt = 0; nt < 8; nt++) {
                m0 = fmaxf(m0, fmaxf(s[nt][0], s[nt][1]));
                m1 = fmaxf(m1, fmaxf(s[nt][2], s[nt][3]));
            }
            m0 = fmaxf(m0, __shfl_xor_sync(0xffffffffu, m0, 1));
            m0 = fmaxf(m0, __shfl_xor_sync(0xffffffffu, m0, 2));
            m1 = fmaxf(m1, __shfl_xor_sync(0xffffffffu, m1, 1));
            m1 = fmaxf(m1, __shfl_xor_sync(0xffffffffu, m1, 2));
            float nm0 = fmaxf(rm0, m0), nm1 = fmaxf(rm1, m1);
            float al0 = __expf(rm0 - nm0), al1 = __expf(rm1 - nm1);
            rm0 = nm0; rm1 = nm1;
            float l0 = 0.f, l1 = 0.f;
#pragma unroll
            for (int nt = 0; nt < 8; nt++) {
                s[nt][0] = tf32r(__expf(s[nt][0] - nm0));
                s[nt][1] = tf32r(__expf(s[nt][1] - nm0));
                s[nt][2] = tf32r(__expf(s[nt][2] - nm1));
                s[nt][3] = tf32r(__expf(s[nt][3] - nm1));
                l0 += s[nt][0] + s[nt][1];
                l1 += s[nt][2] + s[nt][3];
            }
            l0 += __shfl_xor_sync(0xffffffffu, l0, 1);
            l0 += __shfl_xor_sync(0xffffffffu, l0, 2);
            l1 += __shfl_xor_sync(0xffffffffu, l1, 1);
            l1 += __shfl_xor_sync(0xffffffffu, l1, 2);
            rs0 = rs0 * al0 + l0;
            rs1 = rs1 * al1 + l1;
#pragma unroll
            for (int nt = 0; nt < 8; nt++) {
                o[nt][0] *= al0; o[nt][1] *= al0;
                o[nt][2] *= al1; o[nt][3] *= al1;
            }
#pragma unroll
            for (int kt = 0; kt < 8; kt++) {
                float v00 = __shfl_sync(0xffffffffu, s[kt][0], src0);
                float v01 = __shfl_sync(0xffffffffu, s[kt][1], src0);
                float v02 = __shfl_sync(0xffffffffu, s[kt][2], src0);
                float v03 = __shfl_sync(0xffffffffu, s[kt][3], src0);
                float v10 = __shfl_sync(0xffffffffu, s[kt][0], src1);
                float v11 = __shfl_sync(0xffffffffu, s[kt][1], src1);
                float v12 = __shfl_sync(0xffffffffu, s[kt][2], src1);
                float v13 = __shfl_sync(0xffffffffu, s[kt][3], src1);
                float a[4];
                a[0] = hi ? v01 : v00;
                a[1] = hi ? v03 : v02;
                a[2] = hi ? v11 : v10;
                a[3] = hi ? v13 : v12;
                int kb = kt * 8 + tig;
#pragma unroll
                for (int nt = 0; nt < 8; nt++) {
                    float bfr[2] = { Vs[kb * 72 + nt * 8 + g],
                                     Vs[(kb + 4) * 72 + nt * 8 + g] };
                    mma8(o[nt], a, bfr);
                }
            }
        }
        __syncthreads();
    }

    float inv0 = 1.0f / rs0, inv1 = 1.0f / rs1;
    int r0 = i0 + warp * 16 + g;
#pragma unroll
    for (int nt = 0; nt < 8; nt++) {
        int col = h * HDD + nt * 8 + 2 * tig;
        float* p0 = ao + (size_t)(b * TT + r0) * DD + col;
        float* p1 = ao + (size_t)(b * TT + r0 + 8) * DD + col;
        *(float2*)p0 = make_float2(tf32r(o[nt][0] * inv0), tf32r(o[nt][1] * inv0));
        *(float2*)p1 = make_float2(tf32r(o[nt][2] * inv1), tf32r(o[nt][3] * inv1));
    }
}

// ---------------------------------------------------------------------------
// Launch
// ---------------------------------------------------------------------------
extern "C" void kernel_launch(void* const* d_in, const int* in_sizes, int n_in,
                              void* d_out, int out_size)
{
    const float* x      = (const float*)d_in[0];
    const float* w_pre  = (const float*)d_in[1];
    const float* wq     = (const float*)d_in[2];
    const float* wk     = (const float*)d_in[3];
    const float* wv     = (const float*)d_in[4];
    const float* wo     = (const float*)d_in[5];
    const float* w_attn = (const float*)d_in[6];
    const float* w1     = (const float*)d_in[7];
    const float* w2     = (const float*)d_in[8];
    const float* w_ffn  = (const float*)d_in[9];
    float* out = (float*)d_out;

    float *h_, *qkv_, *ao_, *tmp_, *y_, *mid_, *w_;
    cudaGetSymbolAddress((void**)&h_,   g_h);
    cudaGetSymbolAddress((void**)&qkv_, g_qkv);
    cudaGetSymbolAddress((void**)&ao_,  g_ao);
    cudaGetSymbolAddress((void**)&tmp_, g_tmp);
    cudaGetSymbolAddress((void**)&y_,   g_y);
    cudaGetSymbolAddress((void**)&mid_, g_mid);
    cudaGetSymbolAddress((void**)&w_,   g_w);

    // 0) pack + round weights
    pack_kernel<<<12288, 256>>>((const float4*)wq, (const float4*)wk,
                                (const float4*)wv, (const float4*)wo,
                                (const float4*)w1, (const float4*)w2,
                                (float4*)w_);

    // 1) h = rmsnorm(x)
    rmsnorm_kernel<1><<<MT, 256>>>(x, nullptr, w_pre, h_);

    // 2) fused qkv projection: [4096x1024] @ [1024x3072]
    {
        dim3 g(QS / 128, MT / 128);    // 24 x 32 = 768 CTAs
        tgemm_kernel<0, 1><<<g, 256>>>(h_, w_ + WQKV_OFF, qkv_, MT, QS, DD);
    }

    // 3) fused flash attention (heavy-first, 2 CTAs/SM)
    {
        dim3 g(TT / 128, BB * HH);
        flash_kernel<<<g, 256>>>(qkv_, ao_);
    }

    // 4) o-proj + residual norm
    {
        dim3 g(DD / 128, MT / 128);
        tgemm_kernel<0, 0><<<g, 256>>>(ao_, w_ + WO_OFF, tmp_, MT, DD, DD);
    }
    rmsnorm_kernel<1><<<MT, 256>>>(h_, tmp_, w_attn, y_);

    // 5) FFN
    {
        dim3 g(FFD / 128, MT / 128);
        tgemm_kernel<1, 1><<<g, 256>>>(y_, w_ + W1_OFF, mid_, MT, FFD, DD);
    }
    {
        dim3 g(DD / 128, MT / 128);
        tgemm_kernel<0, 0><<<g, 256>>>(mid_, w_ + W2_OFF, tmp_, MT, DD, FFD);
    }
    rmsnorm_kernel<0><<<MT, 256>>>(y_, tmp_, w_ffn, out);
}

// round 9
// speedup vs baseline: 1.3906x; 1.0317x over previous
#include <cuda_runtime.h>
#include <cstdint>
#include <cstddef>

#define BB   2
#define TT   2048
#define DD   1024
#define HH   16
#define HDD  64
#define FFD  4096
#define MT   (BB*TT)
#define QS   (3*DD)          // fused qkv row stride

// ---------------------------------------------------------------------------
// Scratch
// ---------------------------------------------------------------------------
__device__ float g_h  [MT*DD];
__device__ float g_qkv[MT*QS];
__device__ float g_ao [MT*DD];
__device__ float g_tmp[MT*DD];
__device__ float g_y  [MT*DD];
__device__ float g_mid[MT*FFD];
__device__ float g_w  [12*1024*1024]; // tf32: wqkv[1024][3072] | wo | w1 | w2

#define WQKV_OFF 0
#define WO_OFF (3*1024*1024)
#define W1_OFF (4*1024*1024)
#define W2_OFF (8*1024*1024)

// ---------------------------------------------------------------------------
// Helpers
// ---------------------------------------------------------------------------
__device__ __forceinline__ float tf32r(float x) {
    float r; asm("cvt.rna.tf32.f32 %0, %1;" : "=f"(r) : "f"(x)); return r;
}
__device__ __forceinline__ uint32_t smaddr(const void* p) {
    return (uint32_t)__cvta_generic_to_shared(p);
}
#define CP16(dst, src) asm volatile("cp.async.cg.shared.global [%0], [%1], 16;\n" :: "r"(dst), "l"(src))
#define CP_COMMIT()    asm volatile("cp.async.commit_group;\n")

__device__ __forceinline__ void mma8(float* d, const float* a, const float* b) {
    asm volatile(
        "mma.sync.aligned.m16n8k8.row.col.f32.tf32.tf32.f32 "
        "{%0,%1,%2,%3}, {%4,%5,%6,%7}, {%8,%9}, {%0,%1,%2,%3};\n"
        : "+f"(d[0]), "+f"(d[1]), "+f"(d[2]), "+f"(d[3])
        : "r"(__float_as_uint(a[0])), "r"(__float_as_uint(a[1])),
          "r"(__float_as_uint(a[2])), "r"(__float_as_uint(a[3])),
          "r"(__float_as_uint(b[0])), "r"(__float_as_uint(b[1])));
}

// ---------------------------------------------------------------------------
// Pack weights -> tf32, wq|wk|wv interleaved into [1024][3072]
// ---------------------------------------------------------------------------
__global__ void __launch_bounds__(256) pack_kernel(
    const float4* __restrict__ wq, const float4* __restrict__ wk,
    const float4* __restrict__ wv, const float4* __restrict__ wo,
    const float4* __restrict__ w1, const float4* __restrict__ w2,
    float4* __restrict__ out)
{
    int i = blockIdx.x * 256 + threadIdx.x;
    const int Q = 256 * 1024;
    float4 v; int dst;
    if (i < 3 * Q) {
        int sel = i / Q;
        int j = i - sel * Q;
        int r = j >> 8, c = j & 255;
        const float4* src = sel == 0 ? wq : (sel == 1 ? wk : wv);
        v = src[j];
        dst = r * 768 + sel * 256 + c;
    } else if (i < 4 * Q) {
        v = wo[i - 3 * Q]; dst = i;
    } else if (i < 8 * Q) {
        v = w1[i - 4 * Q]; dst = i;
    } else {
        v = w2[i - 8 * Q]; dst = i;
    }
    v.x = tf32r(v.x); v.y = tf32r(v.y); v.z = tf32r(v.z); v.w = tf32r(v.w);
    out[dst] = v;
}

// ---------------------------------------------------------------------------
// RMSNorm (optionally + residual); RND: round output to tf32
// ---------------------------------------------------------------------------
template <int RND>
__global__ void __launch_bounds__(256) rmsnorm_kernel(
    const float* __restrict__ a, const float* __restrict__ b,
    const float* __restrict__ w, float* __restrict__ out)
{
    int row = blockIdx.x;
    size_t base = (size_t)row * DD;
    float v[4];
    float ss = 0.f;
#pragma unroll
    for (int t = 0; t < 4; t++) {
        int c = threadIdx.x + t * 256;
        float x = a[base + c];
        if (b) x += b[base + c];
        v[t] = x;
        ss += x * x;
    }
    __shared__ float red[8];
#pragma unroll
    for (int o = 16; o; o >>= 1) ss += __shfl_xor_sync(0xffffffffu, ss, o);
    if ((threadIdx.x & 31) == 0) red[threadIdx.x >> 5] = ss;
    __syncthreads();
    if (threadIdx.x == 0) {
        float tot = 0.f;
#pragma unroll
        for (int i = 0; i < 8; i++) tot += red[i];
        red[0] = tot;
    }
    __syncthreads();
    float scale = rsqrtf(red[0] * (1.0f / DD) + 1e-6f);
#pragma unroll
    for (int t = 0; t < 4; t++) {
        int c = threadIdx.x + t * 256;
        float o = v[t] * scale * w[c];
        out[base + c] = RND ? tf32r(o) : o;
    }
}

// ---------------------------------------------------------------------------
// TF32 GEMM — R3 tile config + 3-stage cp.async pipeline.
// BM=BN=128, BK=16, 256 threads (8 warps x 64x32), launch_bounds(256,2).
// ---------------------------------------------------------------------------
template <int EPI, int RND>
__global__ void __launch_bounds__(256, 2) tgemm_kernel(
    const float* __restrict__ A, const float* __restrict__ B,
    float* __restrict__ C, int M, int N, int K)
{
    __shared__ float As[3][128 * 20];
    __shared__ float Bs[3][16 * 136];

    int tid = threadIdx.x;
    int warp = tid >> 5, lane = tid & 31;
    int g = lane >> 2, tig = lane & 3;
    int wm = (warp >> 2) * 64, wn = (warp & 3) * 32;
    int bx = blockIdx.x, by = blockIdx.y;

    int ar = tid >> 2;            // 0..63 (+64 on second load)
    int ac = (tid & 3) * 4;       // 0,4,8,12
    int br = tid >> 5;            // 0..7 (+8 on second load)
    int bc = lane * 4;            // 0..124

    const float* a_src = A + (size_t)(by * 128 + ar) * K + ac;
    const float* b_src = B + (size_t)br * N + bx * 128 + bc;
    uint32_t a_dst = smaddr(&As[0][ar * 20 + ac]);
    uint32_t b_dst = smaddr(&Bs[0][br * 136 + bc]);

    float acc[4][4][4];
#pragma unroll
    for (int i = 0; i < 4; i++)
#pragma unroll
        for (int j = 0; j < 4; j++)
#pragma unroll
            for (int r = 0; r < 4; r++) acc[i][j][r] = 0.f;

    int KT = K >> 4;

#define ISSUE(stage, kt)                                                     \
    {                                                                        \
        uint32_t ad = a_dst + (stage) * 10240;                               \
        const float* ap = a_src + ((kt) << 4);                               \
        CP16(ad, ap);                                                        \
        CP16(ad + 5120, ap + (size_t)64 * K);                                \
        uint32_t bd = b_dst + (stage) * 8704;                                \
        const float* bp = b_src + (size_t)((kt) << 4) * N;                   \
        CP16(bd, bp);                                                        \
        CP16(bd + 4352, bp + (size_t)8 * N);                                 \
        CP_COMMIT();                                                         \
    }

    ISSUE(0, 0);
    if (KT > 1) ISSUE(1, 1);

    int st = 2;      // next stage to fill
    int buf = 0;     // stage to consume
    for (int kt = 0; kt < KT; kt++) {
        if (kt + 2 < KT) {
            ISSUE(st, kt + 2);
            st = (st == 2) ? 0 : st + 1;
            asm volatile("cp.async.wait_group 2;\n");
        } else if (kt + 1 < KT) {
            asm volatile("cp.async.wait_group 1;\n");
        } else {
            asm volatile("cp.async.wait_group 0;\n");
        }
        __syncthreads();

        const float* as = As[buf];
        const float* bs = Bs[buf];
#pragma unroll
        for (int ch = 0; ch < 2; ch++) {
            int kb = ch * 8 + tig;
            float a[4][4], b[4][2];
#pragma unroll
            for (int mt = 0; mt < 4; mt++) {
                int m = wm + mt * 16 + g;
                a[mt][0] = as[m * 20 + kb];
                a[mt][1] = as[(m + 8) * 20 + kb];
                a[mt][2] = as[m * 20 + kb + 4];
                a[mt][3] = as[(m + 8) * 20 + kb + 4];
            }
#pragma unroll
            for (int nt = 0; nt < 4; nt++) {
                int n = wn + nt * 8 + g;
                b[nt][0] = bs[kb * 136 + n];
                b[nt][1] = bs[(kb + 4) * 136 + n];
            }
#pragma unroll
            for (int mt = 0; mt < 4; mt++)
#pragma unroll
                for (int nt = 0; nt < 4; nt++) mma8(acc[mt][nt], a[mt], b[nt]);
        }
        __syncthreads();
        buf = (buf == 2) ? 0 : buf + 1;
    }
#undef ISSUE

#pragma unroll
    for (int mt = 0; mt < 4; mt++) {
#pragma unroll
        for (int nt = 0; nt < 4; nt++) {
            int row = by * 128 + wm + mt * 16 + g;
            int col = bx * 128 + wn + nt * 8 + 2 * tig;
            float e[4];
#pragma unroll
            for (int r = 0; r < 4; r++) {
                float c = acc[mt][nt][r];
                if (EPI == 1) c = c / (1.0f + __expf(-c));
                if (RND)      c = tf32r(c);
                e[r] = c;
            }
            *(float2*)&C[(size_t)row * N + col]       = make_float2(e[0], e[1]);
            *(float2*)&C[(size_t)(row + 8) * N + col] = make_float2(e[2], e[3]);
        }
    }
}

// ---------------------------------------------------------------------------
// Flash attention, cp.async pipelined: K double-buffered, V single-buffered.
// Per tile: [issue V | prefetch K(next)] -> wait K -> QK+softmax (V hides)
//           -> wait V -> PV.  Heavy tiles first; 2 CTAs/SM.
// smem: K0(4352) K1(4352) V(4608) = 13312 floats = 52KB. Qstage aliases K0|K1.
// ---------------------------------------------------------------------------
__global__ void __launch_bounds__(256, 2) flash_kernel(
    const float* __restrict__ qkv, float* __restrict__ ao)
{
    int it = (int)gridDim.x - 1 - (int)blockIdx.x;   // heavy-first (LPT)
    int bh = blockIdx.y;
    int b = bh >> 4, h = bh & 15;
    int i0 = it * 128;

    __shared__ float smem[2 * 64 * 68 + 64 * 72];
    float* Kbuf0  = smem;
    float* Kbuf1  = smem + 64 * 68;
    float* Vs     = smem + 2 * 64 * 68;
    float* Qstage = smem;                 // 128*68 = both K buffers

    int tid = threadIdx.x, warp = tid >> 5, lane = tid & 31;
    int g = lane >> 2, tig = lane & 3;

    const float* q = qkv + h * HDD;
    const float* k = qkv + DD + h * HDD;
    const float* v = qkv + 2 * DD + h * HDD;

    // ---- stage Q, pull to regs ----
    {
        int r = tid >> 1;
        int cb = (tid & 1) * 32;
        const float* qp = q + (size_t)(b * TT + i0 + r) * QS + cb;
        float* dst = Qstage + r * 68 + cb;
#pragma unroll
        for (int c4 = 0; c4 < 8; c4++)
            *(float4*)(dst + c4 * 4) = *(const float4*)(qp + c4 * 4);
    }
    __syncthreads();
    float qa[8][4];
    {
        int m = warp * 16 + g;
#pragma unroll
        for (int kt = 0; kt < 8; kt++) {
            int kb = kt * 8 + tig;
            qa[kt][0] = Qstage[m * 68 + kb] * 0.125f;
            qa[kt][1] = Qstage[(m + 8) * 68 + kb] * 0.125f;
            qa[kt][2] = Qstage[m * 68 + kb + 4] * 0.125f;
            qa[kt][3] = Qstage[(m + 8) * 68 + kb + 4] * 0.125f;
        }
    }
    __syncthreads();   // Qstage free; K buffers may now be overwritten

    // per-thread load coords (64x64 tile, 4x CP16 each)
    int lr = tid >> 2, lc = (tid & 3) * 16;
    const float* krow = k + (size_t)(b * TT + lr) * QS + lc;
    const float* vrow = v + (size_t)(b * TT + lr) * QS + lc;
    uint32_t kd0 = smaddr(Kbuf0 + lr * 68 + lc);
    uint32_t kd1 = smaddr(Kbuf1 + lr * 68 + lc);
    uint32_t vd  = smaddr(Vs + lr * 72 + lc);

    int jt_max = 2 * it + 1;

    // prefetch K(0) -> Kbuf0
    {
        const float* kp = krow;                       // j0 = 0
#pragma unroll
        for (int c4 = 0; c4 < 4; c4++) CP16(kd0 + c4 * 16, kp + c4 * 4);
        CP_COMMIT();
    }

    float o[8][4];
#pragma unroll
    for (int nt = 0; nt < 8; nt++)
#pragma unroll
        for (int r = 0; r < 4; r++) o[nt][r] = 0.f;
    float rm0 = -1e30f, rm1 = -1e30f, rs0 = 0.f, rs1 = 0.f;

    int warp_row0 = i0 + warp * 16;
    int src0 = g * 4 + (tig >> 1);
    int src1 = src0 + 2;
    bool hi = tig & 1;

    for (int jt = 0; jt <= jt_max; jt++) {
        int j0 = jt * 64;
        const float* Ks = (jt & 1) ? Kbuf1 : Kbuf0;
        bool has_next = (jt < jt_max);

        // issue V(jt)
        {
            const float* vp = vrow + (size_t)j0 * QS;
#pragma unroll
            for (int c4 = 0; c4 < 4; c4++) CP16(vd + c4 * 16, vp + c4 * 4);
            CP_COMMIT();
        }
        // prefetch K(jt+1)
        if (has_next) {
            const float* kp = krow + (size_t)(j0 + 64) * QS;
            uint32_t kd = (jt & 1) ? kd0 : kd1;
#pragma unroll
            for (int c4 = 0; c4 < 4; c4++) CP16(kd + c4 * 16, kp + c4 * 4);
            CP_COMMIT();
        }
        // wait for K(jt): allow {V, K(jt+1)} pending
        if (has_next) asm volatile("cp.async.wait_group 2;\n");
        else          asm volatile("cp.async.wait_group 1;\n");
        __syncthreads();

        float s[8][4];
        bool active = (j0 <= warp_row0 + 15);
        if (active) {
            // ---- S = Q K^T ----
#pragma unroll
            for (int nt = 0; nt < 8; nt++)
#pragma unroll
                for (int r = 0; r < 4; r++) s[nt][r] = 0.f;
#pragma unroll
            for (int kt = 0; kt < 8; kt++) {
                int kb = kt * 8 + tig;
#pragma unroll
                for (int nt = 0; nt < 8; nt++) {
                    float bfr[2] = { Ks[(nt * 8 + g) * 68 + kb],
                                     Ks[(nt * 8 + g) * 68 + kb + 4] };
                    mma8(s[nt], qa[kt], bfr);
                }
            }
            int r0 = warp_row0 + g, r1 = r0 + 8;
            if (j0 + 63 > warp_row0) {
#pragma unroll
                for (int nt = 0; nt < 8; nt++) {
                    int j = j0 + nt * 8 + 2 * tig;
                    if (j     > r0) s[nt][0] = -1e30f;
                    if (j + 1 > r0) s[nt][1] = -1e30f;
                    if (j     > r1) s[nt][2] = -1e30f;
                    if (j + 1 > r1) s[nt][3] = -1e30f;
                }
            }
            // ---- online softmax ----
            float m0 = -1e30f, m1 = -1e30f;
#pragma unroll
            for (int nt = 0; nt < 8; nt++) {
                m0 = fmaxf(m0, fmaxf(s[nt][0], s[nt][1]));
                m1 = fmaxf(m1, fmaxf(s[nt][2], s[nt][3]));
            }
            m0 = fmaxf(m0, __shfl_xor_sync(0xffffffffu, m0, 1));
            m0 = fmaxf(m0, __shfl_xor_sync(0xffffffffu, m0, 2));
            m1 = fmaxf(m1, __shfl_xor_sync(0xffffffffu, m1, 1));
            m1 = fmaxf(m1, __shfl_xor_sync(0xffffffffu, m1, 2));
            float nm0 = fmaxf(rm0, m0), nm1 = fmaxf(rm1, m1);
            float al0 = __expf(rm0 - nm0), al1 = __expf(rm1 - nm1);
            rm0 = nm0; rm1 = nm1;
            float l0 = 0.f, l1 = 0.f;
#pragma unroll
            for (int nt = 0; nt < 8; nt++) {
                s[nt][0] = tf32r(__expf(s[nt][0] - nm0));
                s[nt][1] = tf32r(__expf(s[nt][1] - nm0));
                s[nt][2] = tf32r(__expf(s[nt][2] - nm1));
                s[nt][3] = tf32r(__expf(s[nt][3] - nm1));
                l0 += s[nt][0] + s[nt][1];
                l1 += s[nt][2] + s[nt][3];
            }
            l0 += __shfl_xor_sync(0xffffffffu, l0, 1);
            l0 += __shfl_xor_sync(0xffffffffu, l0, 2);
            l1 += __shfl_xor_sync(0xffffffffu, l1, 1);
            l1 += __shfl_xor_sync(0xffffffffu, l1, 2);
            rs0 = rs0 * al0 + l0;
            rs1 = rs1 * al1 + l1;
#pragma unroll
            for (int nt = 0; nt < 8; nt++) {
                o[nt][0] *= al0; o[nt][1] *= al0;
                o[nt][2] *= al1; o[nt][3] *= al1;
            }
        }
        // wait for V(jt): allow {K(jt+1)} pending
        if (has_next) asm volatile("cp.async.wait_group 1;\n");
        else          asm volatile("cp.async.wait_group 0;\n");
        __syncthreads();

        if (active) {
            // ---- O += P V (P C-frag -> A-frag via shuffles) ----
#pragma unroll
            for (int kt = 0; kt < 8; kt++) {
                float v00 = __shfl_sync(0xffffffffu, s[kt][0], src0);
                float v01 = __shfl_sync(0xffffffffu, s[kt][1], src0);
                float v02 = __shfl_sync(0xffffffffu, s[kt][2], src0);
                float v03 = __shfl_sync(0xffffffffu, s[kt][3], src0);
                float v10 = __shfl_sync(0xffffffffu, s[kt][0], src1);
                float v11 = __shfl_sync(0xffffffffu, s[kt][1], src1);
                float v12 = __shfl_sync(0xffffffffu, s[kt][2], src1);
                float v13 = __shfl_sync(0xffffffffu, s[kt][3], src1);
                float a[4];
                a[0] = hi ? v01 : v00;
                a[1] = hi ? v03 : v02;
                a[2] = hi ? v11 : v10;
                a[3] = hi ? v13 : v12;
                int kb = kt * 8 + tig;
#pragma unroll
                for (int nt = 0; nt < 8; nt++) {
                    float bfr[2] = { Vs[kb * 72 + nt * 8 + g],
                                     Vs[(kb + 4) * 72 + nt * 8 + g] };
                    mma8(o[nt], a, bfr);
                }
            }
        }
        __syncthreads();   // Vs reusable next iter
    }

    float inv0 = 1.0f / rs0, inv1 = 1.0f / rs1;
    int r0 = i0 + warp * 16 + g;
#pragma unroll
    for (int nt = 0; nt < 8; nt++) {
        int col = h * HDD + nt * 8 + 2 * tig;
        float* p0 = ao + (size_t)(b * TT + r0) * DD + col;
        float* p1 = ao + (size_t)(b * TT + r0 + 8) * DD + col;
        *(float2*)p0 = make_float2(tf32r(o[nt][0] * inv0), tf32r(o[nt][1] * inv0));
        *(float2*)p1 = make_float2(tf32r(o[nt][2] * inv1), tf32r(o[nt][3] * inv1));
    }
}

// ---------------------------------------------------------------------------
// Launch
// ---------------------------------------------------------------------------
extern "C" void kernel_launch(void* const* d_in, const int* in_sizes, int n_in,
                              void* d_out, int out_size)
{
    const float* x      = (const float*)d_in[0];
    const float* w_pre  = (const float*)d_in[1];
    const float* wq     = (const float*)d_in[2];
    const float* wk     = (const float*)d_in[3];
    const float* wv     = (const float*)d_in[4];
    const float* wo     = (const float*)d_in[5];
    const float* w_attn = (const float*)d_in[6];
    const float* w1     = (const float*)d_in[7];
    const float* w2     = (const float*)d_in[8];
    const float* w_ffn  = (const float*)d_in[9];
    float* out = (float*)d_out;

    float *h_, *qkv_, *ao_, *tmp_, *y_, *mid_, *w_;
    cudaGetSymbolAddress((void**)&h_,   g_h);
    cudaGetSymbolAddress((void**)&qkv_, g_qkv);
    cudaGetSymbolAddress((void**)&ao_,  g_ao);
    cudaGetSymbolAddress((void**)&tmp_, g_tmp);
    cudaGetSymbolAddress((void**)&y_,   g_y);
    cudaGetSymbolAddress((void**)&mid_, g_mid);
    cudaGetSymbolAddress((void**)&w_,   g_w);

    // 0) pack + round weights
    pack_kernel<<<12288, 256>>>((const float4*)wq, (const float4*)wk,
                                (const float4*)wv, (const float4*)wo,
                                (const float4*)w1, (const float4*)w2,
                                (float4*)w_);

    // 1) h = rmsnorm(x)
    rmsnorm_kernel<1><<<MT, 256>>>(x, nullptr, w_pre, h_);

    // 2) fused qkv projection: [4096x1024] @ [1024x3072]
    {
        dim3 g(QS / 128, MT / 128);    // 24 x 32 = 768 CTAs
        tgemm_kernel<0, 1><<<g, 256>>>(h_, w_ + WQKV_OFF, qkv_, MT, QS, DD);
    }

    // 3) fused flash attention (pipelined, heavy-first, 2 CTAs/SM)
    {
        dim3 g(TT / 128, BB * HH);
        flash_kernel<<<g, 256>>>(qkv_, ao_);
    }

    // 4) o-proj + residual norm
    {
        dim3 g(DD / 128, MT / 128);
        tgemm_kernel<0, 0><<<g, 256>>>(ao_, w_ + WO_OFF, tmp_, MT, DD, DD);
    }
    rmsnorm_kernel<1><<<MT, 256>>>(h_, tmp_, w_attn, y_);

    // 5) FFN
    {
        dim3 g(FFD / 128, MT / 128);
        tgemm_kernel<1, 1><<<g, 256>>>(y_, w_ + W1_OFF, mid_, MT, FFD, DD);
    }
    {
        dim3 g(DD / 128, MT / 128);
        tgemm_kernel<0, 0><<<g, 256>>>(mid_, w_ + W2_OFF, tmp_, MT, DD, FFD);
    }
    rmsnorm_kernel<0><<<MT, 256>>>(y_, tmp_, w_ffn, out);
}

// round 10
// speedup vs baseline: 1.4065x; 1.0114x over previous
#include <cuda_runtime.h>
#include <cstdint>
#include <cstddef>

#define BB   2
#define TT   2048
#define DD   1024
#define HH   16
#define HDD  64
#define FFD  4096
#define MT   (BB*TT)
#define QS   (3*DD)          // fused qkv row stride

// ---------------------------------------------------------------------------
// Scratch
// ---------------------------------------------------------------------------
__device__ float g_h  [MT*DD];
__device__ float g_qkv[MT*QS];
__device__ float g_ao [MT*DD];
__device__ float g_tmp[MT*DD];
__device__ float g_y  [MT*DD];
__device__ float g_mid[MT*FFD];
__device__ float g_w  [12*1024*1024]; // tf32: wqkv[1024][3072] | wo | w1 | w2

#define WQKV_OFF 0
#define WO_OFF (3*1024*1024)
#define W1_OFF (4*1024*1024)
#define W2_OFF (8*1024*1024)

// ---------------------------------------------------------------------------
// Helpers
// ---------------------------------------------------------------------------
__device__ __forceinline__ float tf32r(float x) {
    float r; asm("cvt.rna.tf32.f32 %0, %1;" : "=f"(r) : "f"(x)); return r;
}
__device__ __forceinline__ uint32_t smaddr(const void* p) {
    return (uint32_t)__cvta_generic_to_shared(p);
}
#define CP16(dst, src) asm volatile("cp.async.cg.shared.global [%0], [%1], 16;\n" :: "r"(dst), "l"(src))
#define CP_COMMIT()    asm volatile("cp.async.commit_group;\n")

__device__ __forceinline__ void mma8(float* d, const float* a, const float* b) {
    asm volatile(
        "mma.sync.aligned.m16n8k8.row.col.f32.tf32.tf32.f32 "
        "{%0,%1,%2,%3}, {%4,%5,%6,%7}, {%8,%9}, {%0,%1,%2,%3};\n"
        : "+f"(d[0]), "+f"(d[1]), "+f"(d[2]), "+f"(d[3])
        : "r"(__float_as_uint(a[0])), "r"(__float_as_uint(a[1])),
          "r"(__float_as_uint(a[2])), "r"(__float_as_uint(a[3])),
          "r"(__float_as_uint(b[0])), "r"(__float_as_uint(b[1])));
}

// ---------------------------------------------------------------------------
// Pack weights -> tf32, wq|wk|wv interleaved into [1024][3072]
// ---------------------------------------------------------------------------
__global__ void __launch_bounds__(256) pack_kernel(
    const float4* __restrict__ wq, const float4* __restrict__ wk,
    const float4* __restrict__ wv, const float4* __restrict__ wo,
    const float4* __restrict__ w1, const float4* __restrict__ w2,
    float4* __restrict__ out)
{
    int i = blockIdx.x * 256 + threadIdx.x;
    const int Q = 256 * 1024;
    float4 v; int dst;
    if (i < 3 * Q) {
        int sel = i / Q;
        int j = i - sel * Q;
        int r = j >> 8, c = j & 255;
        const float4* src = sel == 0 ? wq : (sel == 1 ? wk : wv);
        v = src[j];
        dst = r * 768 + sel * 256 + c;
    } else if (i < 4 * Q) {
        v = wo[i - 3 * Q]; dst = i;
    } else if (i < 8 * Q) {
        v = w1[i - 4 * Q]; dst = i;
    } else {
        v = w2[i - 8 * Q]; dst = i;
    }
    v.x = tf32r(v.x); v.y = tf32r(v.y); v.z = tf32r(v.z); v.w = tf32r(v.w);
    out[dst] = v;
}

// ---------------------------------------------------------------------------
// RMSNorm (optionally + residual); RND: round output to tf32
// ---------------------------------------------------------------------------
template <int RND>
__global__ void __launch_bounds__(256) rmsnorm_kernel(
    const float* __restrict__ a, const float* __restrict__ b,
    const float* __restrict__ w, float* __restrict__ out)
{
    int row = blockIdx.x;
    size_t base = (size_t)row * DD;
    float v[4];
    float ss = 0.f;
#pragma unroll
    for (int t = 0; t < 4; t++) {
        int c = threadIdx.x + t * 256;
        float x = a[base + c];
        if (b) x += b[base + c];
        v[t] = x;
        ss += x * x;
    }
    __shared__ float red[8];
#pragma unroll
    for (int o = 16; o; o >>= 1) ss += __shfl_xor_sync(0xffffffffu, ss, o);
    if ((threadIdx.x & 31) == 0) red[threadIdx.x >> 5] = ss;
    __syncthreads();
    if (threadIdx.x == 0) {
        float tot = 0.f;
#pragma unroll
        for (int i = 0; i < 8; i++) tot += red[i];
        red[0] = tot;
    }
    __syncthreads();
    float scale = rsqrtf(red[0] * (1.0f / DD) + 1e-6f);
#pragma unroll
    for (int t = 0; t < 4; t++) {
        int c = threadIdx.x + t * 256;
        float o = v[t] * scale * w[c];
        out[base + c] = RND ? tf32r(o) : o;
    }
}

// ---------------------------------------------------------------------------
// TF32 GEMM — R3 tile config, 3-stage cp.async, ONE sync per K-chunk.
// BM=BN=128, BK=16, 256 threads (8 warps x 64x32), launch_bounds(256,2).
// ---------------------------------------------------------------------------
template <int EPI, int RND>
__global__ void __launch_bounds__(256, 2) tgemm_kernel(
    const float* __restrict__ A, const float* __restrict__ B,
    float* __restrict__ C, int M, int N, int K)
{
    __shared__ float As[3][128 * 20];
    __shared__ float Bs[3][16 * 136];

    int tid = threadIdx.x;
    int warp = tid >> 5, lane = tid & 31;
    int g = lane >> 2, tig = lane & 3;
    int wm = (warp >> 2) * 64, wn = (warp & 3) * 32;
    int bx = blockIdx.x, by = blockIdx.y;

    int ar = tid >> 2;            // 0..63 (+64 on second load)
    int ac = (tid & 3) * 4;       // 0,4,8,12
    int br = tid >> 5;            // 0..7 (+8 on second load)
    int bc = lane * 4;            // 0..124

    const float* a_src = A + (size_t)(by * 128 + ar) * K + ac;
    const float* b_src = B + (size_t)br * N + bx * 128 + bc;
    uint32_t a_dst = smaddr(&As[0][ar * 20 + ac]);
    uint32_t b_dst = smaddr(&Bs[0][br * 136 + bc]);

    float acc[4][4][4];
#pragma unroll
    for (int i = 0; i < 4; i++)
#pragma unroll
        for (int j = 0; j < 4; j++)
#pragma unroll
            for (int r = 0; r < 4; r++) acc[i][j][r] = 0.f;

    int KT = K >> 4;

#define ISSUE(stage, kt)                                                     \
    {                                                                        \
        uint32_t ad = a_dst + (stage) * 10240;                               \
        const float* ap = a_src + ((kt) << 4);                               \
        CP16(ad, ap);                                                        \
        CP16(ad + 5120, ap + (size_t)64 * K);                                \
        uint32_t bd = b_dst + (stage) * 8704;                                \
        const float* bp = b_src + (size_t)((kt) << 4) * N;                   \
        CP16(bd, bp);                                                        \
        CP16(bd + 4352, bp + (size_t)8 * N);                                 \
        CP_COMMIT();                                                         \
    }

    ISSUE(0, 0);
    if (KT > 1) ISSUE(1, 1);

    int st = 2;      // stage to fill next
    int buf = 0;     // stage to consume
    for (int kt = 0; kt < KT; kt++) {
        if (kt + 1 < KT) asm volatile("cp.async.wait_group 1;\n");
        else             asm volatile("cp.async.wait_group 0;\n");
        __syncthreads();
        // stage (kt+2)%3 was consumed at kt-1; every thread passed the sync
        // above, so it's finished with it -> safe to refill, no trailing sync.
        if (kt + 2 < KT) {
            ISSUE(st, kt + 2);
            st = (st == 2) ? 0 : st + 1;
        }

        const float* as = As[buf];
        const float* bs = Bs[buf];
#pragma unroll
        for (int ch = 0; ch < 2; ch++) {
            int kb = ch * 8 + tig;
            float a[4][4], b[4][2];
#pragma unroll
            for (int mt = 0; mt < 4; mt++) {
                int m = wm + mt * 16 + g;
                a[mt][0] = as[m * 20 + kb];
                a[mt][1] = as[(m + 8) * 20 + kb];
                a[mt][2] = as[m * 20 + kb + 4];
                a[mt][3] = as[(m + 8) * 20 + kb + 4];
            }
#pragma unroll
            for (int nt = 0; nt < 4; nt++) {
                int n = wn + nt * 8 + g;
                b[nt][0] = bs[kb * 136 + n];
                b[nt][1] = bs[(kb + 4) * 136 + n];
            }
#pragma unroll
            for (int mt = 0; mt < 4; mt++)
#pragma unroll
                for (int nt = 0; nt < 4; nt++) mma8(acc[mt][nt], a[mt], b[nt]);
        }
        buf = (buf == 2) ? 0 : buf + 1;
    }
#undef ISSUE

#pragma unroll
    for (int mt = 0; mt < 4; mt++) {
#pragma unroll
        for (int nt = 0; nt < 4; nt++) {
            int row = by * 128 + wm + mt * 16 + g;
            int col = bx * 128 + wn + nt * 8 + 2 * tig;
            float e[4];
#pragma unroll
            for (int r = 0; r < 4; r++) {
                float c = acc[mt][nt][r];
                if (EPI == 1) c = c / (1.0f + __expf(-c));
                if (RND)      c = tf32r(c);
                e[r] = c;
            }
            *(float2*)&C[(size_t)row * N + col]       = make_float2(e[0], e[1]);
            *(float2*)&C[(size_t)(row + 8) * N + col] = make_float2(e[2], e[3]);
        }
    }
}

// ---------------------------------------------------------------------------
// Flash attention: K AND V double-buffered, prefetch distance 1,
// ONE __syncthreads per tile. Heavy tiles first; 2 CTAs/SM.
// smem: K0 K1 (64x68 each) | V0 V1 (64x72 each) = 17920 floats = 70KB.
// Qstage aliases K0|K1 exactly (128*68 = 8704 floats).
// ---------------------------------------------------------------------------
__global__ void __launch_bounds__(256, 2) flash_kernel(
    const float* __restrict__ qkv, float* __restrict__ ao)
{
    int it = (int)gridDim.x - 1 - (int)blockIdx.x;   // heavy-first (LPT)
    int bh = blockIdx.y;
    int b = bh >> 4, h = bh & 15;
    int i0 = it * 128;

    __shared__ float smem[2 * 64 * 68 + 2 * 64 * 72];
    float* Qstage = smem;                 // aliases K0|K1

    int tid = threadIdx.x, warp = tid >> 5, lane = tid & 31;
    int g = lane >> 2, tig = lane & 3;

    const float* q = qkv + h * HDD;
    const float* k = qkv + DD + h * HDD;
    const float* v = qkv + 2 * DD + h * HDD;

    // ---- stage Q, pull to regs ----
    {
        int r = tid >> 1;
        int cb = (tid & 1) * 32;
        const float* qp = q + (size_t)(b * TT + i0 + r) * QS + cb;
        float* dst = Qstage + r * 68 + cb;
#pragma unroll
        for (int c4 = 0; c4 < 8; c4++)
            *(float4*)(dst + c4 * 4) = *(const float4*)(qp + c4 * 4);
    }
    __syncthreads();
    float qa[8][4];
    {
        int m = warp * 16 + g;
#pragma unroll
        for (int kt = 0; kt < 8; kt++) {
            int kb = kt * 8 + tig;
            qa[kt][0] = Qstage[m * 68 + kb] * 0.125f;
            qa[kt][1] = Qstage[(m + 8) * 68 + kb] * 0.125f;
            qa[kt][2] = Qstage[m * 68 + kb + 4] * 0.125f;
            qa[kt][3] = Qstage[(m + 8) * 68 + kb + 4] * 0.125f;
        }
    }
    __syncthreads();   // Qstage free -> K buffers usable

    // per-thread load coords (64x64 tile, 4x CP16 for K and 4x for V)
    int lr = tid >> 2, lc = (tid & 3) * 16;
    const float* krow = k + (size_t)(b * TT + lr) * QS + lc;
    const float* vrow = v + (size_t)(b * TT + lr) * QS + lc;
    uint32_t kd[2] = { smaddr(smem + lr * 68 + lc),
                       smaddr(smem + 4352 + lr * 68 + lc) };
    uint32_t vd[2] = { smaddr(smem + 8704 + lr * 72 + lc),
                       smaddr(smem + 8704 + 4608 + lr * 72 + lc) };

    int jt_max = 2 * it + 1;

    // issue tile 0 (K+V, one group)
    {
#pragma unroll
        for (int c4 = 0; c4 < 4; c4++) {
            CP16(kd[0] + c4 * 16, krow + c4 * 4);
            CP16(vd[0] + c4 * 16, vrow + c4 * 4);
        }
        CP_COMMIT();
    }

    float o[8][4];
#pragma unroll
    for (int nt = 0; nt < 8; nt++)
#pragma unroll
        for (int r = 0; r < 4; r++) o[nt][r] = 0.f;
    float rm0 = -1e30f, rm1 = -1e30f, rs0 = 0.f, rs1 = 0.f;

    int warp_row0 = i0 + warp * 16;
    int src0 = g * 4 + (tig >> 1);
    int src1 = src0 + 2;
    bool hi = tig & 1;

    for (int jt = 0; jt <= jt_max; jt++) {
        int j0 = jt * 64;
        asm volatile("cp.async.wait_group 0;\n");   // tile jt arrived
        __syncthreads();
        // prefetch tile jt+1 into buffer (jt+1)&1 (last read at jt-1; the
        // sync above guarantees everyone is done with it)
        if (jt < jt_max) {
            int jb = (jt + 1) & 1;
            const float* kp = krow + (size_t)(j0 + 64) * QS;
            const float* vp = vrow + (size_t)(j0 + 64) * QS;
#pragma unroll
            for (int c4 = 0; c4 < 4; c4++) {
                CP16(kd[jb] + c4 * 16, kp + c4 * 4);
                CP16(vd[jb] + c4 * 16, vp + c4 * 4);
            }
            CP_COMMIT();
        }

        if (j0 <= warp_row0 + 15) {
            const float* Ks = smem + (jt & 1) * 4352;
            const float* Vs = smem + 8704 + (jt & 1) * 4608;
            // ---- S = Q K^T ----
            float s[8][4];
#pragma unroll
            for (int nt = 0; nt < 8; nt++)
#pragma unroll
                for (int r = 0; r < 4; r++) s[nt][r] = 0.f;
#pragma unroll
            for (int kt = 0; kt < 8; kt++) {
                int kb = kt * 8 + tig;
#pragma unroll
                for (int nt = 0; nt < 8; nt++) {
                    float bfr[2] = { Ks[(nt * 8 + g) * 68 + kb],
                                     Ks[(nt * 8 + g) * 68 + kb + 4] };
                    mma8(s[nt], qa[kt], bfr);
                }
            }
            int r0 = warp_row0 + g, r1 = r0 + 8;
            if (j0 + 63 > warp_row0) {
#pragma unroll
                for (int nt = 0; nt < 8; nt++) {
                    int j = j0 + nt * 8 + 2 * tig;
                    if (j     > r0) s[nt][0] = -1e30f;
                    if (j + 1 > r0) s[nt][1] = -1e30f;
                    if (j     > r1) s[nt][2] = -1e30f;
                    if (j + 1 > r1) s[nt][3] = -1e30f;
                }
            }
            // ---- online softmax ----
            float m0 = -1e30f, m1 = -1e30f;
#pragma unroll
            for (int nt = 0; nt < 8; nt++) {
                m0 = fmaxf(m0, fmaxf(s[nt][0], s[nt][1]));
                m1 = fmaxf(m1, fmaxf(s[nt][2], s[nt][3]));
            }
            m0 = fmaxf(m0, __shfl_xor_sync(0xffffffffu, m0, 1));
            m0 = fmaxf(m0, __shfl_xor_sync(0xffffffffu, m0, 2));
            m1 = fmaxf(m1, __shfl_xor_sync(0xffffffffu, m1, 1));
            m1 = fmaxf(m1, __shfl_xor_sync(0xffffffffu, m1, 2));
            float nm0 = fmaxf(rm0, m0), nm1 = fmaxf(rm1, m1);
            float al0 = __expf(rm0 - nm0), al1 = __expf(rm1 - nm1);
            rm0 = nm0; rm1 = nm1;
            float l0 = 0.f, l1 = 0.f;
#pragma unroll
            for (int nt = 0; nt < 8; nt++) {
                s[nt][0] = tf32r(__expf(s[nt][0] - nm0));
                s[nt][1] = tf32r(__expf(s[nt][1] - nm0));
                s[nt][2] = tf32r(__expf(s[nt][2] - nm1));
                s[nt][3] = tf32r(__expf(s[nt][3] - nm1));
                l0 += s[nt][0] + s[nt][1];
                l1 += s[nt][2] + s[nt][3];
            }
            l0 += __shfl_xor_sync(0xffffffffu, l0, 1);
            l0 += __shfl_xor_sync(0xffffffffu, l0, 2);
            l1 += __shfl_xor_sync(0xffffffffu, l1, 1);
            l1 += __shfl_xor_sync(0xffffffffu, l1, 2);
            rs0 = rs0 * al0 + l0;
            rs1 = rs1 * al1 + l1;
#pragma unroll
            for (int nt = 0; nt < 8; nt++) {
                o[nt][0] *= al0; o[nt][1] *= al0;
                o[nt][2] *= al1; o[nt][3] *= al1;
            }
            // ---- O += P V (P C-frag -> A-frag via shuffles) ----
#pragma unroll
            for (int kt = 0; kt < 8; kt++) {
                float v00 = __shfl_sync(0xffffffffu, s[kt][0], src0);
                float v01 = __shfl_sync(0xffffffffu, s[kt][1], src0);
                float v02 = __shfl_sync(0xffffffffu, s[kt][2], src0);
                float v03 = __shfl_sync(0xffffffffu, s[kt][3], src0);
                float v10 = __shfl_sync(0xffffffffu, s[kt][0], src1);
                float v11 = __shfl_sync(0xffffffffu, s[kt][1], src1);
                float v12 = __shfl_sync(0xffffffffu, s[kt][2], src1);
                float v13 = __shfl_sync(0xffffffffu, s[kt][3], src1);
                float a[4];
                a[0] = hi ? v01 : v00;
                a[1] = hi ? v03 : v02;
                a[2] = hi ? v11 : v10;
                a[3] = hi ? v13 : v12;
                int kb = kt * 8 + tig;
#pragma unroll
                for (int nt = 0; nt < 8; nt++) {
                    float bfr[2] = { Vs[kb * 72 + nt * 8 + g],
                                     Vs[(kb + 4) * 72 + nt * 8 + g] };
                    mma8(o[nt], a, bfr);
                }
            }
        }
        // no trailing sync: next iter's wait+sync protects buffer reuse
    }

    float inv0 = 1.0f / rs0, inv1 = 1.0f / rs1;
    int r0 = i0 + warp * 16 + g;
#pragma unroll
    for (int nt = 0; nt < 8; nt++) {
        int col = h * HDD + nt * 8 + 2 * tig;
        float* p0 = ao + (size_t)(b * TT + r0) * DD + col;
        float* p1 = ao + (size_t)(b * TT + r0 + 8) * DD + col;
        *(float2*)p0 = make_float2(tf32r(o[nt][0] * inv0), tf32r(o[nt][1] * inv0));
        *(float2*)p1 = make_float2(tf32r(o[nt][2] * inv1), tf32r(o[nt][3] * inv1));
    }
}

// ---------------------------------------------------------------------------
// Launch
// ---------------------------------------------------------------------------
extern "C" void kernel_launch(void* const* d_in, const int* in_sizes, int n_in,
                              void* d_out, int out_size)
{
    const float* x      = (const float*)d_in[0];
    const float* w_pre  = (const float*)d_in[1];
    const float* wq     = (const float*)d_in[2];
    const float* wk     = (const float*)d_in[3];
    const float* wv     = (const float*)d_in[4];
    const float* wo     = (const float*)d_in[5];
    const float* w_attn = (const float*)d_in[6];
    const float* w1     = (const float*)d_in[7];
    const float* w2     = (const float*)d_in[8];
    const float* w_ffn  = (const float*)d_in[9];
    float* out = (float*)d_out;

    float *h_, *qkv_, *ao_, *tmp_, *y_, *mid_, *w_;
    cudaGetSymbolAddress((void**)&h_,   g_h);
    cudaGetSymbolAddress((void**)&qkv_, g_qkv);
    cudaGetSymbolAddress((void**)&ao_,  g_ao);
    cudaGetSymbolAddress((void**)&tmp_, g_tmp);
    cudaGetSymbolAddress((void**)&y_,   g_y);
    cudaGetSymbolAddress((void**)&mid_, g_mid);
    cudaGetSymbolAddress((void**)&w_,   g_w);

    // 0) pack + round weights
    pack_kernel<<<12288, 256>>>((const float4*)wq, (const float4*)wk,
                                (const float4*)wv, (const float4*)wo,
                                (const float4*)w1, (const float4*)w2,
                                (float4*)w_);

    // 1) h = rmsnorm(x)
    rmsnorm_kernel<1><<<MT, 256>>>(x, nullptr, w_pre, h_);

    // 2) fused qkv projection: [4096x1024] @ [1024x3072]
    {
        dim3 g(QS / 128, MT / 128);    // 24 x 32 = 768 CTAs
        tgemm_kernel<0, 1><<<g, 256>>>(h_, w_ + WQKV_OFF, qkv_, MT, QS, DD);
    }

    // 3) fused flash attention (fully double-buffered, heavy-first)
    {
        dim3 g(TT / 128, BB * HH);
        flash_kernel<<<g, 256>>>(qkv_, ao_);
    }

    // 4) o-proj + residual norm
    {
        dim3 g(DD / 128, MT / 128);
        tgemm_kernel<0, 0><<<g, 256>>>(ao_, w_ + WO_OFF, tmp_, MT, DD, DD);
    }
    rmsnorm_kernel<1><<<MT, 256>>>(h_, tmp_, w_attn, y_);

    // 5) FFN
    {
        dim3 g(FFD / 128, MT / 128);
        tgemm_kernel<1, 1><<<g, 256>>>(y_, w_ + W1_OFF, mid_, MT, FFD, DD);
    }
    {
        dim3 g(DD / 128, MT / 128);
        tgemm_kernel<0, 0><<<g, 256>>>(mid_, w_ + W2_OFF, tmp_, MT, DD, FFD);
    }
    rmsnorm_kernel<0><<<MT, 256>>>(y_, tmp_, w_ffn, out);
}

// round 12
// speedup vs baseline: 1.8141x; 1.2898x over previous
#include <cuda_runtime.h>
#include <cuda_fp16.h>
#include <cstdint>
#include <cstddef>

#define BB   2
#define TT   2048
#define DD   1024
#define HH   16
#define HDD  64
#define FFD  4096
#define MT   (BB*TT)
#define QS   (3*DD)          // fused qkv row stride (fp32 for flash)

// ---------------------------------------------------------------------------
// Scratch
// ---------------------------------------------------------------------------
__device__ __half g_h  [MT*DD];
__device__ float  g_qkv[MT*QS];
__device__ __half g_ao [MT*DD];
__device__ float  g_tmp[MT*DD];
__device__ __half g_y  [MT*DD];
__device__ __half g_mid[MT*FFD];
__device__ __half g_w  [12*1024*1024]; // fp16 TRANSPOSED: wqkvT[3072][1024] | woT | w1T | w2T

#define WQKV_OFF 0
#define WO_OFF (3*1024*1024)
#define W1_OFF (4*1024*1024)
#define W2_OFF (8*1024*1024)

// ---------------------------------------------------------------------------
// Helpers
// ---------------------------------------------------------------------------
__device__ __forceinline__ float tf32r(float x) {
    float r; asm("cvt.rna.tf32.f32 %0, %1;" : "=f"(r) : "f"(x)); return r;
}
__device__ __forceinline__ uint32_t smaddr(const void* p) {
    return (uint32_t)__cvta_generic_to_shared(p);
}
#define CP16(dst, src) asm volatile("cp.async.cg.shared.global [%0], [%1], 16;\n" :: "r"(dst), "l"(src))
#define CP_COMMIT()    asm volatile("cp.async.commit_group;\n")

// tf32 m16n8k8 (flash only)
__device__ __forceinline__ void mma8(float* d, const float* a, const float* b) {
    asm volatile(
        "mma.sync.aligned.m16n8k8.row.col.f32.tf32.tf32.f32 "
        "{%0,%1,%2,%3}, {%4,%5,%6,%7}, {%8,%9}, {%0,%1,%2,%3};\n"
        : "+f"(d[0]), "+f"(d[1]), "+f"(d[2]), "+f"(d[3])
        : "r"(__float_as_uint(a[0])), "r"(__float_as_uint(a[1])),
          "r"(__float_as_uint(a[2])), "r"(__float_as_uint(a[3])),
          "r"(__float_as_uint(b[0])), "r"(__float_as_uint(b[1])));
}

// fp16 m16n8k16 (dense GEMMs)
__device__ __forceinline__ void mma16(float* d, const uint32_t* a, const uint32_t* b) {
    asm volatile(
        "mma.sync.aligned.m16n8k16.row.col.f32.f16.f16.f32 "
        "{%0,%1,%2,%3}, {%4,%5,%6,%7}, {%8,%9}, {%0,%1,%2,%3};\n"
        : "+f"(d[0]), "+f"(d[1]), "+f"(d[2]), "+f"(d[3])
        : "r"(a[0]), "r"(a[1]), "r"(a[2]), "r"(a[3]), "r"(b[0]), "r"(b[1]));
}

// ---------------------------------------------------------------------------
// Pack weights -> fp16, TRANSPOSED to [N][K] row-major (K-major B operand).
// wq|wk|wv fused -> wqkvT[3072][1024]. Tiled 32x32 transpose, 256 thr.
// blocks: qkv 3072 | wo 1024 | w1 4096 | w2 4096 = 12288.
// ---------------------------------------------------------------------------
__global__ void __launch_bounds__(256) packT_kernel(
    const float* __restrict__ wq, const float* __restrict__ wk,
    const float* __restrict__ wv, const float* __restrict__ wo,
    const float* __restrict__ w1, const float* __restrict__ w2,
    __half* __restrict__ out)
{
    __shared__ float tile[32][33];
    int t = blockIdx.x;
    const float* src; __half* dst;
    int srcN, dstK, n0, k0, scol;
    if (t < 3072) {                      // wqkvT [3072][1024]
        int nt = t >> 5, kt = t & 31;
        n0 = nt * 32; k0 = kt * 32;
        int sel = n0 >> 10;
        src = sel == 0 ? wq : (sel == 1 ? wk : wv);
        srcN = 1024; scol = n0 & 1023;
        dst = out + WQKV_OFF; dstK = 1024;
    } else if (t < 4096) {               // woT [1024][1024]
        int u = t - 3072;
        int nt = u >> 5, kt = u & 31;
        n0 = nt * 32; k0 = kt * 32;
        src = wo; srcN = 1024; scol = n0;
        dst = out + WO_OFF; dstK = 1024;
    } else if (t < 8192) {               // w1T [4096][1024]
        int u = t - 4096;
        int nt = u >> 5, kt = u & 31;
        n0 = nt * 32; k0 = kt * 32;
        src = w1; srcN = 4096; scol = n0;
        dst = out + W1_OFF; dstK = 1024;
    } else {                             // w2T [1024][4096]
        int u = t - 8192;
        int nt = u >> 7, kt = u & 127;
        n0 = nt * 32; k0 = kt * 32;
        src = w2; srcN = 1024; scol = n0;
        dst = out + W2_OFF; dstK = 4096;
    }
    int tx = threadIdx.x & 31, ty = threadIdx.x >> 5;
#pragma unroll
    for (int i = 0; i < 4; i++)
        tile[ty + i * 8][tx] = src[(size_t)(k0 + ty + i * 8) * srcN + scol + tx];
    __syncthreads();
#pragma unroll
    for (int i = 0; i < 4; i++)
        dst[(size_t)(n0 + ty + i * 8) * dstK + k0 + tx] = __float2half(tile[tx][ty + i * 8]);
}

// ---------------------------------------------------------------------------
// RMSNorm: out = (a (+ b)) * rsqrt(mean sq + eps) * w ; AT/OT = half or float
// ---------------------------------------------------------------------------
template <typename AT, typename OT>
__global__ void __launch_bounds__(256) rmsnorm_kernel(
    const AT* __restrict__ a, const float* __restrict__ b,
    const float* __restrict__ w, OT* __restrict__ out)
{
    int row = blockIdx.x;
    size_t base = (size_t)row * DD;
    float v[4];
    float ss = 0.f;
#pragma unroll
    for (int t = 0; t < 4; t++) {
        int c = threadIdx.x + t * 256;
        float x = (float)a[base + c];
        if (b) x += b[base + c];
        v[t] = x;
        ss += x * x;
    }
    __shared__ float red[8];
#pragma unroll
    for (int o = 16; o; o >>= 1) ss += __shfl_xor_sync(0xffffffffu, ss, o);
    if ((threadIdx.x & 31) == 0) red[threadIdx.x >> 5] = ss;
    __syncthreads();
    if (threadIdx.x == 0) {
        float tot = 0.f;
#pragma unroll
        for (int i = 0; i < 8; i++) tot += red[i];
        red[0] = tot;
    }
    __syncthreads();
    float scale = rsqrtf(red[0] * (1.0f / DD) + 1e-6f);
#pragma unroll
    for (int t = 0; t < 4; t++) {
        int c = threadIdx.x + t * 256;
        out[base + c] = (OT)(v[t] * scale * w[c]);
    }
}

// ---------------------------------------------------------------------------
// FP16 GEMM: C[M,N] = A[M,K] @ Bt[N,K]^T.  BM=BN=128, BK=32, 256 threads,
// 8 warps x (64x32), m16n8k16, 3-stage cp.async, ONE sync per chunk.
// smem rows: 40 halfs (80B) stride — conflict-free fragment loads.
// EPI: 0 none, 1 SiLU. RND: tf32-round fp32 outputs. OT: __half or float.
// ---------------------------------------------------------------------------
template <int EPI, int RND, typename OT>
__global__ void __launch_bounds__(256, 2) hgemm_kernel(
    const __half* __restrict__ A, const __half* __restrict__ Bt,
    OT* __restrict__ C, int M, int N, int K)
{
    __shared__ __half As[3][128 * 40];   // 10240B/stage
    __shared__ __half Bs[3][128 * 40];

    int tid = threadIdx.x;
    int warp = tid >> 5, lane = tid & 31;
    int g = lane >> 2, tig = lane & 3;
    int wm = (warp >> 2) * 64, wn = (warp & 3) * 32;
    int bx = blockIdx.x, by = blockIdx.y;

    // loader: 2 threads/row, 2x CP16 (16 halfs) each per matrix
    int r = tid >> 1, hf = tid & 1;
    const __half* a_src = A  + (size_t)(by * 128 + r) * K + hf * 16;
    const __half* b_src = Bt + (size_t)(bx * 128 + r) * K + hf * 16;
    uint32_t a_dst = smaddr(&As[0][r * 40 + hf * 16]);
    uint32_t b_dst = smaddr(&Bs[0][r * 40 + hf * 16]);

    float acc[4][4][4];
#pragma unroll
    for (int i = 0; i < 4; i++)
#pragma unroll
        for (int j = 0; j < 4; j++)
#pragma unroll
            for (int q = 0; q < 4; q++) acc[i][j][q] = 0.f;

    int KT = K >> 5;

#define ISSUE(stage, kt)                                                     \
    {                                                                        \
        const __half* ap = a_src + ((kt) << 5);                              \
        uint32_t ad = a_dst + (stage) * 10240;                               \
        CP16(ad, ap); CP16(ad + 16, ap + 8);                                 \
        const __half* bp = b_src + ((kt) << 5);                              \
        uint32_t bd = b_dst + (stage) * 10240;                               \
        CP16(bd, bp); CP16(bd + 16, bp + 8);                                 \
        CP_COMMIT();                                                         \
    }

    ISSUE(0, 0);
    if (KT > 1) ISSUE(1, 1);

    int st = 2, buf = 0;
    for (int kt = 0; kt < KT; kt++) {
        if (kt + 1 < KT) asm volatile("cp.async.wait_group 1;\n");
        else             asm volatile("cp.async.wait_group 0;\n");
        __syncthreads();
        if (kt + 2 < KT) {
            ISSUE(st, kt + 2);
            st = (st == 2) ? 0 : st + 1;
        }

        const __half* as = As[buf];
        const __half* bs = Bs[buf];
#pragma unroll
        for (int ss = 0; ss < 2; ss++) {
            int kb = ss * 16 + 2 * tig;
            uint32_t a[4][4], b[4][2];
#pragma unroll
            for (int mt = 0; mt < 4; mt++) {
                int m = wm + mt * 16 + g;
                a[mt][0] = *(const uint32_t*)&as[m * 40 + kb];
                a[mt][1] = *(const uint32_t*)&as[(m + 8) * 40 + kb];
                a[mt][2] = *(const uint32_t*)&as[m * 40 + kb + 8];
                a[mt][3] = *(const uint32_t*)&as[(m + 8) * 40 + kb + 8];
            }
#pragma unroll
            for (int nt = 0; nt < 4; nt++) {
                int n = wn + nt * 8 + g;
                b[nt][0] = *(const uint32_t*)&bs[n * 40 + kb];
                b[nt][1] = *(const uint32_t*)&bs[n * 40 + kb + 8];
            }
#pragma unroll
            for (int mt = 0; mt < 4; mt++)
#pragma unroll
                for (int nt = 0; nt < 4; nt++) mma16(acc[mt][nt], a[mt], b[nt]);
        }
        buf = (buf == 2) ? 0 : buf + 1;
    }
#undef ISSUE

#pragma unroll
    for (int mt = 0; mt < 4; mt++) {
#pragma unroll
        for (int nt = 0; nt < 4; nt++) {
            int row = by * 128 + wm + mt * 16 + g;
            int col = bx * 128 + wn + nt * 8 + 2 * tig;
            float e[4];
#pragma unroll
            for (int q = 0; q < 4; q++) {
                float c = acc[mt][nt][q];
                if (EPI == 1) c = c / (1.0f + __expf(-c));
                e[q] = c;
            }
            if (sizeof(OT) == 2) {
                __half2* p0 = (__half2*)((__half*)C + (size_t)row * N + col);
                __half2* p1 = (__half2*)((__half*)C + (size_t)(row + 8) * N + col);
                *p0 = __floats2half2_rn(e[0], e[1]);
                *p1 = __floats2half2_rn(e[2], e[3]);
            } else {
                if (RND) {
                    e[0] = tf32r(e[0]); e[1] = tf32r(e[1]);
                    e[2] = tf32r(e[2]); e[3] = tf32r(e[3]);
                }
                float* p0 = (float*)C + (size_t)row * N + col;
                float* p1 = (float*)C + (size_t)(row + 8) * N + col;
                *(float2*)p0 = make_float2(e[0], e[1]);
                *(float2*)p1 = make_float2(e[2], e[3]);
            }
        }
    }
}

// ---------------------------------------------------------------------------
// Flash attention (R10-proven): fp32 qkv in, fp16 ao out.
// K/V double-buffered cp.async, 1 sync/tile, heavy-first, 2 CTAs/SM.
// ---------------------------------------------------------------------------
__global__ void __launch_bounds__(256, 2) flash_kernel(
    const float* __restrict__ qkv, __half* __restrict__ ao)
{
    int it = (int)gridDim.x - 1 - (int)blockIdx.x;
    int bh = blockIdx.y;
    int b = bh >> 4, h = bh & 15;
    int i0 = it * 128;

    __shared__ float smem[2 * 64 * 68 + 2 * 64 * 72];
    float* Qstage = smem;

    int tid = threadIdx.x, warp = tid >> 5, lane = tid & 31;
    int g = lane >> 2, tig = lane & 3;

    const float* q = qkv + h * HDD;
    const float* k = qkv + DD + h * HDD;
    const float* v = qkv + 2 * DD + h * HDD;

    {
        int r = tid >> 1;
        int cb = (tid & 1) * 32;
        const float* qp = q + (size_t)(b * TT + i0 + r) * QS + cb;
        float* dst = Qstage + r * 68 + cb;
#pragma unroll
        for (int c4 = 0; c4 < 8; c4++)
            *(float4*)(dst + c4 * 4) = *(const float4*)(qp + c4 * 4);
    }
    __syncthreads();
    float qa[8][4];
    {
        int m = warp * 16 + g;
#pragma unroll
        for (int kt = 0; kt < 8; kt++) {
            int kb = kt * 8 + tig;
            qa[kt][0] = Qstage[m * 68 + kb] * 0.125f;
            qa[kt][1] = Qstage[(m + 8) * 68 + kb] * 0.125f;
            qa[kt][2] = Qstage[m * 68 + kb + 4] * 0.125f;
            qa[kt][3] = Qstage[(m + 8) * 68 + kb + 4] * 0.125f;
        }
    }
    __syncthreads();

    int lr = tid >> 2, lc = (tid & 3) * 16;
    const float* krow = k + (size_t)(b * TT + lr) * QS + lc;
    const float* vrow = v + (size_t)(b * TT + lr) * QS + lc;
    uint32_t kd[2] = { smaddr(smem + lr * 68 + lc),
                       smaddr(smem + 4352 + lr * 68 + lc) };
    uint32_t vd[2] = { smaddr(smem + 8704 + lr * 72 + lc),
                       smaddr(smem + 8704 + 4608 + lr * 72 + lc) };

    int jt_max = 2 * it + 1;

    {
#pragma unroll
        for (int c4 = 0; c4 < 4; c4++) {
            CP16(kd[0] + c4 * 16, krow + c4 * 4);
            CP16(vd[0] + c4 * 16, vrow + c4 * 4);
        }
        CP_COMMIT();
    }

    float o[8][4];
#pragma unroll
    for (int nt = 0; nt < 8; nt++)
#pragma unroll
        for (int r = 0; r < 4; r++) o[nt][r] = 0.f;
    float rm0 = -1e30f, rm1 = -1e30f, rs0 = 0.f, rs1 = 0.f;

    int warp_row0 = i0 + warp * 16;
    int src0 = g * 4 + (tig >> 1);
    int src1 = src0 + 2;
    bool hi = tig & 1;

    for (int jt = 0; jt <= jt_max; jt++) {
        int j0 = jt * 64;
        asm volatile("cp.async.wait_group 0;\n");
        __syncthreads();
        if (jt < jt_max) {
            int jb = (jt + 1) & 1;
            const float* kp = krow + (size_t)(j0 + 64) * QS;
            const float* vp = vrow + (size_t)(j0 + 64) * QS;
#pragma unroll
            for (int c4 = 0; c4 < 4; c4++) {
                CP16(kd[jb] + c4 * 16, kp + c4 * 4);
                CP16(vd[jb] + c4 * 16, vp + c4 * 4);
            }
            CP_COMMIT();
        }

        if (j0 <= warp_row0 + 15) {
            const float* Ks = smem + (jt & 1) * 4352;
            const float* Vs = smem + 8704 + (jt & 1) * 4608;
            float s[8][4];
#pragma unroll
            for (int nt = 0; nt < 8; nt++)
#pragma unroll
                for (int r = 0; r < 4; r++) s[nt][r] = 0.f;
#pragma unroll
            for (int kt = 0; kt < 8; kt++) {
                int kb = kt * 8 + tig;
#pragma unroll
                for (int nt = 0; nt < 8; nt++) {
                    float bfr[2] = { Ks[(nt * 8 + g) * 68 + kb],
                                     Ks[(nt * 8 + g) * 68 + kb + 4] };
                    mma8(s[nt], qa[kt], bfr);
                }
            }
            int r0 = warp_row0 + g, r1 = r0 + 8;
            if (j0 + 63 > warp_row0) {
#pragma unroll
                for (int nt = 0; nt < 8; nt++) {
                    int j = j0 + nt * 8 + 2 * tig;
                    if (j     > r0) s[nt][0] = -1e30f;
                    if (j + 1 > r0) s[nt][1] = -1e30f;
                    if (j     > r1) s[nt][2] = -1e30f;
                    if (j + 1 > r1) s[nt][3] = -1e30f;
                }
            }
            float m0 = -1e30f, m1 = -1e30f;
#pragma unroll
            for (int nt = 0; nt < 8; nt++) {
                m0 = fmaxf(m0, fmaxf(s[nt][0], s[nt][1]));
                m1 = fmaxf(m1, fmaxf(s[nt][2], s[nt][3]));
            }
            m0 = fmaxf(m0, __shfl_xor_sync(0xffffffffu, m0, 1));
            m0 = fmaxf(m0, __shfl_xor_sync(0xffffffffu, m0, 2));
            m1 = fmaxf(m1, __shfl_xor_sync(0xffffffffu, m1, 1));
            m1 = fmaxf(m1, __shfl_xor_sync(0xffffffffu, m1, 2));
            float nm0 = fmaxf(rm0, m0), nm1 = fmaxf(rm1, m1);
            float al0 = __expf(rm0 - nm0), al1 = __expf(rm1 - nm1);
            rm0 = nm0; rm1 = nm1;
            float l0 = 0.f, l1 = 0.f;
#pragma unroll
            for (int nt = 0; nt < 8; nt++) {
                s[nt][0] = tf32r(__expf(s[nt][0] - nm0));
                s[nt][1] = tf32r(__expf(s[nt][1] - nm0));
                s[nt][2] = tf32r(__expf(s[nt][2] - nm1));
                s[nt][3] = tf32r(__expf(s[nt][3] - nm1));
                l0 += s[nt][0] + s[nt][1];
                l1 += s[nt][2] + s[nt][3];
            }
            l0 += __shfl_xor_sync(0xffffffffu, l0, 1);
            l0 += __shfl_xor_sync(0xffffffffu, l0, 2);
            l1 += __shfl_xor_sync(0xffffffffu, l1, 1);
            l1 += __shfl_xor_sync(0xffffffffu, l1, 2);
            rs0 = rs0 * al0 + l0;
            rs1 = rs1 * al1 + l1;
#pragma unroll
            for (int nt = 0; nt < 8; nt++) {
                o[nt][0] *= al0; o[nt][1] *= al0;
                o[nt][2] *= al1; o[nt][3] *= al1;
            }
#pragma unroll
            for (int kt = 0; kt < 8; kt++) {
                float v00 = __shfl_sync(0xffffffffu, s[kt][0], src0);
                float v01 = __shfl_sync(0xffffffffu, s[kt][1], src0);
                float v02 = __shfl_sync(0xffffffffu, s[kt][2], src0);
                float v03 = __shfl_sync(0xffffffffu, s[kt][3], src0);
                float v10 = __shfl_sync(0xffffffffu, s[kt][0], src1);
                float v11 = __shfl_sync(0xffffffffu, s[kt][1], src1);
                float v12 = __shfl_sync(0xffffffffu, s[kt][2], src1);
                float v13 = __shfl_sync(0xffffffffu, s[kt][3], src1);
                float a[4];
                a[0] = hi ? v01 : v00;
                a[1] = hi ? v03 : v02;
                a[2] = hi ? v11 : v10;
                a[3] = hi ? v13 : v12;
                int kb = kt * 8 + tig;
#pragma unroll
                for (int nt = 0; nt < 8; nt++) {
                    float bfr[2] = { Vs[kb * 72 + nt * 8 + g],
                                     Vs[(kb + 4) * 72 + nt * 8 + g] };
                    mma8(o[nt], a, bfr);
                }
            }
        }
    }

    float inv0 = 1.0f / rs0, inv1 = 1.0f / rs1;
    int r0 = i0 + warp * 16 + g;
#pragma unroll
    for (int nt = 0; nt < 8; nt++) {
        int col = h * HDD + nt * 8 + 2 * tig;
        __half2* p0 = (__half2*)(ao + (size_t)(b * TT + r0) * DD + col);
        __half2* p1 = (__half2*)(ao + (size_t)(b * TT + r0 + 8) * DD + col);
        *p0 = __floats2half2_rn(o[nt][0] * inv0, o[nt][1] * inv0);
        *p1 = __floats2half2_rn(o[nt][2] * inv1, o[nt][3] * inv1);
    }
}

// ---------------------------------------------------------------------------
// Launch
// ---------------------------------------------------------------------------
extern "C" void kernel_launch(void* const* d_in, const int* in_sizes, int n_in,
                              void* d_out, int out_size)
{
    const float* x      = (const float*)d_in[0];
    const float* w_pre  = (const float*)d_in[1];
    const float* wq     = (const float*)d_in[2];
    const float* wk     = (const float*)d_in[3];
    const float* wv     = (const float*)d_in[4];
    const float* wo     = (const float*)d_in[5];
    const float* w_attn = (const float*)d_in[6];
    const float* w1     = (const float*)d_in[7];
    const float* w2     = (const float*)d_in[8];
    const float* w_ffn  = (const float*)d_in[9];
    float* out = (float*)d_out;

    __half *h_, *ao_, *y_, *mid_, *w_;
    float *qkv_, *tmp_;
    cudaGetSymbolAddress((void**)&h_,   g_h);
    cudaGetSymbolAddress((void**)&qkv_, g_qkv);
    cudaGetSymbolAddress((void**)&ao_,  g_ao);
    cudaGetSymbolAddress((void**)&tmp_, g_tmp);
    cudaGetSymbolAddress((void**)&y_,   g_y);
    cudaGetSymbolAddress((void**)&mid_, g_mid);
    cudaGetSymbolAddress((void**)&w_,   g_w);

    // 0) pack + transpose + round weights to fp16
    packT_kernel<<<12288, 256>>>(wq, wk, wv, wo, w1, w2, w_);

    // 1) h = rmsnorm(x) -> fp16
    rmsnorm_kernel<float, __half><<<MT, 256>>>(x, nullptr, w_pre, h_);

    // 2) fused qkv projection (fp16 mma): out fp32 (tf32-rounded) for flash
    {
        dim3 g(QS / 128, MT / 128);    // 24 x 32
        hgemm_kernel<0, 1, float><<<g, 256>>>(h_, w_ + WQKV_OFF, qkv_, MT, QS, DD);
    }

    // 3) fused flash attention -> ao fp16
    {
        dim3 g(TT / 128, BB * HH);
        flash_kernel<<<g, 256>>>(qkv_, ao_);
    }

    // 4) o-proj (fp16 mma, fp32 out) + residual norm -> y fp16
    {
        dim3 g(DD / 128, MT / 128);
        hgemm_kernel<0, 0, float><<<g, 256>>>(ao_, w_ + WO_OFF, tmp_, MT, DD, DD);
    }
    rmsnorm_kernel<__half, __half><<<MT, 256>>>(h_, tmp_, w_attn, y_);

    // 5) FFN: mid = silu(y@w1) fp16; f = mid@w2 fp32; out = rmsnorm(y+f)
    {
        dim3 g(FFD / 128, MT / 128);
        hgemm_kernel<1, 0, __half><<<g, 256>>>(y_, w_ + W1_OFF, mid_, MT, FFD, DD);
    }
    {
        dim3 g(DD / 128, MT / 128);
        hgemm_kernel<0, 0, float><<<g, 256>>>(mid_, w_ + W2_OFF, tmp_, MT, DD, FFD);
    }
    rmsnorm_kernel<__half, float><<<MT, 256>>>(y_, tmp_, w_ffn, out);
}

// round 13
// speedup vs baseline: 2.2177x; 1.2224x over previous
#include <cuda_runtime.h>
#include <cuda_fp16.h>
#include <cstdint>
#include <cstddef>

#define BB   2
#define TT   2048
#define DD   1024
#define HH   16
#define HDD  64
#define FFD  4096
#define MT   (BB*TT)
#define QS   (3*DD)          // fused qkv row stride (fp16)

// ---------------------------------------------------------------------------
// Scratch
// ---------------------------------------------------------------------------
__device__ __half g_h  [MT*DD];
__device__ __half g_qkv[MT*QS];
__device__ __half g_ao [MT*DD];
__device__ float  g_tmp[MT*DD];
__device__ __half g_y  [MT*DD];
__device__ __half g_mid[MT*FFD];
__device__ __half g_w  [12*1024*1024]; // fp16 T: wqkvT[3072][1024] | woT | w1T | w2T

#define WQKV_OFF 0
#define WO_OFF (3*1024*1024)
#define W1_OFF (4*1024*1024)
#define W2_OFF (8*1024*1024)

// ---------------------------------------------------------------------------
// Helpers
// ---------------------------------------------------------------------------
__device__ __forceinline__ uint32_t smaddr(const void* p) {
    return (uint32_t)__cvta_generic_to_shared(p);
}
#define CP16(dst, src) asm volatile("cp.async.cg.shared.global [%0], [%1], 16;\n" :: "r"(dst), "l"(src))
#define CP_COMMIT()    asm volatile("cp.async.commit_group;\n")

// fp16 m16n8k16
__device__ __forceinline__ void mma16(float* d, const uint32_t* a, const uint32_t* b) {
    asm volatile(
        "mma.sync.aligned.m16n8k16.row.col.f32.f16.f16.f32 "
        "{%0,%1,%2,%3}, {%4,%5,%6,%7}, {%8,%9}, {%0,%1,%2,%3};\n"
        : "+f"(d[0]), "+f"(d[1]), "+f"(d[2]), "+f"(d[3])
        : "r"(a[0]), "r"(a[1]), "r"(a[2]), "r"(a[3]), "r"(b[0]), "r"(b[1]));
}

__device__ __forceinline__ uint32_t packh2(float x, float y) {
    __half2 t = __floats2half2_rn(x, y);
    return *(uint32_t*)&t;
}

// ---------------------------------------------------------------------------
// Pack weights -> fp16, TRANSPOSED to [N][K] row-major.
// ---------------------------------------------------------------------------
__global__ void __launch_bounds__(256) packT_kernel(
    const float* __restrict__ wq, const float* __restrict__ wk,
    const float* __restrict__ wv, const float* __restrict__ wo,
    const float* __restrict__ w1, const float* __restrict__ w2,
    __half* __restrict__ out)
{
    __shared__ float tile[32][33];
    int t = blockIdx.x;
    const float* src; __half* dst;
    int srcN, dstK, n0, k0, scol;
    if (t < 3072) {
        int nt = t >> 5, kt = t & 31;
        n0 = nt * 32; k0 = kt * 32;
        int sel = n0 >> 10;
        src = sel == 0 ? wq : (sel == 1 ? wk : wv);
        srcN = 1024; scol = n0 & 1023;
        dst = out + WQKV_OFF; dstK = 1024;
    } else if (t < 4096) {
        int u = t - 3072;
        int nt = u >> 5, kt = u & 31;
        n0 = nt * 32; k0 = kt * 32;
        src = wo; srcN = 1024; scol = n0;
        dst = out + WO_OFF; dstK = 1024;
    } else if (t < 8192) {
        int u = t - 4096;
        int nt = u >> 5, kt = u & 31;
        n0 = nt * 32; k0 = kt * 32;
        src = w1; srcN = 4096; scol = n0;
        dst = out + W1_OFF; dstK = 1024;
    } else {
        int u = t - 8192;
        int nt = u >> 7, kt = u & 127;
        n0 = nt * 32; k0 = kt * 32;
        src = w2; srcN = 1024; scol = n0;
        dst = out + W2_OFF; dstK = 4096;
    }
    int tx = threadIdx.x & 31, ty = threadIdx.x >> 5;
#pragma unroll
    for (int i = 0; i < 4; i++)
        tile[ty + i * 8][tx] = src[(size_t)(k0 + ty + i * 8) * srcN + scol + tx];
    __syncthreads();
#pragma unroll
    for (int i = 0; i < 4; i++)
        dst[(size_t)(n0 + ty + i * 8) * dstK + k0 + tx] = __float2half(tile[tx][ty + i * 8]);
}

// ---------------------------------------------------------------------------
// RMSNorm
// ---------------------------------------------------------------------------
template <typename AT, typename OT>
__global__ void __launch_bounds__(256) rmsnorm_kernel(
    const AT* __restrict__ a, const float* __restrict__ b,
    const float* __restrict__ w, OT* __restrict__ out)
{
    int row = blockIdx.x;
    size_t base = (size_t)row * DD;
    float v[4];
    float ss = 0.f;
#pragma unroll
    for (int t = 0; t < 4; t++) {
        int c = threadIdx.x + t * 256;
        float x = (float)a[base + c];
        if (b) x += b[base + c];
        v[t] = x;
        ss += x * x;
    }
    __shared__ float red[8];
#pragma unroll
    for (int o = 16; o; o >>= 1) ss += __shfl_xor_sync(0xffffffffu, ss, o);
    if ((threadIdx.x & 31) == 0) red[threadIdx.x >> 5] = ss;
    __syncthreads();
    if (threadIdx.x == 0) {
        float tot = 0.f;
#pragma unroll
        for (int i = 0; i < 8; i++) tot += red[i];
        red[0] = tot;
    }
    __syncthreads();
    float scale = rsqrtf(red[0] * (1.0f / DD) + 1e-6f);
#pragma unroll
    for (int t = 0; t < 4; t++) {
        int c = threadIdx.x + t * 256;
        out[base + c] = (OT)(v[t] * scale * w[c]);
    }
}

// ---------------------------------------------------------------------------
// FP16 GEMM (R12-proven): BM=BN=128, BK=32, 8 warps x (64x32), 3-stage, 1 sync.
// ---------------------------------------------------------------------------
template <int EPI, typename OT>
__global__ void __launch_bounds__(256, 2) hgemm_kernel(
    const __half* __restrict__ A, const __half* __restrict__ Bt,
    OT* __restrict__ C, int M, int N, int K)
{
    __shared__ __half As[3][128 * 40];
    __shared__ __half Bs[3][128 * 40];

    int tid = threadIdx.x;
    int warp = tid >> 5, lane = tid & 31;
    int g = lane >> 2, tig = lane & 3;
    int wm = (warp >> 2) * 64, wn = (warp & 3) * 32;
    int bx = blockIdx.x, by = blockIdx.y;

    int r = tid >> 1, hf = tid & 1;
    const __half* a_src = A  + (size_t)(by * 128 + r) * K + hf * 16;
    const __half* b_src = Bt + (size_t)(bx * 128 + r) * K + hf * 16;
    uint32_t a_dst = smaddr(&As[0][r * 40 + hf * 16]);
    uint32_t b_dst = smaddr(&Bs[0][r * 40 + hf * 16]);

    float acc[4][4][4];
#pragma unroll
    for (int i = 0; i < 4; i++)
#pragma unroll
        for (int j = 0; j < 4; j++)
#pragma unroll
            for (int q = 0; q < 4; q++) acc[i][j][q] = 0.f;

    int KT = K >> 5;

#define ISSUE(stage, kt)                                                     \
    {                                                                        \
        const __half* ap = a_src + ((kt) << 5);                              \
        uint32_t ad = a_dst + (stage) * 10240;                               \
        CP16(ad, ap); CP16(ad + 16, ap + 8);                                 \
        const __half* bp = b_src + ((kt) << 5);                              \
        uint32_t bd = b_dst + (stage) * 10240;                               \
        CP16(bd, bp); CP16(bd + 16, bp + 8);                                 \
        CP_COMMIT();                                                         \
    }

    ISSUE(0, 0);
    if (KT > 1) ISSUE(1, 1);

    int st = 2, buf = 0;
    for (int kt = 0; kt < KT; kt++) {
        if (kt + 1 < KT) asm volatile("cp.async.wait_group 1;\n");
        else             asm volatile("cp.async.wait_group 0;\n");
        __syncthreads();
        if (kt + 2 < KT) {
            ISSUE(st, kt + 2);
            st = (st == 2) ? 0 : st + 1;
        }

        const __half* as = As[buf];
        const __half* bs = Bs[buf];
#pragma unroll
        for (int ss = 0; ss < 2; ss++) {
            int kb = ss * 16 + 2 * tig;
            uint32_t a[4][4], b[4][2];
#pragma unroll
            for (int mt = 0; mt < 4; mt++) {
                int m = wm + mt * 16 + g;
                a[mt][0] = *(const uint32_t*)&as[m * 40 + kb];
                a[mt][1] = *(const uint32_t*)&as[(m + 8) * 40 + kb];
                a[mt][2] = *(const uint32_t*)&as[m * 40 + kb + 8];
                a[mt][3] = *(const uint32_t*)&as[(m + 8) * 40 + kb + 8];
            }
#pragma unroll
            for (int nt = 0; nt < 4; nt++) {
                int n = wn + nt * 8 + g;
                b[nt][0] = *(const uint32_t*)&bs[n * 40 + kb];
                b[nt][1] = *(const uint32_t*)&bs[n * 40 + kb + 8];
            }
#pragma unroll
            for (int mt = 0; mt < 4; mt++)
#pragma unroll
                for (int nt = 0; nt < 4; nt++) mma16(acc[mt][nt], a[mt], b[nt]);
        }
        buf = (buf == 2) ? 0 : buf + 1;
    }
#undef ISSUE

#pragma unroll
    for (int mt = 0; mt < 4; mt++) {
#pragma unroll
        for (int nt = 0; nt < 4; nt++) {
            int row = by * 128 + wm + mt * 16 + g;
            int col = bx * 128 + wn + nt * 8 + 2 * tig;
            float e[4];
#pragma unroll
            for (int q = 0; q < 4; q++) {
                float c = acc[mt][nt][q];
                if (EPI == 1) c = c / (1.0f + __expf(-c));
                e[q] = c;
            }
            if (sizeof(OT) == 2) {
                __half2* p0 = (__half2*)((__half*)C + (size_t)row * N + col);
                __half2* p1 = (__half2*)((__half*)C + (size_t)(row + 8) * N + col);
                *p0 = __floats2half2_rn(e[0], e[1]);
                *p1 = __floats2half2_rn(e[2], e[3]);
            } else {
                float* p0 = (float*)C + (size_t)row * N + col;
                float* p1 = (float*)C + (size_t)(row + 8) * N + col;
                *(float2*)p0 = make_float2(e[0], e[1]);
                *(float2*)p1 = make_float2(e[2], e[3]);
            }
        }
    }
}

// ---------------------------------------------------------------------------
// FP16 flash attention. qkv fp16; K/V double-buffered cp.async, 1 sync/tile;
// QK: m16n8k16 with K-major K tiles; PV: P packed from C-frags (NO shuffles),
// V b-frags via ldmatrix.x4.trans. Heavy tiles first; 2 CTAs/SM. smem 36KB.
// Layout (halfs): K0@0, K1@4608, V0@9216, V1@13824; Qstage aliases K0|K1.
// ---------------------------------------------------------------------------
__global__ void __launch_bounds__(256, 2) flash_kernel(
    const __half* __restrict__ qkv, __half* __restrict__ ao)
{
    int it = (int)gridDim.x - 1 - (int)blockIdx.x;
    int bh = blockIdx.y;
    int b = bh >> 4, h = bh & 15;
    int i0 = it * 128;

    __shared__ __align__(16) __half smem[2 * 64 * 72 + 2 * 64 * 72];
    __half* Qstage = smem;

    int tid = threadIdx.x, warp = tid >> 5, lane = tid & 31;
    int g = lane >> 2, tig = lane & 3;

    // ---- stage Q (128 x 64 fp16), pull to A-frags, fold 0.125 scale ----
    {
        int r = tid >> 1, cb = (tid & 1) * 32;
        const __half* qp = qkv + (size_t)(b * TT + i0 + r) * QS + h * HDD + cb;
        __half* dst = Qstage + r * 72 + cb;
#pragma unroll
        for (int c8 = 0; c8 < 4; c8++)
            *(float4*)(dst + c8 * 8) = *(const float4*)(qp + c8 * 8);
    }
    __syncthreads();
    uint32_t qa[4][4];
    {
        int m = warp * 16 + g;
        __half2 scl = __float2half2_rn(0.125f);
#pragma unroll
        for (int kt = 0; kt < 4; kt++) {
            int kb = kt * 16 + 2 * tig;
            __half2 t0 = *(const __half2*)&Qstage[m * 72 + kb];
            __half2 t1 = *(const __half2*)&Qstage[(m + 8) * 72 + kb];
            __half2 t2 = *(const __half2*)&Qstage[m * 72 + kb + 8];
            __half2 t3 = *(const __half2*)&Qstage[(m + 8) * 72 + kb + 8];
            t0 = __hmul2(t0, scl); t1 = __hmul2(t1, scl);
            t2 = __hmul2(t2, scl); t3 = __hmul2(t3, scl);
            qa[kt][0] = *(uint32_t*)&t0; qa[kt][1] = *(uint32_t*)&t1;
            qa[kt][2] = *(uint32_t*)&t2; qa[kt][3] = *(uint32_t*)&t3;
        }
    }
    __syncthreads();   // Qstage free -> K buffers usable

    // K/V loader coords: 4 threads/row, 16 halfs (2x CP16) each
    int lr = tid >> 2, lc = (tid & 3) * 16;
    const __half* krow = qkv + (size_t)(b * TT + lr) * QS + DD + h * HDD + lc;
    const __half* vrow = qkv + (size_t)(b * TT + lr) * QS + 2 * DD + h * HDD + lc;
    uint32_t kd[2] = { smaddr(smem + lr * 72 + lc),
                       smaddr(smem + 4608 + lr * 72 + lc) };
    uint32_t vd[2] = { smaddr(smem + 9216 + lr * 72 + lc),
                       smaddr(smem + 13824 + lr * 72 + lc) };

    int jt_max = 2 * it + 1;

    {   // issue tile 0
#pragma unroll
        for (int c = 0; c < 2; c++) {
            CP16(kd[0] + c * 16, krow + c * 8);
            CP16(vd[0] + c * 16, vrow + c * 8);
        }
        CP_COMMIT();
    }

    float o[8][4];
#pragma unroll
    for (int nt = 0; nt < 8; nt++)
#pragma unroll
        for (int r = 0; r < 4; r++) o[nt][r] = 0.f;
    float rm0 = -1e30f, rm1 = -1e30f, rs0 = 0.f, rs1 = 0.f;

    int warp_row0 = i0 + warp * 16;
    // ldmatrix address components (lane-dependent, loop-invariant)
    int lmat = lane >> 3;                      // matrix 0..3
    int lrow = (lane & 7) + 8 * (lmat & 1);    // k-row within 16
    int lcol8 = 8 * (lmat >> 1);               // extra n offset (0 or 8)

    for (int jt = 0; jt <= jt_max; jt++) {
        int j0 = jt * 64;
        asm volatile("cp.async.wait_group 0;\n");
        __syncthreads();
        if (jt < jt_max) {
            int jb = (jt + 1) & 1;
            const __half* kp = krow + (size_t)(j0 + 64) * QS;
            const __half* vp = vrow + (size_t)(j0 + 64) * QS;
#pragma unroll
            for (int c = 0; c < 2; c++) {
                CP16(kd[jb] + c * 16, kp + c * 8);
                CP16(vd[jb] + c * 16, vp + c * 8);
            }
            CP_COMMIT();
        }

        if (j0 <= warp_row0 + 15) {
            const __half* Ks = smem + (jt & 1) * 4608;
            const __half* Vs = smem + 9216 + (jt & 1) * 4608;
            // ---- S = Q K^T (fp16 mma) ----
            float s[8][4];
#pragma unroll
            for (int nt = 0; nt < 8; nt++)
#pragma unroll
                for (int r = 0; r < 4; r++) s[nt][r] = 0.f;
#pragma unroll
            for (int kt = 0; kt < 4; kt++) {
                int kb = kt * 16 + 2 * tig;
#pragma unroll
                for (int nt = 0; nt < 8; nt++) {
                    const __half* kr = Ks + (nt * 8 + g) * 72 + kb;
                    uint32_t bb[2] = { *(const uint32_t*)kr,
                                       *(const uint32_t*)(kr + 8) };
                    mma16(s[nt], qa[kt], bb);
                }
            }
            // ---- causal mask ----
            int r0 = warp_row0 + g, r1 = r0 + 8;
            if (j0 + 63 > warp_row0) {
#pragma unroll
                for (int nt = 0; nt < 8; nt++) {
                    int j = j0 + nt * 8 + 2 * tig;
                    if (j     > r0) s[nt][0] = -1e30f;
                    if (j + 1 > r0) s[nt][1] = -1e30f;
                    if (j     > r1) s[nt][2] = -1e30f;
                    if (j + 1 > r1) s[nt][3] = -1e30f;
                }
            }
            // ---- online softmax ----
            float m0 = -1e30f, m1 = -1e30f;
#pragma unroll
            for (int nt = 0; nt < 8; nt++) {
                m0 = fmaxf(m0, fmaxf(s[nt][0], s[nt][1]));
                m1 = fmaxf(m1, fmaxf(s[nt][2], s[nt][3]));
            }
            m0 = fmaxf(m0, __shfl_xor_sync(0xffffffffu, m0, 1));
            m0 = fmaxf(m0, __shfl_xor_sync(0xffffffffu, m0, 2));
            m1 = fmaxf(m1, __shfl_xor_sync(0xffffffffu, m1, 1));
            m1 = fmaxf(m1, __shfl_xor_sync(0xffffffffu, m1, 2));
            float nm0 = fmaxf(rm0, m0), nm1 = fmaxf(rm1, m1);
            float al0 = __expf(rm0 - nm0), al1 = __expf(rm1 - nm1);
            rm0 = nm0; rm1 = nm1;
            float l0 = 0.f, l1 = 0.f;
#pragma unroll
            for (int nt = 0; nt < 8; nt++) {
                s[nt][0] = __expf(s[nt][0] - nm0);
                s[nt][1] = __expf(s[nt][1] - nm0);
                s[nt][2] = __expf(s[nt][2] - nm1);
                s[nt][3] = __expf(s[nt][3] - nm1);
                l0 += s[nt][0] + s[nt][1];
                l1 += s[nt][2] + s[nt][3];
            }
            l0 += __shfl_xor_sync(0xffffffffu, l0, 1);
            l0 += __shfl_xor_sync(0xffffffffu, l0, 2);
            l1 += __shfl_xor_sync(0xffffffffu, l1, 1);
            l1 += __shfl_xor_sync(0xffffffffu, l1, 2);
            rs0 = rs0 * al0 + l0;
            rs1 = rs1 * al1 + l1;
#pragma unroll
            for (int nt = 0; nt < 8; nt++) {
                o[nt][0] *= al0; o[nt][1] *= al0;
                o[nt][2] *= al1; o[nt][3] *= al1;
            }
            // ---- O += P V : P C-frag == fp16 A-frag layout (no shuffles) ----
            uint32_t vsb = smaddr(Vs);
#pragma unroll
            for (int kc = 0; kc < 4; kc++) {
                uint32_t a[4];
                a[0] = packh2(s[2 * kc][0],     s[2 * kc][1]);
                a[1] = packh2(s[2 * kc][2],     s[2 * kc][3]);
                a[2] = packh2(s[2 * kc + 1][0], s[2 * kc + 1][1]);
                a[3] = packh2(s[2 * kc + 1][2], s[2 * kc + 1][3]);
                uint32_t rbase = vsb + (uint32_t)(kc * 16 + lrow) * 144u;
#pragma unroll
                for (int np = 0; np < 4; np++) {   // nt pairs {0,1},{2,3},...
                    uint32_t vaddr = rbase + (uint32_t)(np * 16 + lcol8) * 2u;
                    uint32_t b0, b1, b2, b3;
                    asm volatile(
                        "ldmatrix.sync.aligned.m8n8.x4.trans.shared.b16 "
                        "{%0,%1,%2,%3}, [%4];"
                        : "=r"(b0), "=r"(b1), "=r"(b2), "=r"(b3) : "r"(vaddr));
                    uint32_t bb0[2] = { b0, b1 };
                    uint32_t bb1[2] = { b2, b3 };
                    mma16(o[np * 2],     a, bb0);
                    mma16(o[np * 2 + 1], a, bb1);
                }
            }
        }
    }

    float inv0 = 1.0f / rs0, inv1 = 1.0f / rs1;
    int r0 = i0 + warp * 16 + g;
#pragma unroll
    for (int nt = 0; nt < 8; nt++) {
        int col = h * HDD + nt * 8 + 2 * tig;
        __half2* p0 = (__half2*)(ao + (size_t)(b * TT + r0) * DD + col);
        __half2* p1 = (__half2*)(ao + (size_t)(b * TT + r0 + 8) * DD + col);
        *p0 = __floats2half2_rn(o[nt][0] * inv0, o[nt][1] * inv0);
        *p1 = __floats2half2_rn(o[nt][2] * inv1, o[nt][3] * inv1);
    }
}

// ---------------------------------------------------------------------------
// Launch
// ---------------------------------------------------------------------------
extern "C" void kernel_launch(void* const* d_in, const int* in_sizes, int n_in,
                              void* d_out, int out_size)
{
    const float* x      = (const float*)d_in[0];
    const float* w_pre  = (const float*)d_in[1];
    const float* wq     = (const float*)d_in[2];
    const float* wk     = (const float*)d_in[3];
    const float* wv     = (const float*)d_in[4];
    const float* wo     = (const float*)d_in[5];
    const float* w_attn = (const float*)d_in[6];
    const float* w1     = (const float*)d_in[7];
    const float* w2     = (const float*)d_in[8];
    const float* w_ffn  = (const float*)d_in[9];
    float* out = (float*)d_out;

    __half *h_, *qkv_, *ao_, *y_, *mid_, *w_;
    float *tmp_;
    cudaGetSymbolAddress((void**)&h_,   g_h);
    cudaGetSymbolAddress((void**)&qkv_, g_qkv);
    cudaGetSymbolAddress((void**)&ao_,  g_ao);
    cudaGetSymbolAddress((void**)&tmp_, g_tmp);
    cudaGetSymbolAddress((void**)&y_,   g_y);
    cudaGetSymbolAddress((void**)&mid_, g_mid);
    cudaGetSymbolAddress((void**)&w_,   g_w);

    // 0) pack + transpose + round weights to fp16
    packT_kernel<<<12288, 256>>>(wq, wk, wv, wo, w1, w2, w_);

    // 1) h = rmsnorm(x) -> fp16
    rmsnorm_kernel<float, __half><<<MT, 256>>>(x, nullptr, w_pre, h_);

    // 2) fused qkv projection -> fp16
    {
        dim3 g(QS / 128, MT / 128);
        hgemm_kernel<0, __half><<<g, 256>>>(h_, w_ + WQKV_OFF, qkv_, MT, QS, DD);
    }

    // 3) fp16 flash attention -> ao fp16
    {
        dim3 g(TT / 128, BB * HH);
        flash_kernel<<<g, 256>>>(qkv_, ao_);
    }

    // 4) o-proj (fp32 out) + residual norm -> y fp16
    {
        dim3 g(DD / 128, MT / 128);
        hgemm_kernel<0, float><<<g, 256>>>(ao_, w_ + WO_OFF, tmp_, MT, DD, DD);
    }
    rmsnorm_kernel<__half, __half><<<MT, 256>>>(h_, tmp_, w_attn, y_);

    // 5) FFN
    {
        dim3 g(FFD / 128, MT / 128);
        hgemm_kernel<1, __half><<<g, 256>>>(y_, w_ + W1_OFF, mid_, MT, FFD, DD);
    }
    {
        dim3 g(DD / 128, MT / 128);
        hgemm_kernel<0, float><<<g, 256>>>(mid_, w_ + W2_OFF, tmp_, MT, DD, FFD);
    }
    rmsnorm_kernel<__half, float><<<MT, 256>>>(y_, tmp_, w_ffn, out);
}

// round 14
// speedup vs baseline: 2.4661x; 1.1120x over previous
#include <cuda_runtime.h>
#include <cuda_fp16.h>
#include <cstdint>
#include <cstddef>

#define BB   2
#define TT   2048
#define DD   1024
#define HH   16
#define HDD  64
#define FFD  4096
#define MT   (BB*TT)
#define QS   (3*DD)          // fused qkv row stride (fp16)

// ---------------------------------------------------------------------------
// Scratch
// ---------------------------------------------------------------------------
__device__ __half g_h  [MT*DD];
__device__ __half g_qkv[MT*QS];
__device__ __half g_ao [MT*DD];
__device__ float  g_tmp[MT*DD];
__device__ __half g_y  [MT*DD];
__device__ __half g_mid[MT*FFD];
__device__ __half g_w  [12*1024*1024]; // fp16 T: wqkvT[3072][1024] | woT | w1T | w2T

#define WQKV_OFF 0
#define WO_OFF (3*1024*1024)
#define W1_OFF (4*1024*1024)
#define W2_OFF (8*1024*1024)

// ---------------------------------------------------------------------------
// Helpers
// ---------------------------------------------------------------------------
__device__ __forceinline__ uint32_t smaddr(const void* p) {
    return (uint32_t)__cvta_generic_to_shared(p);
}
#define CP16(dst, src) asm volatile("cp.async.cg.shared.global [%0], [%1], 16;\n" :: "r"(dst), "l"(src))
#define CP_COMMIT()    asm volatile("cp.async.commit_group;\n")

// fp16 m16n8k16
__device__ __forceinline__ void mma16(float* d, const uint32_t* a, const uint32_t* b) {
    asm volatile(
        "mma.sync.aligned.m16n8k16.row.col.f32.f16.f16.f32 "
        "{%0,%1,%2,%3}, {%4,%5,%6,%7}, {%8,%9}, {%0,%1,%2,%3};\n"
        : "+f"(d[0]), "+f"(d[1]), "+f"(d[2]), "+f"(d[3])
        : "r"(a[0]), "r"(a[1]), "r"(a[2]), "r"(a[3]), "r"(b[0]), "r"(b[1]));
}

__device__ __forceinline__ uint32_t packh2(float x, float y) {
    __half2 t = __floats2half2_rn(x, y);
    return *(uint32_t*)&t;
}

#define LDSM4(r0, r1, r2, r3, addr) \
    asm volatile("ldmatrix.sync.aligned.m8n8.x4.shared.b16 {%0,%1,%2,%3}, [%4];" \
                 : "=r"(r0), "=r"(r1), "=r"(r2), "=r"(r3) : "r"(addr))
#define LDSM4T(r0, r1, r2, r3, addr) \
    asm volatile("ldmatrix.sync.aligned.m8n8.x4.trans.shared.b16 {%0,%1,%2,%3}, [%4];" \
                 : "=r"(r0), "=r"(r1), "=r"(r2), "=r"(r3) : "r"(addr))

// ---------------------------------------------------------------------------
// Pack weights -> fp16, TRANSPOSED to [N][K] row-major.
// ---------------------------------------------------------------------------
__global__ void __launch_bounds__(256) packT_kernel(
    const float* __restrict__ wq, const float* __restrict__ wk,
    const float* __restrict__ wv, const float* __restrict__ wo,
    const float* __restrict__ w1, const float* __restrict__ w2,
    __half* __restrict__ out)
{
    __shared__ float tile[32][33];
    int t = blockIdx.x;
    const float* src; __half* dst;
    int srcN, dstK, n0, k0, scol;
    if (t < 3072) {
        int nt = t >> 5, kt = t & 31;
        n0 = nt * 32; k0 = kt * 32;
        int sel = n0 >> 10;
        src = sel == 0 ? wq : (sel == 1 ? wk : wv);
        srcN = 1024; scol = n0 & 1023;
        dst = out + WQKV_OFF; dstK = 1024;
    } else if (t < 4096) {
        int u = t - 3072;
        int nt = u >> 5, kt = u & 31;
        n0 = nt * 32; k0 = kt * 32;
        src = wo; srcN = 1024; scol = n0;
        dst = out + WO_OFF; dstK = 1024;
    } else if (t < 8192) {
        int u = t - 4096;
        int nt = u >> 5, kt = u & 31;
        n0 = nt * 32; k0 = kt * 32;
        src = w1; srcN = 4096; scol = n0;
        dst = out + W1_OFF; dstK = 1024;
    } else {
        int u = t - 8192;
        int nt = u >> 7, kt = u & 127;
        n0 = nt * 32; k0 = kt * 32;
        src = w2; srcN = 1024; scol = n0;
        dst = out + W2_OFF; dstK = 4096;
    }
    int tx = threadIdx.x & 31, ty = threadIdx.x >> 5;
#pragma unroll
    for (int i = 0; i < 4; i++)
        tile[ty + i * 8][tx] = src[(size_t)(k0 + ty + i * 8) * srcN + scol + tx];
    __syncthreads();
#pragma unroll
    for (int i = 0; i < 4; i++)
        dst[(size_t)(n0 + ty + i * 8) * dstK + k0 + tx] = __float2half(tile[tx][ty + i * 8]);
}

// ---------------------------------------------------------------------------
// RMSNorm
// ---------------------------------------------------------------------------
template <typename AT, typename OT>
__global__ void __launch_bounds__(256) rmsnorm_kernel(
    const AT* __restrict__ a, const float* __restrict__ b,
    const float* __restrict__ w, OT* __restrict__ out)
{
    int row = blockIdx.x;
    size_t base = (size_t)row * DD;
    float v[4];
    float ss = 0.f;
#pragma unroll
    for (int t = 0; t < 4; t++) {
        int c = threadIdx.x + t * 256;
        float x = (float)a[base + c];
        if (b) x += b[base + c];
        v[t] = x;
        ss += x * x;
    }
    __shared__ float red[8];
#pragma unroll
    for (int o = 16; o; o >>= 1) ss += __shfl_xor_sync(0xffffffffu, ss, o);
    if ((threadIdx.x & 31) == 0) red[threadIdx.x >> 5] = ss;
    __syncthreads();
    if (threadIdx.x == 0) {
        float tot = 0.f;
#pragma unroll
        for (int i = 0; i < 8; i++) tot += red[i];
        red[0] = tot;
    }
    __syncthreads();
    float scale = rsqrtf(red[0] * (1.0f / DD) + 1e-6f);
#pragma unroll
    for (int t = 0; t < 4; t++) {
        int c = threadIdx.x + t * 256;
        out[base + c] = (OT)(v[t] * scale * w[c]);
    }
}

// ---------------------------------------------------------------------------
// FP16 GEMM: BM=BN=128, BK=32, 8 warps x (64x32), 3-stage, 1 sync/chunk,
// ldmatrix fragment loads (4x A-LDSM + 2x B-LDSM per sub-step).
// ---------------------------------------------------------------------------
template <int EPI, typename OT>
__global__ void __launch_bounds__(256, 2) hgemm_kernel(
    const __half* __restrict__ A, const __half* __restrict__ Bt,
    OT* __restrict__ C, int M, int N, int K)
{
    __shared__ __half As[3][128 * 40];   // 10240B/stage
    __shared__ __half Bs[3][128 * 40];

    int tid = threadIdx.x;
    int warp = tid >> 5, lane = tid & 31;
    int g = lane >> 2, tig = lane & 3;
    int wm = (warp >> 2) * 64, wn = (warp & 3) * 32;
    int bx = blockIdx.x, by = blockIdx.y;

    int r = tid >> 1, hf = tid & 1;
    const __half* a_src = A  + (size_t)(by * 128 + r) * K + hf * 16;
    const __half* b_src = Bt + (size_t)(bx * 128 + r) * K + hf * 16;
    uint32_t a_dst = smaddr(&As[0][r * 40 + hf * 16]);
    uint32_t b_dst = smaddr(&Bs[0][r * 40 + hf * 16]);

    // ldmatrix per-lane byte offsets (relative to stage base)
    uint32_t a_base = smaddr(&As[0][0]);
    uint32_t b_base = smaddr(&Bs[0][0]);
    uint32_t a_lm[4], b_lm[2];
#pragma unroll
    for (int mt = 0; mt < 4; mt++)
        a_lm[mt] = (uint32_t)(((wm + mt * 16 + (lane & 15)) * 40 + (lane >> 4) * 8) * 2);
#pragma unroll
    for (int np = 0; np < 2; np++)
        b_lm[np] = (uint32_t)(((wn + np * 16 + (lane >> 4) * 8 + (lane & 7)) * 40
                               + ((lane >> 3) & 1) * 8) * 2);

    float acc[4][4][4];
#pragma unroll
    for (int i = 0; i < 4; i++)
#pragma unroll
        for (int j = 0; j < 4; j++)
#pragma unroll
            for (int q = 0; q < 4; q++) acc[i][j][q] = 0.f;

    int KT = K >> 5;

#define ISSUE(stage, kt)                                                     \
    {                                                                        \
        const __half* ap = a_src + ((kt) << 5);                              \
        uint32_t ad = a_dst + (stage) * 10240;                               \
        CP16(ad, ap); CP16(ad + 16, ap + 8);                                 \
        const __half* bp = b_src + ((kt) << 5);                              \
        uint32_t bd = b_dst + (stage) * 10240;                               \
        CP16(bd, bp); CP16(bd + 16, bp + 8);                                 \
        CP_COMMIT();                                                         \
    }

    ISSUE(0, 0);
    if (KT > 1) ISSUE(1, 1);

    int st = 2, buf = 0;
    for (int kt = 0; kt < KT; kt++) {
        if (kt + 1 < KT) asm volatile("cp.async.wait_group 1;\n");
        else             asm volatile("cp.async.wait_group 0;\n");
        __syncthreads();
        if (kt + 2 < KT) {
            ISSUE(st, kt + 2);
            st = (st == 2) ? 0 : st + 1;
        }

        uint32_t ab = a_base + buf * 10240;
        uint32_t bb = b_base + buf * 10240;
#pragma unroll
        for (int ss = 0; ss < 2; ss++) {
            uint32_t koff = ss * 32;            // 16 halfs
            uint32_t a[4][4], b[4][2];
#pragma unroll
            for (int mt = 0; mt < 4; mt++)
                LDSM4(a[mt][0], a[mt][1], a[mt][2], a[mt][3], ab + a_lm[mt] + koff);
#pragma unroll
            for (int np = 0; np < 2; np++)
                LDSM4(b[2 * np][0], b[2 * np][1], b[2 * np + 1][0], b[2 * np + 1][1],
                      bb + b_lm[np] + koff);
#pragma unroll
            for (int mt = 0; mt < 4; mt++)
#pragma unroll
                for (int nt = 0; nt < 4; nt++) mma16(acc[mt][nt], a[mt], b[nt]);
        }
        buf = (buf == 2) ? 0 : buf + 1;
    }
#undef ISSUE

#pragma unroll
    for (int mt = 0; mt < 4; mt++) {
#pragma unroll
        for (int nt = 0; nt < 4; nt++) {
            int row = by * 128 + wm + mt * 16 + g;
            int col = bx * 128 + wn + nt * 8 + 2 * tig;
            float e[4];
#pragma unroll
            for (int q = 0; q < 4; q++) {
                float c = acc[mt][nt][q];
                if (EPI == 1) c = c / (1.0f + __expf(-c));
                e[q] = c;
            }
            if (sizeof(OT) == 2) {
                __half2* p0 = (__half2*)((__half*)C + (size_t)row * N + col);
                __half2* p1 = (__half2*)((__half*)C + (size_t)(row + 8) * N + col);
                *p0 = __floats2half2_rn(e[0], e[1]);
                *p1 = __floats2half2_rn(e[2], e[3]);
            } else {
                float* p0 = (float*)C + (size_t)row * N + col;
                float* p1 = (float*)C + (size_t)(row + 8) * N + col;
                *(float2*)p0 = make_float2(e[0], e[1]);
                *(float2*)p1 = make_float2(e[2], e[3]);
            }
        }
    }
}

// ---------------------------------------------------------------------------
// FP16 flash attention (R13 + ldmatrix K-frags).
// ---------------------------------------------------------------------------
__global__ void __launch_bounds__(256, 2) flash_kernel(
    const __half* __restrict__ qkv, __half* __restrict__ ao)
{
    int it = (int)gridDim.x - 1 - (int)blockIdx.x;
    int bh = blockIdx.y;
    int b = bh >> 4, h = bh & 15;
    int i0 = it * 128;

    __shared__ __align__(16) __half smem[2 * 64 * 72 + 2 * 64 * 72];
    __half* Qstage = smem;

    int tid = threadIdx.x, warp = tid >> 5, lane = tid & 31;
    int g = lane >> 2, tig = lane & 3;

    // ---- stage Q, pull to A-frags with 0.125 scale ----
    {
        int r = tid >> 1, cb = (tid & 1) * 32;
        const __half* qp = qkv + (size_t)(b * TT + i0 + r) * QS + h * HDD + cb;
        __half* dst = Qstage + r * 72 + cb;
#pragma unroll
        for (int c8 = 0; c8 < 4; c8++)
            *(float4*)(dst + c8 * 8) = *(const float4*)(qp + c8 * 8);
    }
    __syncthreads();
    uint32_t qa[4][4];
    {
        int m = warp * 16 + g;
        __half2 scl = __float2half2_rn(0.125f);
#pragma unroll
        for (int kt = 0; kt < 4; kt++) {
            int kb = kt * 16 + 2 * tig;
            __half2 t0 = *(const __half2*)&Qstage[m * 72 + kb];
            __half2 t1 = *(const __half2*)&Qstage[(m + 8) * 72 + kb];
            __half2 t2 = *(const __half2*)&Qstage[m * 72 + kb + 8];
            __half2 t3 = *(const __half2*)&Qstage[(m + 8) * 72 + kb + 8];
            t0 = __hmul2(t0, scl); t1 = __hmul2(t1, scl);
            t2 = __hmul2(t2, scl); t3 = __hmul2(t3, scl);
            qa[kt][0] = *(uint32_t*)&t0; qa[kt][1] = *(uint32_t*)&t1;
            qa[kt][2] = *(uint32_t*)&t2; qa[kt][3] = *(uint32_t*)&t3;
        }
    }
    __syncthreads();

    int lr = tid >> 2, lc = (tid & 3) * 16;
    const __half* krow = qkv + (size_t)(b * TT + lr) * QS + DD + h * HDD + lc;
    const __half* vrow = qkv + (size_t)(b * TT + lr) * QS + 2 * DD + h * HDD + lc;
    uint32_t kd[2] = { smaddr(smem + lr * 72 + lc),
                       smaddr(smem + 4608 + lr * 72 + lc) };
    uint32_t vd[2] = { smaddr(smem + 9216 + lr * 72 + lc),
                       smaddr(smem + 13824 + lr * 72 + lc) };

    // ldmatrix K-frag per-lane offsets (rows = n, stride 72 halfs)
    uint32_t k_lm[4];
#pragma unroll
    for (int np = 0; np < 4; np++)
        k_lm[np] = (uint32_t)(((np * 16 + (lane >> 4) * 8 + (lane & 7)) * 72
                               + ((lane >> 3) & 1) * 8) * 2);

    int jt_max = 2 * it + 1;

    {
#pragma unroll
        for (int c = 0; c < 2; c++) {
            CP16(kd[0] + c * 16, krow + c * 8);
            CP16(vd[0] + c * 16, vrow + c * 8);
        }
        CP_COMMIT();
    }

    float o[8][4];
#pragma unroll
    for (int nt = 0; nt < 8; nt++)
#pragma unroll
        for (int r = 0; r < 4; r++) o[nt][r] = 0.f;
    float rm0 = -1e30f, rm1 = -1e30f, rs0 = 0.f, rs1 = 0.f;

    int warp_row0 = i0 + warp * 16;
    int lmat = lane >> 3;
    int lrow = (lane & 7) + 8 * (lmat & 1);
    int lcol8 = 8 * (lmat >> 1);

    for (int jt = 0; jt <= jt_max; jt++) {
        int j0 = jt * 64;
        asm volatile("cp.async.wait_group 0;\n");
        __syncthreads();
        if (jt < jt_max) {
            int jb = (jt + 1) & 1;
            const __half* kp = krow + (size_t)(j0 + 64) * QS;
            const __half* vp = vrow + (size_t)(j0 + 64) * QS;
#pragma unroll
            for (int c = 0; c < 2; c++) {
                CP16(kd[jb] + c * 16, kp + c * 8);
                CP16(vd[jb] + c * 16, vp + c * 8);
            }
            CP_COMMIT();
        }

        if (j0 <= warp_row0 + 15) {
            uint32_t ksb = smaddr(smem) + (jt & 1) * 9216;   // bytes
            uint32_t vsb = smaddr(smem) + 18432 + (jt & 1) * 9216;
            // ---- S = Q K^T ----
            float s[8][4];
#pragma unroll
            for (int nt = 0; nt < 8; nt++)
#pragma unroll
                for (int r = 0; r < 4; r++) s[nt][r] = 0.f;
#pragma unroll
            for (int kt = 0; kt < 4; kt++) {
                uint32_t koff = kt * 32;
#pragma unroll
                for (int np = 0; np < 4; np++) {
                    uint32_t b0, b1, b2, b3;
                    LDSM4(b0, b1, b2, b3, ksb + k_lm[np] + koff);
                    uint32_t bb0[2] = { b0, b1 };
                    uint32_t bb1[2] = { b2, b3 };
                    mma16(s[2 * np],     qa[kt], bb0);
                    mma16(s[2 * np + 1], qa[kt], bb1);
                }
            }
            // ---- causal mask ----
            int r0 = warp_row0 + g, r1 = r0 + 8;
            if (j0 + 63 > warp_row0) {
#pragma unroll
                for (int nt = 0; nt < 8; nt++) {
                    int j = j0 + nt * 8 + 2 * tig;
                    if (j     > r0) s[nt][0] = -1e30f;
                    if (j + 1 > r0) s[nt][1] = -1e30f;
                    if (j     > r1) s[nt][2] = -1e30f;
                    if (j + 1 > r1) s[nt][3] = -1e30f;
                }
            }
            // ---- online softmax ----
            float m0 = -1e30f, m1 = -1e30f;
#pragma unroll
            for (int nt = 0; nt < 8; nt++) {
                m0 = fmaxf(m0, fmaxf(s[nt][0], s[nt][1]));
                m1 = fmaxf(m1, fmaxf(s[nt][2], s[nt][3]));
            }
            m0 = fmaxf(m0, __shfl_xor_sync(0xffffffffu, m0, 1));
            m0 = fmaxf(m0, __shfl_xor_sync(0xffffffffu, m0, 2));
            m1 = fmaxf(m1, __shfl_xor_sync(0xffffffffu, m1, 1));
            m1 = fmaxf(m1, __shfl_xor_sync(0xffffffffu, m1, 2));
            float nm0 = fmaxf(rm0, m0), nm1 = fmaxf(rm1, m1);
            float al0 = __expf(rm0 - nm0), al1 = __expf(rm1 - nm1);
            rm0 = nm0; rm1 = nm1;
            float l0 = 0.f, l1 = 0.f;
#pragma unroll
            for (int nt = 0; nt < 8; nt++) {
                s[nt][0] = __expf(s[nt][0] - nm0);
                s[nt][1] = __expf(s[nt][1] - nm0);
                s[nt][2] = __expf(s[nt][2] - nm1);
                s[nt][3] = __expf(s[nt][3] - nm1);
                l0 += s[nt][0] + s[nt][1];
                l1 += s[nt][2] + s[nt][3];
            }
            l0 += __shfl_xor_sync(0xffffffffu, l0, 1);
            l0 += __shfl_xor_sync(0xffffffffu, l0, 2);
            l1 += __shfl_xor_sync(0xffffffffu, l1, 1);
            l1 += __shfl_xor_sync(0xffffffffu, l1, 2);
            rs0 = rs0 * al0 + l0;
            rs1 = rs1 * al1 + l1;
#pragma unroll
            for (int nt = 0; nt < 8; nt++) {
                o[nt][0] *= al0; o[nt][1] *= al0;
                o[nt][2] *= al1; o[nt][3] *= al1;
            }
            // ---- O += P V ----
#pragma unroll
            for (int kc = 0; kc < 4; kc++) {
                uint32_t a[4];
                a[0] = packh2(s[2 * kc][0],     s[2 * kc][1]);
                a[1] = packh2(s[2 * kc][2],     s[2 * kc][3]);
                a[2] = packh2(s[2 * kc + 1][0], s[2 * kc + 1][1]);
                a[3] = packh2(s[2 * kc + 1][2], s[2 * kc + 1][3]);
                uint32_t rbase = vsb + (uint32_t)(kc * 16 + lrow) * 144u;
#pragma unroll
                for (int np = 0; np < 4; np++) {
                    uint32_t vaddr = rbase + (uint32_t)(np * 16 + lcol8) * 2u;
                    uint32_t b0, b1, b2, b3;
                    LDSM4T(b0, b1, b2, b3, vaddr);
                    uint32_t bb0[2] = { b0, b1 };
                    uint32_t bb1[2] = { b2, b3 };
                    mma16(o[np * 2],     a, bb0);
                    mma16(o[np * 2 + 1], a, bb1);
                }
            }
        }
    }

    float inv0 = 1.0f / rs0, inv1 = 1.0f / rs1;
    int r0 = i0 + warp * 16 + g;
#pragma unroll
    for (int nt = 0; nt < 8; nt++) {
        int col = h * HDD + nt * 8 + 2 * tig;
        __half2* p0 = (__half2*)(ao + (size_t)(b * TT + r0) * DD + col);
        __half2* p1 = (__half2*)(ao + (size_t)(b * TT + r0 + 8) * DD + col);
        *p0 = __floats2half2_rn(o[nt][0] * inv0, o[nt][1] * inv0);
        *p1 = __floats2half2_rn(o[nt][2] * inv1, o[nt][3] * inv1);
    }
}

// ---------------------------------------------------------------------------
// Launch
// ---------------------------------------------------------------------------
extern "C" void kernel_launch(void* const* d_in, const int* in_sizes, int n_in,
                              void* d_out, int out_size)
{
    const float* x      = (const float*)d_in[0];
    const float* w_pre  = (const float*)d_in[1];
    const float* wq     = (const float*)d_in[2];
    const float* wk     = (const float*)d_in[3];
    const float* wv     = (const float*)d_in[4];
    const float* wo     = (const float*)d_in[5];
    const float* w_attn = (const float*)d_in[6];
    const float* w1     = (const float*)d_in[7];
    const float* w2     = (const float*)d_in[8];
    const float* w_ffn  = (const float*)d_in[9];
    float* out = (float*)d_out;

    __half *h_, *qkv_, *ao_, *y_, *mid_, *w_;
    float *tmp_;
    cudaGetSymbolAddress((void**)&h_,   g_h);
    cudaGetSymbolAddress((void**)&qkv_, g_qkv);
    cudaGetSymbolAddress((void**)&ao_,  g_ao);
    cudaGetSymbolAddress((void**)&tmp_, g_tmp);
    cudaGetSymbolAddress((void**)&y_,   g_y);
    cudaGetSymbolAddress((void**)&mid_, g_mid);
    cudaGetSymbolAddress((void**)&w_,   g_w);

    // 0) pack + transpose + round weights to fp16
    packT_kernel<<<12288, 256>>>(wq, wk, wv, wo, w1, w2, w_);

    // 1) h = rmsnorm(x) -> fp16
    rmsnorm_kernel<float, __half><<<MT, 256>>>(x, nullptr, w_pre, h_);

    // 2) fused qkv projection -> fp16
    {
        dim3 g(QS / 128, MT / 128);
        hgemm_kernel<0, __half><<<g, 256>>>(h_, w_ + WQKV_OFF, qkv_, MT, QS, DD);
    }

    // 3) fp16 flash attention -> ao fp16
    {
        dim3 g(TT / 128, BB * HH);
        flash_kernel<<<g, 256>>>(qkv_, ao_);
    }

    // 4) o-proj (fp32 out) + residual norm -> y fp16
    {
        dim3 g(DD / 128, MT / 128);
        hgemm_kernel<0, float><<<g, 256>>>(ao_, w_ + WO_OFF, tmp_, MT, DD, DD);
    }
    rmsnorm_kernel<__half, __half><<<MT, 256>>>(h_, tmp_, w_attn, y_);

    // 5) FFN
    {
        dim3 g(FFD / 128, MT / 128);
        hgemm_kernel<1, __half><<<g, 256>>>(y_, w_ + W1_OFF, mid_, MT, FFD, DD);
    }
    {
        dim3 g(DD / 128, MT / 128);
        hgemm_kernel<0, float><<<g, 256>>>(mid_, w_ + W2_OFF, tmp_, MT, DD, FFD);
    }
    rmsnorm_kernel<__half, float><<<MT, 256>>>(y_, tmp_, w_ffn, out);
}

// round 15
// speedup vs baseline: 2.4772x; 1.0045x over previous
#include <cuda_runtime.h>
#include <cuda_fp16.h>
#include <cstdint>
#include <cstddef>

#define BB   2
#define TT   2048
#define DD   1024
#define HH   16
#define HDD  64
#define FFD  4096
#define MT   (BB*TT)
#define QS   (3*DD)          // fused qkv row stride (fp16)

// ---------------------------------------------------------------------------
// Scratch
// ---------------------------------------------------------------------------
__device__ __half g_h  [MT*DD];
__device__ __half g_qkv[MT*QS];
__device__ __half g_ao [MT*DD];
__device__ float  g_tmp[MT*DD];
__device__ __half g_y  [MT*DD];
__device__ __half g_mid[MT*FFD];
__device__ __half g_w  [12*1024*1024]; // fp16 T: wqkvT[3072][1024] | woT | w1T | w2T

#define WQKV_OFF 0
#define WO_OFF (3*1024*1024)
#define W1_OFF (4*1024*1024)
#define W2_OFF (8*1024*1024)

// ---------------------------------------------------------------------------
// Helpers
// ---------------------------------------------------------------------------
__device__ __forceinline__ uint32_t smaddr(const void* p) {
    return (uint32_t)__cvta_generic_to_shared(p);
}
#define CP16(dst, src) asm volatile("cp.async.cg.shared.global [%0], [%1], 16;\n" :: "r"(dst), "l"(src))
#define CP_COMMIT()    asm volatile("cp.async.commit_group;\n")

// fp16 m16n8k16
__device__ __forceinline__ void mma16(float* d, const uint32_t* a, const uint32_t* b) {
    asm volatile(
        "mma.sync.aligned.m16n8k16.row.col.f32.f16.f16.f32 "
        "{%0,%1,%2,%3}, {%4,%5,%6,%7}, {%8,%9}, {%0,%1,%2,%3};\n"
        : "+f"(d[0]), "+f"(d[1]), "+f"(d[2]), "+f"(d[3])
        : "r"(a[0]), "r"(a[1]), "r"(a[2]), "r"(a[3]), "r"(b[0]), "r"(b[1]));
}

__device__ __forceinline__ uint32_t packh2(float x, float y) {
    __half2 t = __floats2half2_rn(x, y);
    return *(uint32_t*)&t;
}

#define LDSM4(r0, r1, r2, r3, addr) \
    asm volatile("ldmatrix.sync.aligned.m8n8.x4.shared.b16 {%0,%1,%2,%3}, [%4];" \
                 : "=r"(r0), "=r"(r1), "=r"(r2), "=r"(r3) : "r"(addr))
#define LDSM4T(r0, r1, r2, r3, addr) \
    asm volatile("ldmatrix.sync.aligned.m8n8.x4.trans.shared.b16 {%0,%1,%2,%3}, [%4];" \
                 : "=r"(r0), "=r"(r1), "=r"(r2), "=r"(r3) : "r"(addr))

// ---------------------------------------------------------------------------
// Pack weights -> fp16, TRANSPOSED to [N][K] row-major.
// ---------------------------------------------------------------------------
__global__ void __launch_bounds__(256) packT_kernel(
    const float* __restrict__ wq, const float* __restrict__ wk,
    const float* __restrict__ wv, const float* __restrict__ wo,
    const float* __restrict__ w1, const float* __restrict__ w2,
    __half* __restrict__ out)
{
    __shared__ float tile[32][33];
    int t = blockIdx.x;
    const float* src; __half* dst;
    int srcN, dstK, n0, k0, scol;
    if (t < 3072) {
        int nt = t >> 5, kt = t & 31;
        n0 = nt * 32; k0 = kt * 32;
        int sel = n0 >> 10;
        src = sel == 0 ? wq : (sel == 1 ? wk : wv);
        srcN = 1024; scol = n0 & 1023;
        dst = out + WQKV_OFF; dstK = 1024;
    } else if (t < 4096) {
        int u = t - 3072;
        int nt = u >> 5, kt = u & 31;
        n0 = nt * 32; k0 = kt * 32;
        src = wo; srcN = 1024; scol = n0;
        dst = out + WO_OFF; dstK = 1024;
    } else if (t < 8192) {
        int u = t - 4096;
        int nt = u >> 5, kt = u & 31;
        n0 = nt * 32; k0 = kt * 32;
        src = w1; srcN = 4096; scol = n0;
        dst = out + W1_OFF; dstK = 1024;
    } else {
        int u = t - 8192;
        int nt = u >> 7, kt = u & 127;
        n0 = nt * 32; k0 = kt * 32;
        src = w2; srcN = 1024; scol = n0;
        dst = out + W2_OFF; dstK = 4096;
    }
    int tx = threadIdx.x & 31, ty = threadIdx.x >> 5;
#pragma unroll
    for (int i = 0; i < 4; i++)
        tile[ty + i * 8][tx] = src[(size_t)(k0 + ty + i * 8) * srcN + scol + tx];
    __syncthreads();
#pragma unroll
    for (int i = 0; i < 4; i++)
        dst[(size_t)(n0 + ty + i * 8) * dstK + k0 + tx] = __float2half(tile[tx][ty + i * 8]);
}

// ---------------------------------------------------------------------------
// RMSNorm
// ---------------------------------------------------------------------------
template <typename AT, typename OT>
__global__ void __launch_bounds__(256) rmsnorm_kernel(
    const AT* __restrict__ a, const float* __restrict__ b,
    const float* __restrict__ w, OT* __restrict__ out)
{
    int row = blockIdx.x;
    size_t base = (size_t)row * DD;
    float v[4];
    float ss = 0.f;
#pragma unroll
    for (int t = 0; t < 4; t++) {
        int c = threadIdx.x + t * 256;
        float x = (float)a[base + c];
        if (b) x += b[base + c];
        v[t] = x;
        ss += x * x;
    }
    __shared__ float red[8];
#pragma unroll
    for (int o = 16; o; o >>= 1) ss += __shfl_xor_sync(0xffffffffu, ss, o);
    if ((threadIdx.x & 31) == 0) red[threadIdx.x >> 5] = ss;
    __syncthreads();
    if (threadIdx.x == 0) {
        float tot = 0.f;
#pragma unroll
        for (int i = 0; i < 8; i++) tot += red[i];
        red[0] = tot;
    }
    __syncthreads();
    float scale = rsqrtf(red[0] * (1.0f / DD) + 1e-6f);
#pragma unroll
    for (int t = 0; t < 4; t++) {
        int c = threadIdx.x + t * 256;
        out[base + c] = (OT)(v[t] * scale * w[c]);
    }
}

// ---------------------------------------------------------------------------
// FP16 GEMM: BM=BN=128, BK=32, 8 warps x (64x32), 3-stage, 1 sync/chunk,
// ldmatrix fragment loads (4x A-LDSM + 2x B-LDSM per sub-step).
// ---------------------------------------------------------------------------
template <int EPI, typename OT>
__global__ void __launch_bounds__(256, 2) hgemm_kernel(
    const __half* __restrict__ A, const __half* __restrict__ Bt,
    OT* __restrict__ C, int M, int N, int K)
{
    __shared__ __half As[3][128 * 40];   // 10240B/stage
    __shared__ __half Bs[3][128 * 40];

    int tid = threadIdx.x;
    int warp = tid >> 5, lane = tid & 31;
    int g = lane >> 2, tig = lane & 3;
    int wm = (warp >> 2) * 64, wn = (warp & 3) * 32;
    int bx = blockIdx.x, by = blockIdx.y;

    int r = tid >> 1, hf = tid & 1;
    const __half* a_src = A  + (size_t)(by * 128 + r) * K + hf * 16;
    const __half* b_src = Bt + (size_t)(bx * 128 + r) * K + hf * 16;
    uint32_t a_dst = smaddr(&As[0][r * 40 + hf * 16]);
    uint32_t b_dst = smaddr(&Bs[0][r * 40 + hf * 16]);

    // ldmatrix per-lane byte offsets (relative to stage base)
    uint32_t a_base = smaddr(&As[0][0]);
    uint32_t b_base = smaddr(&Bs[0][0]);
    uint32_t a_lm[4], b_lm[2];
#pragma unroll
    for (int mt = 0; mt < 4; mt++)
        a_lm[mt] = (uint32_t)(((wm + mt * 16 + (lane & 15)) * 40 + (lane >> 4) * 8) * 2);
#pragma unroll
    for (int np = 0; np < 2; np++)
        b_lm[np] = (uint32_t)(((wn + np * 16 + (lane >> 4) * 8 + (lane & 7)) * 40
                               + ((lane >> 3) & 1) * 8) * 2);

    float acc[4][4][4];
#pragma unroll
    for (int i = 0; i < 4; i++)
#pragma unroll
        for (int j = 0; j < 4; j++)
#pragma unroll
            for (int q = 0; q < 4; q++) acc[i][j][q] = 0.f;

    int KT = K >> 5;

#define ISSUE(stage, kt)                                                     \
    {                                                                        \
        const __half* ap = a_src + ((kt) << 5);                              \
        uint32_t ad = a_dst + (stage) * 10240;                               \
        CP16(ad, ap); CP16(ad + 16, ap + 8);                                 \
        const __half* bp = b_src + ((kt) << 5);                              \
        uint32_t bd = b_dst + (stage) * 10240;                               \
        CP16(bd, bp); CP16(bd + 16, bp + 8);                                 \
        CP_COMMIT();                                                         \
    }

    ISSUE(0, 0);
    if (KT > 1) ISSUE(1, 1);

    int st = 2, buf = 0;
    for (int kt = 0; kt < KT; kt++) {
        if (kt + 1 < KT) asm volatile("cp.async.wait_group 1;\n");
        else             asm volatile("cp.async.wait_group 0;\n");
        __syncthreads();
        if (kt + 2 < KT) {
            ISSUE(st, kt + 2);
            st = (st == 2) ? 0 : st + 1;
        }

        uint32_t ab = a_base + buf * 10240;
        uint32_t bb = b_base + buf * 10240;
#pragma unroll
        for (int ss = 0; ss < 2; ss++) {
            uint32_t koff = ss * 32;            // 16 halfs
            uint32_t a[4][4], b[4][2];
#pragma unroll
            for (int mt = 0; mt < 4; mt++)
                LDSM4(a[mt][0], a[mt][1], a[mt][2], a[mt][3], ab + a_lm[mt] + koff);
#pragma unroll
            for (int np = 0; np < 2; np++)
                LDSM4(b[2 * np][0], b[2 * np][1], b[2 * np + 1][0], b[2 * np + 1][1],
                      bb + b_lm[np] + koff);
#pragma unroll
            for (int mt = 0; mt < 4; mt++)
#pragma unroll
                for (int nt = 0; nt < 4; nt++) mma16(acc[mt][nt], a[mt], b[nt]);
        }
        buf = (buf == 2) ? 0 : buf + 1;
    }
#undef ISSUE

#pragma unroll
    for (int mt = 0; mt < 4; mt++) {
#pragma unroll
        for (int nt = 0; nt < 4; nt++) {
            int row = by * 128 + wm + mt * 16 + g;
            int col = bx * 128 + wn + nt * 8 + 2 * tig;
            float e[4];
#pragma unroll
            for (int q = 0; q < 4; q++) {
                float c = acc[mt][nt][q];
                if (EPI == 1) c = c / (1.0f + __expf(-c));
                e[q] = c;
            }
            if (sizeof(OT) == 2) {
                __half2* p0 = (__half2*)((__half*)C + (size_t)row * N + col);
                __half2* p1 = (__half2*)((__half*)C + (size_t)(row + 8) * N + col);
                *p0 = __floats2half2_rn(e[0], e[1]);
                *p1 = __floats2half2_rn(e[2], e[3]);
            } else {
                float* p0 = (float*)C + (size_t)row * N + col;
                float* p1 = (float*)C + (size_t)(row + 8) * N + col;
                *(float2*)p0 = make_float2(e[0], e[1]);
                *(float2*)p1 = make_float2(e[2], e[3]);
            }
        }
    }
}

// ---------------------------------------------------------------------------
// FP16 flash attention (R13 + ldmatrix K-frags).
// ---------------------------------------------------------------------------
__global__ void __launch_bounds__(256, 2) flash_kernel(
    const __half* __restrict__ qkv, __half* __restrict__ ao)
{
    int it = (int)gridDim.x - 1 - (int)blockIdx.x;
    int bh = blockIdx.y;
    int b = bh >> 4, h = bh & 15;
    int i0 = it * 128;

    __shared__ __align__(16) __half smem[2 * 64 * 72 + 2 * 64 * 72];
    __half* Qstage = smem;

    int tid = threadIdx.x, warp = tid >> 5, lane = tid & 31;
    int g = lane >> 2, tig = lane & 3;

    // ---- stage Q, pull to A-frags with 0.125 scale ----
    {
        int r = tid >> 1, cb = (tid & 1) * 32;
        const __half* qp = qkv + (size_t)(b * TT + i0 + r) * QS + h * HDD + cb;
        __half* dst = Qstage + r * 72 + cb;
#pragma unroll
        for (int c8 = 0; c8 < 4; c8++)
            *(float4*)(dst + c8 * 8) = *(const float4*)(qp + c8 * 8);
    }
    __syncthreads();
    uint32_t qa[4][4];
    {
        int m = warp * 16 + g;
        __half2 scl = __float2half2_rn(0.125f);
#pragma unroll
        for (int kt = 0; kt < 4; kt++) {
            int kb = kt * 16 + 2 * tig;
            __half2 t0 = *(const __half2*)&Qstage[m * 72 + kb];
            __half2 t1 = *(const __half2*)&Qstage[(m + 8) * 72 + kb];
            __half2 t2 = *(const __half2*)&Qstage[m * 72 + kb + 8];
            __half2 t3 = *(const __half2*)&Qstage[(m + 8) * 72 + kb + 8];
            t0 = __hmul2(t0, scl); t1 = __hmul2(t1, scl);
            t2 = __hmul2(t2, scl); t3 = __hmul2(t3, scl);
            qa[kt][0] = *(uint32_t*)&t0; qa[kt][1] = *(uint32_t*)&t1;
            qa[kt][2] = *(uint32_t*)&t2; qa[kt][3] = *(uint32_t*)&t3;
        }
    }
    __syncthreads();

    int lr = tid >> 2, lc = (tid & 3) * 16;
    const __half* krow = qkv + (size_t)(b * TT + lr) * QS + DD + h * HDD + lc;
    const __half* vrow = qkv + (size_t)(b * TT + lr) * QS + 2 * DD + h * HDD + lc;
    uint32_t kd[2] = { smaddr(smem + lr * 72 + lc),
                       smaddr(smem + 4608 + lr * 72 + lc) };
    uint32_t vd[2] = { smaddr(smem + 9216 + lr * 72 + lc),
                       smaddr(smem + 13824 + lr * 72 + lc) };

    // ldmatrix K-frag per-lane offsets (rows = n, stride 72 halfs)
    uint32_t k_lm[4];
#pragma unroll
    for (int np = 0; np < 4; np++)
        k_lm[np] = (uint32_t)(((np * 16 + (lane >> 4) * 8 + (lane & 7)) * 72
                               + ((lane >> 3) & 1) * 8) * 2);

    int jt_max = 2 * it + 1;

    {
#pragma unroll
        for (int c = 0; c < 2; c++) {
            CP16(kd[0] + c * 16, krow + c * 8);
            CP16(vd[0] + c * 16, vrow + c * 8);
        }
        CP_COMMIT();
    }

    float o[8][4];
#pragma unroll
    for (int nt = 0; nt < 8; nt++)
#pragma unroll
        for (int r = 0; r < 4; r++) o[nt][r] = 0.f;
    float rm0 = -1e30f, rm1 = -1e30f, rs0 = 0.f, rs1 = 0.f;

    int warp_row0 = i0 + warp * 16;
    int lmat = lane >> 3;
    int lrow = (lane & 7) + 8 * (lmat & 1);
    int lcol8 = 8 * (lmat >> 1);

    for (int jt = 0; jt <= jt_max; jt++) {
        int j0 = jt * 64;
        asm volatile("cp.async.wait_group 0;\n");
        __syncthreads();
        if (jt < jt_max) {
            int jb = (jt + 1) & 1;
            const __half* kp = krow + (size_t)(j0 + 64) * QS;
            const __half* vp = vrow + (size_t)(j0 + 64) * QS;
#pragma unroll
            for (int c = 0; c < 2; c++) {
                CP16(kd[jb] + c * 16, kp + c * 8);
                CP16(vd[jb] + c * 16, vp + c * 8);
            }
            CP_COMMIT();
        }

        if (j0 <= warp_row0 + 15) {
            uint32_t ksb = smaddr(smem) + (jt & 1) * 9216;   // bytes
            uint32_t vsb = smaddr(smem) + 18432 + (jt & 1) * 9216;
            // ---- S = Q K^T ----
            float s[8][4];
#pragma unroll
            for (int nt = 0; nt < 8; nt++)
#pragma unroll
                for (int r = 0; r < 4; r++) s[nt][r] = 0.f;
#pragma unroll
            for (int kt = 0; kt < 4; kt++) {
                uint32_t koff = kt * 32;
#pragma unroll
                for (int np = 0; np < 4; np++) {
                    uint32_t b0, b1, b2, b3;
                    LDSM4(b0, b1, b2, b3, ksb + k_lm[np] + koff);
                    uint32_t bb0[2] = { b0, b1 };
                    uint32_t bb1[2] = { b2, b3 };
                    mma16(s[2 * np],     qa[kt], bb0);
                    mma16(s[2 * np + 1], qa[kt], bb1);
                }
            }
            // ---- causal mask ----
            int r0 = warp_row0 + g, r1 = r0 + 8;
            if (j0 + 63 > warp_row0) {
#pragma unroll
                for (int nt = 0; nt < 8; nt++) {
                    int j = j0 + nt * 8 + 2 * tig;
                    if (j     > r0) s[nt][0] = -1e30f;
                    if (j + 1 > r0) s[nt][1] = -1e30f;
                    if (j     > r1) s[nt][2] = -1e30f;
                    if (j + 1 > r1) s[nt][3] = -1e30f;
                }
            }
            // ---- online softmax ----
            float m0 = -1e30f, m1 = -1e30f;
#pragma unroll
            for (int nt = 0; nt < 8; nt++) {
                m0 = fmaxf(m0, fmaxf(s[nt][0], s[nt][1]));
                m1 = fmaxf(m1, fmaxf(s[nt][2], s[nt][3]));
            }
            m0 = fmaxf(m0, __shfl_xor_sync(0xffffffffu, m0, 1));
            m0 = fmaxf(m0, __shfl_xor_sync(0xffffffffu, m0, 2));
            m1 = fmaxf(m1, __shfl_xor_sync(0xffffffffu, m1, 1));
            m1 = fmaxf(m1, __shfl_xor_sync(0xffffffffu, m1, 2));
            float nm0 = fmaxf(rm0, m0), nm1 = fmaxf(rm1, m1);
            float al0 = __expf(rm0 - nm0), al1 = __expf(rm1 - nm1);
            rm0 = nm0; rm1 = nm1;
            float l0 = 0.f, l1 = 0.f;
#pragma unroll
            for (int nt = 0; nt < 8; nt++) {
                s[nt][0] = __expf(s[nt][0] - nm0);
                s[nt][1] = __expf(s[nt][1] - nm0);
                s[nt][2] = __expf(s[nt][2] - nm1);
                s[nt][3] = __expf(s[nt][3] - nm1);
                l0 += s[nt][0] + s[nt][1];
                l1 += s[nt][2] + s[nt][3];
            }
            l0 += __shfl_xor_sync(0xffffffffu, l0, 1);
            l0 += __shfl_xor_sync(0xffffffffu, l0, 2);
            l1 += __shfl_xor_sync(0xffffffffu, l1, 1);
            l1 += __shfl_xor_sync(0xffffffffu, l1, 2);
            rs0 = rs0 * al0 + l0;
            rs1 = rs1 * al1 + l1;
#pragma unroll
            for (int nt = 0; nt < 8; nt++) {
                o[nt][0] *= al0; o[nt][1] *= al0;
                o[nt][2] *= al1; o[nt][3] *= al1;
            }
            // ---- O += P V ----
#pragma unroll
            for (int kc = 0; kc < 4; kc++) {
                uint32_t a[4];
                a[0] = packh2(s[2 * kc][0],     s[2 * kc][1]);
                a[1] = packh2(s[2 * kc][2],     s[2 * kc][3]);
                a[2] = packh2(s[2 * kc + 1][0], s[2 * kc + 1][1]);
                a[3] = packh2(s[2 * kc + 1][2], s[2 * kc + 1][3]);
                uint32_t rbase = vsb + (uint32_t)(kc * 16 + lrow) * 144u;
#pragma unroll
                for (int np = 0; np < 4; np++) {
                    uint32_t vaddr = rbase + (uint32_t)(np * 16 + lcol8) * 2u;
                    uint32_t b0, b1, b2, b3;
                    LDSM4T(b0, b1, b2, b3, vaddr);
                    uint32_t bb0[2] = { b0, b1 };
                    uint32_t bb1[2] = { b2, b3 };
                    mma16(o[np * 2],     a, bb0);
                    mma16(o[np * 2 + 1], a, bb1);
                }
            }
        }
    }

    float inv0 = 1.0f / rs0, inv1 = 1.0f / rs1;
    int r0 = i0 + warp * 16 + g;
#pragma unroll
    for (int nt = 0; nt < 8; nt++) {
        int col = h * HDD + nt * 8 + 2 * tig;
        __half2* p0 = (__half2*)(ao + (size_t)(b * TT + r0) * DD + col);
        __half2* p1 = (__half2*)(ao + (size_t)(b * TT + r0 + 8) * DD + col);
        *p0 = __floats2half2_rn(o[nt][0] * inv0, o[nt][1] * inv0);
        *p1 = __floats2half2_rn(o[nt][2] * inv1, o[nt][3] * inv1);
    }
}

// ---------------------------------------------------------------------------
// Launch
// ---------------------------------------------------------------------------
extern "C" void kernel_launch(void* const* d_in, const int* in_sizes, int n_in,
                              void* d_out, int out_size)
{
    const float* x      = (const float*)d_in[0];
    const float* w_pre  = (const float*)d_in[1];
    const float* wq     = (const float*)d_in[2];
    const float* wk     = (const float*)d_in[3];
    const float* wv     = (const float*)d_in[4];
    const float* wo     = (const float*)d_in[5];
    const float* w_attn = (const float*)d_in[6];
    const float* w1     = (const float*)d_in[7];
    const float* w2     = (const float*)d_in[8];
    const float* w_ffn  = (const float*)d_in[9];
    float* out = (float*)d_out;

    __half *h_, *qkv_, *ao_, *y_, *mid_, *w_;
    float *tmp_;
    cudaGetSymbolAddress((void**)&h_,   g_h);
    cudaGetSymbolAddress((void**)&qkv_, g_qkv);
    cudaGetSymbolAddress((void**)&ao_,  g_ao);
    cudaGetSymbolAddress((void**)&tmp_, g_tmp);
    cudaGetSymbolAddress((void**)&y_,   g_y);
    cudaGetSymbolAddress((void**)&mid_, g_mid);
    cudaGetSymbolAddress((void**)&w_,   g_w);

    // 0) pack + transpose + round weights to fp16
    packT_kernel<<<12288, 256>>>(wq, wk, wv, wo, w1, w2, w_);

    // 1) h = rmsnorm(x) -> fp16
    rmsnorm_kernel<float, __half><<<MT, 256>>>(x, nullptr, w_pre, h_);

    // 2) fused qkv projection -> fp16
    {
        dim3 g(QS / 128, MT / 128);
        hgemm_kernel<0, __half><<<g, 256>>>(h_, w_ + WQKV_OFF, qkv_, MT, QS, DD);
    }

    // 3) fp16 flash attention -> ao fp16
    {
        dim3 g(TT / 128, BB * HH);
        flash_kernel<<<g, 256>>>(qkv_, ao_);
    }

    // 4) o-proj (fp32 out) + residual norm -> y fp16
    {
        dim3 g(DD / 128, MT / 128);
        hgemm_kernel<0, float><<<g, 256>>>(ao_, w_ + WO_OFF, tmp_, MT, DD, DD);
    }
    rmsnorm_kernel<__half, __half><<<MT, 256>>>(h_, tmp_, w_attn, y_);

    // 5) FFN
    {
        dim3 g(FFD / 128, MT / 128);
        hgemm_kernel<1, __half><<<g, 256>>>(y_, w_ + W1_OFF, mid_, MT, FFD, DD);
    }
    {
        dim3 g(DD / 128, MT / 128);
        hgemm_kernel<0, float><<<g, 256>>>(mid_, w_ + W2_OFF, tmp_, MT, DD, FFD);
    }
    rmsnorm_kernel<__half, float><<<MT, 256>>>(y_, tmp_, w_ffn, out);
}